// round 8
// baseline (speedup 1.0000x reference)
#include <cuda_runtime.h>
#include <cuda_bf16.h>
#include <cstdint>

#define E_DIM 1024
#define K3 (3 * E_DIM)               /* 3072 concat-K */
#define NHEADS 16
#define DH 64
#define HH 128
#define WW 128
#define MROWS (HH * WW)              /* 16384 */
#define HWD ((size_t)MROWS * DH)

#define BK 96
#define NCH (K3 / BK)                 /* 32 */
#define ROWP 104                      /* padded row (bf16 elems), 208B */
#define TILE_ROWS 128
#define STAGE_HALF (TILE_ROWS * ROWP)
#define STAGE_BYTES (2 * STAGE_HALF * 2)     /* 53248 */
#define SMEM_TOTAL (2 * STAGE_BYTES)         /* 106496 */

/* retention smem layout (dynamic, bytes) */
#define RLD 72                        /* bf16 row pitch (144B) */
#define R_KBH 0
#define R_KBL 18432
#define R_VBH 36864
#define R_VBL 55296
#define R_KVH 0
#define R_KVL 9216
#define R_QSH 18432
#define R_QSL 36864
#define RET_SMEM 73728

// ---------------- scratch (static device arrays; no allocation) ----------------
__device__ __nv_bfloat16 g_a2[(size_t)MROWS * K3];        // [Ah|Al|Ah] of x
__device__ __nv_bfloat16 g_b2[4][(size_t)E_DIM * K3];     // [Wh|Wh|Wl] per weight
__device__ __nv_bfloat16 g_o2cat[(size_t)MROWS * K3];     // [hi|lo|hi] of o2
__device__ float g_q[(size_t)NHEADS * MROWS * DH];
__device__ float g_k[(size_t)NHEADS * MROWS * DH];
__device__ float g_v[(size_t)NHEADS * MROWS * DH];
__device__ float g_o1[(size_t)NHEADS * MROWS * DH];

// ======================= helpers =======================
__device__ __forceinline__ uint32_t smem_u32(const void* p) {
    uint32_t a;
    asm("{ .reg .u64 t; cvta.to.shared.u64 t, %1; cvt.u32.u64 %0, t; }"
        : "=r"(a) : "l"(p));
    return a;
}

__device__ __forceinline__ void cp_async16(uint32_t dst, const void* src) {
    asm volatile("cp.async.cg.shared.global [%0], [%1], 16;\n"
                 :: "r"(dst), "l"(src) : "memory");
}

template <int N>
__device__ __forceinline__ void cp_wait() {
    asm volatile("cp.async.wait_group %0;\n" :: "n"(N) : "memory");
}

__device__ __forceinline__ void ldm_x4(uint32_t* r, uint32_t addr) {
    asm volatile(
        "ldmatrix.sync.aligned.m8n8.x4.shared.b16 {%0,%1,%2,%3}, [%4];"
        : "=r"(r[0]), "=r"(r[1]), "=r"(r[2]), "=r"(r[3]) : "r"(addr));
}

__device__ __forceinline__ void ldm_x4t(uint32_t* r, uint32_t addr) {
    asm volatile(
        "ldmatrix.sync.aligned.m8n8.x4.trans.shared.b16 {%0,%1,%2,%3}, [%4];"
        : "=r"(r[0]), "=r"(r[1]), "=r"(r[2]), "=r"(r[3]) : "r"(addr));
}

__device__ __forceinline__ void mma_bf16(float* c, const uint32_t* a,
                                         const uint32_t* b) {
    asm volatile(
        "mma.sync.aligned.m16n8k16.row.col.f32.bf16.bf16.f32 "
        "{%0,%1,%2,%3}, {%4,%5,%6,%7}, {%8,%9}, {%0,%1,%2,%3};"
        : "+f"(c[0]), "+f"(c[1]), "+f"(c[2]), "+f"(c[3])
        : "r"(a[0]), "r"(a[1]), "r"(a[2]), "r"(a[3]), "r"(b[0]), "r"(b[1]));
}

__device__ __forceinline__ __nv_bfloat162 split_hi2(float a, float b,
                                                    float& ra, float& rb) {
    __nv_bfloat16 ha = __float2bfloat16(a);
    __nv_bfloat16 hb = __float2bfloat16(b);
    ra = a - __bfloat162float(ha);
    rb = b - __bfloat162float(hb);
    return __nv_bfloat162(ha, hb);
}

// ======================= bf16 HMMA GEMM =======================
// D[m,n] = sum_{k<3072} A2[m,k] * B2[n,k] + bias[n]
// CTA 128x128, 256 threads (8 warps: 4m x 2n), warp tile 32x64.
// K-chunk 96, double-buffered cp.async (R4-proven structure).
template <int HEADLAYOUT>
__device__ __forceinline__ void mma_gemm_body(
    const __nv_bfloat16* __restrict__ A2, const __nv_bfloat16* __restrict__ B2,
    const float* __restrict__ bias, float* __restrict__ out, bool relu) {
    extern __shared__ char smem[];
    const int tid = threadIdx.x;
    const int wid = tid >> 5;
    const int lane = tid & 31;
    const int wm = wid & 3;
    const int wn = wid >> 2;
    const int m0 = blockIdx.y * 128;
    const int n0 = blockIdx.x * 128;

    float acc[2][8][4];
#pragma unroll
    for (int i = 0; i < 2; i++)
#pragma unroll
        for (int j = 0; j < 8; j++)
#pragma unroll
            for (int c = 0; c < 4; c++) acc[i][j][c] = 0.f;

    auto stA = [&](int s) {
        return reinterpret_cast<__nv_bfloat16*>(smem + s * STAGE_BYTES);
    };
    auto stB = [&](int s) {
        return reinterpret_cast<__nv_bfloat16*>(smem + s * STAGE_BYTES) +
               STAGE_HALF;
    };

    // 128 rows x 96 elems per operand: 1536 cp16 -> 6/thread each
    auto load_chunk = [&](int s, int k0) {
        __nv_bfloat16* a = stA(s);
        __nv_bfloat16* b = stB(s);
#pragma unroll
        for (int i = 0; i < 6; i++) {
            int c = tid + i * 256;
            int row = c / 12;
            int seg = (c % 12) * 8;
            cp_async16(smem_u32(a + row * ROWP + seg),
                       A2 + (size_t)(m0 + row) * K3 + k0 + seg);
            cp_async16(smem_u32(b + row * ROWP + seg),
                       B2 + (size_t)(n0 + row) * K3 + k0 + seg);
        }
        asm volatile("cp.async.commit_group;\n" ::: "memory");
    };

    load_chunk(0, 0);

    const int a_row = lane & 15;
    const int a_c8 = (lane >> 4) * 8;
    const int b_row = (lane & 7) | ((lane & 16) >> 1);
    const int b_c8 = ((lane >> 3) & 1) * 8;

    for (int ch = 0; ch < NCH; ch++) {
        if (ch + 1 < NCH) {
            load_chunk((ch + 1) & 1, (ch + 1) * BK);
            cp_wait<1>();
        } else {
            cp_wait<0>();
        }
        __syncthreads();

        const int buf = ch & 1;
        const uint32_t sbA = smem_u32(stA(buf));
        const uint32_t sbB = smem_u32(stB(buf));

#pragma unroll
        for (int kk = 0; kk < 6; kk++) {
            uint32_t a[2][4], b[8][2];
#pragma unroll
            for (int mt = 0; mt < 2; mt++) {
                uint32_t addr = sbA +
                    2 * ((32 * wm + 16 * mt + a_row) * ROWP + kk * 16 + a_c8);
                ldm_x4(a[mt], addr);
            }
#pragma unroll
            for (int np = 0; np < 4; np++) {
                uint32_t r[4];
                uint32_t addr = sbB +
                    2 * ((64 * wn + 16 * np + b_row) * ROWP + kk * 16 + b_c8);
                ldm_x4(r, addr);
                b[np * 2][0] = r[0]; b[np * 2][1] = r[1];
                b[np * 2 + 1][0] = r[2]; b[np * 2 + 1][1] = r[3];
            }
#pragma unroll
            for (int mt = 0; mt < 2; mt++)
#pragma unroll
                for (int nt = 0; nt < 8; nt++)
                    mma_bf16(acc[mt][nt], a[mt], b[nt]);
        }
        __syncthreads();
    }

    const int g = lane >> 2;
    const int tq = lane & 3;
#pragma unroll
    for (int nt = 0; nt < 8; nt++) {
        const int n = n0 + 64 * wn + 8 * nt + 2 * tq;
        const float b0 = __ldg(bias + n);
        const float b1 = __ldg(bias + n + 1);
#pragma unroll
        for (int mt = 0; mt < 2; mt++) {
            const int mbase = m0 + 32 * wm + 16 * mt + g;
#pragma unroll
            for (int half = 0; half < 2; half++) {
                const int m = mbase + half * 8;
                float v0 = acc[mt][nt][half * 2] + b0;
                float v1 = acc[mt][nt][half * 2 + 1] + b1;
                if (relu) { v0 = fmaxf(v0, 0.f); v1 = fmaxf(v1, 0.f); }
                float2 t = make_float2(v0, v1);
                if (HEADLAYOUT) {
                    *reinterpret_cast<float2*>(
                        out + (size_t)(n >> 6) * HWD + (size_t)m * 64 +
                        (n & 63)) = t;
                } else {
                    *reinterpret_cast<float2*>(out + (size_t)m * E_DIM + n) = t;
                }
            }
        }
    }
}

__global__ __launch_bounds__(256, 2) void qkv_mma_kernel(
    const __nv_bfloat16* __restrict__ a2, const __nv_bfloat16* __restrict__ b2,
    const float* __restrict__ bq, const float* __restrict__ bk,
    const float* __restrict__ bv, float* gq, float* gk, float* gv) {
    const size_t WSZ = (size_t)E_DIM * K3;
    const __nv_bfloat16* B = b2 + (size_t)blockIdx.z * WSZ;
    const float* bias;
    float* outp;
    bool relu;
    if (blockIdx.z == 0) { bias = bq; outp = gq; relu = true; }
    else if (blockIdx.z == 1) { bias = bk; outp = gk; relu = true; }
    else { bias = bv; outp = gv; relu = false; }
    mma_gemm_body<1>(a2, B, bias, outp, relu);
}

__global__ __launch_bounds__(256, 2) void out_mma_kernel(
    const __nv_bfloat16* __restrict__ a2, const __nv_bfloat16* __restrict__ b2,
    const float* __restrict__ bias, float* __restrict__ out) {
    mma_gemm_body<0>(a2, b2, bias, out, false);
}

// ======================= fp32 -> split-bf16 concat =======================
template <int MODEA>
__device__ __forceinline__ void split_one(const float* __restrict__ in,
                                          __nv_bfloat16* __restrict__ out,
                                          int i) {
    float4 v = *reinterpret_cast<const float4*>(in + i);
    float f[4] = {v.x, v.y, v.z, v.w};
    __nv_bfloat16 h[4], l[4];
#pragma unroll
    for (int j = 0; j < 4; j++) {
        h[j] = __float2bfloat16(f[j]);
        l[j] = __float2bfloat16(f[j] - __bfloat162float(h[j]));
    }
    int row = i >> 10;
    int k = i & 1023;
    __nv_bfloat16* base = out + (size_t)row * K3 + k;
    __nv_bfloat162 hp0(h[0], h[1]), hp1(h[2], h[3]);
    __nv_bfloat162 lp0(l[0], l[1]), lp1(l[2], l[3]);
    __nv_bfloat162* p0 = reinterpret_cast<__nv_bfloat162*>(base);
    __nv_bfloat162* p1 = reinterpret_cast<__nv_bfloat162*>(base + E_DIM);
    __nv_bfloat162* p2 = reinterpret_cast<__nv_bfloat162*>(base + 2 * E_DIM);
    p0[0] = hp0; p0[1] = hp1;
    if (MODEA) {
        p1[0] = lp0; p1[1] = lp1;
        p2[0] = hp0; p2[1] = hp1;
    } else {
        p1[0] = hp0; p1[1] = hp1;
        p2[0] = lp0; p2[1] = lp1;
    }
}

__global__ __launch_bounds__(256) void split_a_kernel(
    const float* __restrict__ in, __nv_bfloat16* __restrict__ out, int total) {
    int i = (blockIdx.x * 256 + threadIdx.x) * 4;
    if (i < total) split_one<1>(in, out, i);
}

__global__ __launch_bounds__(256) void split_w_kernel(
    const float* __restrict__ w0, const float* __restrict__ w1,
    const float* __restrict__ w2, const float* __restrict__ w3,
    __nv_bfloat16* __restrict__ out) {
    const float* w = (blockIdx.z == 0) ? w0
                     : (blockIdx.z == 1) ? w1
                     : (blockIdx.z == 2) ? w2 : w3;
    __nv_bfloat16* o = out + (size_t)blockIdx.z * E_DIM * K3;
    int i = (blockIdx.x * 256 + threadIdx.x) * 4;
    split_one<0>(w, o, i);
}

// ======================= fused retention (HMMA, split-bf16) =======================
__global__ __launch_bounds__(256, 3) void retention_kernel(
    const float* __restrict__ kArr, const float* __restrict__ vArr,
    const float* __restrict__ cArr, float* __restrict__ oF,
    __nv_bfloat16* __restrict__ oCat, int mode) {
    extern __shared__ char rsm[];
    const int tid = threadIdx.x;
    const int wid = tid >> 5;
    const int lane = tid & 31;
    const int b = blockIdx.x;
    const int n = b & 15;
    const int idx = b >> 4;

    size_t base;
    int rs;
    if (mode == 0) {
        base = (size_t)n * HWD + (size_t)idx * (WW * DH);
        rs = DH;
    } else {
        base = (size_t)n * HWD + (size_t)idx * DH;
        rs = WW * DH;
    }
    const float* kS = kArr + base;
    const float* vS = vArr + base;
    const float* cS = cArr + base;

    auto conv = [&](const float* src, __nv_bfloat16* dh, __nv_bfloat16* dl) {
#pragma unroll
        for (int i = 0; i < 8; i++) {
            int id = tid + i * 256;
            int w = id >> 4;
            int c = (id & 15) << 2;
            float4 v4 = *reinterpret_cast<const float4*>(src +
                                                         (size_t)w * rs + c);
            float r0, r1, r2, r3;
            __nv_bfloat162 h01 = split_hi2(v4.x, v4.y, r0, r1);
            __nv_bfloat162 h23 = split_hi2(v4.z, v4.w, r2, r3);
            *reinterpret_cast<__nv_bfloat162*>(dh + w * RLD + c) = h01;
            *reinterpret_cast<__nv_bfloat162*>(dh + w * RLD + c + 2) = h23;
            *reinterpret_cast<__nv_bfloat162*>(dl + w * RLD + c) =
                __nv_bfloat162(__float2bfloat16(r0), __float2bfloat16(r1));
            *reinterpret_cast<__nv_bfloat162*>(dl + w * RLD + c + 2) =
                __nv_bfloat162(__float2bfloat16(r2), __float2bfloat16(r3));
        }
    };
    conv(kS, reinterpret_cast<__nv_bfloat16*>(rsm + R_KBH),
         reinterpret_cast<__nv_bfloat16*>(rsm + R_KBL));
    conv(vS, reinterpret_cast<__nv_bfloat16*>(rsm + R_VBH),
         reinterpret_cast<__nv_bfloat16*>(rsm + R_VBL));
    __syncthreads();

    const uint32_t sb = smem_u32(rsm);
    const int g = lane >> 2;
    const int tq = lane & 3;

    // ---- phase A: kvT[e][d] (64x64) via trans ldmatrix ----
    const int e0 = (wid >> 1) * 16;
    const int d0 = (wid & 1) * 32;
    const int ta_row = (lane & 7) + ((lane >> 4) & 1) * 8;
    const int ta_col = ((lane >> 3) & 1) * 8;
    const int tb_row = (lane & 7) + ((lane >> 3) & 1) * 8;
    const int tb_col = ((lane >> 4) & 1) * 8;

    float acc1[4][4];
#pragma unroll
    for (int i = 0; i < 4; i++)
#pragma unroll
        for (int j = 0; j < 4; j++) acc1[i][j] = 0.f;

#pragma unroll
    for (int ks = 0; ks < 8; ks++) {
        const int k0 = ks * 16;
        uint32_t avh[4], avl[4];
        ldm_x4t(avh, sb + R_VBH + 2 * ((k0 + ta_row) * RLD + e0 + ta_col));
        ldm_x4t(avl, sb + R_VBL + 2 * ((k0 + ta_row) * RLD + e0 + ta_col));
#pragma unroll
        for (int nq = 0; nq < 2; nq++) {
            uint32_t bh[4], bl[4];
            ldm_x4t(bh, sb + R_KBH +
                    2 * ((k0 + tb_row) * RLD + d0 + nq * 16 + tb_col));
            ldm_x4t(bl, sb + R_KBL +
                    2 * ((k0 + tb_row) * RLD + d0 + nq * 16 + tb_col));
#pragma unroll
            for (int p = 0; p < 2; p++) {
                const int nt = nq * 2 + p;
                uint32_t bfh[2] = {bh[2 * p], bh[2 * p + 1]};
                uint32_t bfl[2] = {bl[2 * p], bl[2 * p + 1]};
                mma_bf16(acc1[nt], avh, bfh);
                mma_bf16(acc1[nt], avh, bfl);
                mma_bf16(acc1[nt], avl, bfh);
            }
        }
    }
    __syncthreads();

    {
        __nv_bfloat16* kvh = reinterpret_cast<__nv_bfloat16*>(rsm + R_KVH);
        __nv_bfloat16* kvl = reinterpret_cast<__nv_bfloat16*>(rsm + R_KVL);
#pragma unroll
        for (int nt = 0; nt < 4; nt++)
#pragma unroll
            for (int half = 0; half < 2; half++) {
                const int e = e0 + g + half * 8;
                const int d = d0 + nt * 8 + 2 * tq;
                float r0, r1;
                __nv_bfloat162 hp = split_hi2(acc1[nt][half * 2],
                                              acc1[nt][half * 2 + 1], r0, r1);
                *reinterpret_cast<__nv_bfloat162*>(kvh + e * RLD + d) = hp;
                *reinterpret_cast<__nv_bfloat162*>(kvl + e * RLD + d) =
                    __nv_bfloat162(__float2bfloat16(r0), __float2bfloat16(r1));
            }
    }
    conv(cS, reinterpret_cast<__nv_bfloat16*>(rsm + R_QSH),
         reinterpret_cast<__nv_bfloat16*>(rsm + R_QSL));
    __syncthreads();

    // ---- phase B: out[r][e] (128x64) ----
    const int r0 = wid * 16;
    const int a_row = lane & 15;
    const int a_c8 = (lane >> 4) * 8;
    const int b_row = (lane & 7) | ((lane & 16) >> 1);
    const int b_c8 = ((lane >> 3) & 1) * 8;

    float acc2[8][4];
#pragma unroll
    for (int i = 0; i < 8; i++)
#pragma unroll
        for (int j = 0; j < 4; j++) acc2[i][j] = 0.f;

#pragma unroll
    for (int ks = 0; ks < 4; ks++) {
        const int k0 = ks * 16;
        uint32_t aqh[4], aql[4];
        ldm_x4(aqh, sb + R_QSH + 2 * ((r0 + a_row) * RLD + k0 + a_c8));
        ldm_x4(aql, sb + R_QSL + 2 * ((r0 + a_row) * RLD + k0 + a_c8));
#pragma unroll
        for (int nq = 0; nq < 4; nq++) {
            uint32_t kh[4], kl[4];
            ldm_x4(kh, sb + R_KVH +
                   2 * ((nq * 16 + b_row) * RLD + k0 + b_c8));
            ldm_x4(kl, sb + R_KVL +
                   2 * ((nq * 16 + b_row) * RLD + k0 + b_c8));
#pragma unroll
            for (int p = 0; p < 2; p++) {
                const int nt = nq * 2 + p;
                uint32_t bfh[2] = {kh[2 * p], kh[2 * p + 1]};
                uint32_t bfl[2] = {kl[2 * p], kl[2 * p + 1]};
                mma_bf16(acc2[nt], aqh, bfh);
                mma_bf16(acc2[nt], aqh, bfl);
                mma_bf16(acc2[nt], aql, bfh);
            }
        }
    }

#pragma unroll
    for (int nt = 0; nt < 8; nt++) {
        const int e = nt * 8 + 2 * tq;
#pragma unroll
        for (int half = 0; half < 2; half++) {
            const int r = r0 + g + half * 8;
            float v0 = acc2[nt][half * 2];
            float v1 = acc2[nt][half * 2 + 1];
            if (mode == 0) {
                *reinterpret_cast<float2*>(oF + base + (size_t)r * DH + e) =
                    make_float2(v0, v1);
            } else {
                const int m = r * WW + idx;
                float rr0, rr1;
                __nv_bfloat162 hp = split_hi2(v0, v1, rr0, rr1);
                __nv_bfloat162 lp(__float2bfloat16(rr0), __float2bfloat16(rr1));
                __nv_bfloat16* bp = oCat + (size_t)m * K3 + n * DH + e;
                *reinterpret_cast<__nv_bfloat162*>(bp) = hp;
                *reinterpret_cast<__nv_bfloat162*>(bp + E_DIM) = lp;
                *reinterpret_cast<__nv_bfloat162*>(bp + 2 * E_DIM) = hp;
            }
        }
    }
}

// =======================================================================
extern "C" void kernel_launch(void* const* d_in, const int* in_sizes, int n_in,
                              void* d_out, int out_size) {
    const float* x  = (const float*)d_in[0];
    const float* Wq = (const float*)d_in[1];
    const float* bq = (const float*)d_in[2];
    const float* Wk = (const float*)d_in[3];
    const float* bk = (const float*)d_in[4];
    const float* Wv = (const float*)d_in[5];
    const float* bv = (const float*)d_in[6];
    const float* Wo = (const float*)d_in[7];
    const float* bo = (const float*)d_in[8];
    float* out = (float*)d_out;

    __nv_bfloat16 *a2, *b2, *o2cat;
    float *gq, *gk, *gv, *go1;
    cudaGetSymbolAddress((void**)&a2, g_a2);
    cudaGetSymbolAddress((void**)&b2, g_b2);
    cudaGetSymbolAddress((void**)&o2cat, g_o2cat);
    cudaGetSymbolAddress((void**)&gq, g_q);
    cudaGetSymbolAddress((void**)&gk, g_k);
    cudaGetSymbolAddress((void**)&gv, g_v);
    cudaGetSymbolAddress((void**)&go1, g_o1);

    const size_t WSZ = (size_t)E_DIM * K3;
    const int WTOT = E_DIM * E_DIM;

    cudaFuncSetAttribute(qkv_mma_kernel,
                         cudaFuncAttributeMaxDynamicSharedMemorySize,
                         SMEM_TOTAL);
    cudaFuncSetAttribute(out_mma_kernel,
                         cudaFuncAttributeMaxDynamicSharedMemorySize,
                         SMEM_TOTAL);
    cudaFuncSetAttribute(retention_kernel,
                         cudaFuncAttributeMaxDynamicSharedMemorySize,
                         RET_SMEM);

    // splits
    int nx = MROWS * E_DIM;
    split_a_kernel<<<nx / 1024, 256>>>(x, a2, nx);
    dim3 gsw(WTOT / 1024, 1, 4);
    split_w_kernel<<<gsw, 256>>>(Wq, Wk, Wv, Wo, b2);

    // q/k/v projections (HMMA)
    dim3 gqkv(E_DIM / 128, MROWS / 128, 3);
    qkv_mma_kernel<<<gqkv, 256, SMEM_TOTAL>>>(a2, b2, bq, bk, bv, gq, gk, gv);

    // retention (HMMA split-bf16)
    retention_kernel<<<HH * NHEADS, 256, RET_SMEM>>>(gk, gv, gq, go1, nullptr,
                                                     0);
    retention_kernel<<<WW * NHEADS, 256, RET_SMEM>>>(gk, gv, go1, nullptr,
                                                     o2cat, 1);

    // output projection (HMMA)
    dim3 gout(E_DIM / 128, MROWS / 128, 1);
    out_mma_kernel<<<gout, 256, SMEM_TOTAL>>>(o2cat, b2 + 3 * WSZ, bo, out);
}

// round 9
// speedup vs baseline: 1.1458x; 1.1458x over previous
#include <cuda_runtime.h>
#include <cuda_bf16.h>
#include <cstdint>

#define E_DIM 1024
#define K3 (3 * E_DIM)               /* 3072 concat-K */
#define NHEADS 16
#define DH 64
#define HH 128
#define WW 128
#define MROWS (HH * WW)              /* 16384 */
#define HWD ((size_t)MROWS * DH)

#define BK 64
#define NCH (K3 / BK)                 /* 48 */
#define ROWP 72                       /* padded row (bf16 elems), 144B */
#define TILE_ROWS 128
#define STAGE_HALF (TILE_ROWS * ROWP)
#define STAGE_BYTES (2 * STAGE_HALF * 2)   /* 36864 */
#define SMEM_TOTAL (2 * STAGE_BYTES)       /* 73728 */

/* retention smem layout (dynamic, bytes) */
#define RLD 72                        /* bf16 row pitch (144B) */
#define R_KBH 0
#define R_KBL 18432
#define R_VBH 36864
#define R_VBL 55296
#define R_KVH 0
#define R_KVL 9216
#define R_QSH 18432
#define R_QSL 36864
#define RET_SMEM 73728

// ---------------- scratch (static device arrays; no allocation) ----------------
__device__ __nv_bfloat16 g_a2[(size_t)MROWS * K3];        // [Ah|Al|Ah] of x
__device__ __nv_bfloat16 g_b2[4][(size_t)E_DIM * K3];     // [Wh|Wh|Wl] per weight
__device__ __nv_bfloat16 g_o2cat[(size_t)MROWS * K3];     // [hi|lo|hi] of o2
__device__ float g_q[(size_t)NHEADS * MROWS * DH];
__device__ float g_k[(size_t)NHEADS * MROWS * DH];
__device__ float g_v[(size_t)NHEADS * MROWS * DH];
__device__ float g_o1[(size_t)NHEADS * MROWS * DH];

// ======================= helpers =======================
__device__ __forceinline__ uint32_t smem_u32(const void* p) {
    uint32_t a;
    asm("{ .reg .u64 t; cvta.to.shared.u64 t, %1; cvt.u32.u64 %0, t; }"
        : "=r"(a) : "l"(p));
    return a;
}

__device__ __forceinline__ void cp_async16(uint32_t dst, const void* src) {
    asm volatile("cp.async.cg.shared.global [%0], [%1], 16;\n"
                 :: "r"(dst), "l"(src) : "memory");
}

template <int N>
__device__ __forceinline__ void cp_wait() {
    asm volatile("cp.async.wait_group %0;\n" :: "n"(N) : "memory");
}

__device__ __forceinline__ void ldm_x4(uint32_t* r, uint32_t addr) {
    asm volatile(
        "ldmatrix.sync.aligned.m8n8.x4.shared.b16 {%0,%1,%2,%3}, [%4];"
        : "=r"(r[0]), "=r"(r[1]), "=r"(r[2]), "=r"(r[3]) : "r"(addr));
}

__device__ __forceinline__ void ldm_x4t(uint32_t* r, uint32_t addr) {
    asm volatile(
        "ldmatrix.sync.aligned.m8n8.x4.trans.shared.b16 {%0,%1,%2,%3}, [%4];"
        : "=r"(r[0]), "=r"(r[1]), "=r"(r[2]), "=r"(r[3]) : "r"(addr));
}

__device__ __forceinline__ void mma_bf16(float* c, const uint32_t* a,
                                         const uint32_t* b) {
    asm volatile(
        "mma.sync.aligned.m16n8k16.row.col.f32.bf16.bf16.f32 "
        "{%0,%1,%2,%3}, {%4,%5,%6,%7}, {%8,%9}, {%0,%1,%2,%3};"
        : "+f"(c[0]), "+f"(c[1]), "+f"(c[2]), "+f"(c[3])
        : "r"(a[0]), "r"(a[1]), "r"(a[2]), "r"(a[3]), "r"(b[0]), "r"(b[1]));
}

__device__ __forceinline__ __nv_bfloat162 split_hi2(float a, float b,
                                                    float& ra, float& rb) {
    __nv_bfloat16 ha = __float2bfloat16(a);
    __nv_bfloat16 hb = __float2bfloat16(b);
    ra = a - __bfloat162float(ha);
    rb = b - __bfloat162float(hb);
    return __nv_bfloat162(ha, hb);
}

// ======================= bf16 HMMA GEMM (R4/R5-proven config) =======================
// D[m,n] = sum_{k<3072} A2[m,k] * B2[n,k] + bias[n]
// CTA 128x128, 256 threads (8 warps: 4m x 2n), warp tile 32x64.
// K-chunk 64, double-buffered cp.async.
template <int HEADLAYOUT>
__device__ __forceinline__ void mma_gemm_body(
    const __nv_bfloat16* __restrict__ A2, const __nv_bfloat16* __restrict__ B2,
    const float* __restrict__ bias, float* __restrict__ out, bool relu) {
    extern __shared__ char smem[];
    const int tid = threadIdx.x;
    const int wid = tid >> 5;
    const int lane = tid & 31;
    const int wm = wid & 3;
    const int wn = wid >> 2;
    const int m0 = blockIdx.y * 128;
    const int n0 = blockIdx.x * 128;

    float acc[2][8][4];
#pragma unroll
    for (int i = 0; i < 2; i++)
#pragma unroll
        for (int j = 0; j < 8; j++)
#pragma unroll
            for (int c = 0; c < 4; c++) acc[i][j][c] = 0.f;

    auto stA = [&](int s) {
        return reinterpret_cast<__nv_bfloat16*>(smem + s * STAGE_BYTES);
    };
    auto stB = [&](int s) {
        return reinterpret_cast<__nv_bfloat16*>(smem + s * STAGE_BYTES) +
               STAGE_HALF;
    };

    auto load_chunk = [&](int s, int k0) {
        __nv_bfloat16* a = stA(s);
        __nv_bfloat16* b = stB(s);
#pragma unroll
        for (int i = 0; i < 4; i++) {
            int c = tid + i * 256;
            int row = c >> 3;
            int seg = (c & 7) * 8;
            cp_async16(smem_u32(a + row * ROWP + seg),
                       A2 + (size_t)(m0 + row) * K3 + k0 + seg);
            cp_async16(smem_u32(b + row * ROWP + seg),
                       B2 + (size_t)(n0 + row) * K3 + k0 + seg);
        }
        asm volatile("cp.async.commit_group;\n" ::: "memory");
    };

    load_chunk(0, 0);

    const int a_row = lane & 15;
    const int a_c8 = (lane >> 4) * 8;
    const int b_row = (lane & 7) | ((lane & 16) >> 1);
    const int b_c8 = ((lane >> 3) & 1) * 8;

    for (int ch = 0; ch < NCH; ch++) {
        if (ch + 1 < NCH) {
            load_chunk((ch + 1) & 1, (ch + 1) * BK);
            cp_wait<1>();
        } else {
            cp_wait<0>();
        }
        __syncthreads();

        const int buf = ch & 1;
        const uint32_t sbA = smem_u32(stA(buf));
        const uint32_t sbB = smem_u32(stB(buf));

#pragma unroll
        for (int kk = 0; kk < 4; kk++) {
            uint32_t a[2][4], b[8][2];
#pragma unroll
            for (int mt = 0; mt < 2; mt++) {
                uint32_t addr = sbA +
                    2 * ((32 * wm + 16 * mt + a_row) * ROWP + kk * 16 + a_c8);
                ldm_x4(a[mt], addr);
            }
#pragma unroll
            for (int np = 0; np < 4; np++) {
                uint32_t r[4];
                uint32_t addr = sbB +
                    2 * ((64 * wn + 16 * np + b_row) * ROWP + kk * 16 + b_c8);
                ldm_x4(r, addr);
                b[np * 2][0] = r[0]; b[np * 2][1] = r[1];
                b[np * 2 + 1][0] = r[2]; b[np * 2 + 1][1] = r[3];
            }
#pragma unroll
            for (int mt = 0; mt < 2; mt++)
#pragma unroll
                for (int nt = 0; nt < 8; nt++)
                    mma_bf16(acc[mt][nt], a[mt], b[nt]);
        }
        __syncthreads();
    }

    const int g = lane >> 2;
    const int tq = lane & 3;
#pragma unroll
    for (int nt = 0; nt < 8; nt++) {
        const int n = n0 + 64 * wn + 8 * nt + 2 * tq;
        const float b0 = __ldg(bias + n);
        const float b1 = __ldg(bias + n + 1);
#pragma unroll
        for (int mt = 0; mt < 2; mt++) {
            const int mbase = m0 + 32 * wm + 16 * mt + g;
#pragma unroll
            for (int half = 0; half < 2; half++) {
                const int m = mbase + half * 8;
                float v0 = acc[mt][nt][half * 2] + b0;
                float v1 = acc[mt][nt][half * 2 + 1] + b1;
                if (relu) { v0 = fmaxf(v0, 0.f); v1 = fmaxf(v1, 0.f); }
                float2 t = make_float2(v0, v1);
                if (HEADLAYOUT) {
                    *reinterpret_cast<float2*>(
                        out + (size_t)(n >> 6) * HWD + (size_t)m * 64 +
                        (n & 63)) = t;
                } else {
                    *reinterpret_cast<float2*>(out + (size_t)m * E_DIM + n) = t;
                }
            }
        }
    }
}

__global__ __launch_bounds__(256, 2) void qkv_mma_kernel(
    const __nv_bfloat16* __restrict__ a2, const __nv_bfloat16* __restrict__ b2,
    const float* __restrict__ bq, const float* __restrict__ bk,
    const float* __restrict__ bv, float* gq, float* gk, float* gv) {
    const size_t WSZ = (size_t)E_DIM * K3;
    const __nv_bfloat16* B = b2 + (size_t)blockIdx.z * WSZ;
    const float* bias;
    float* outp;
    bool relu;
    if (blockIdx.z == 0) { bias = bq; outp = gq; relu = true; }
    else if (blockIdx.z == 1) { bias = bk; outp = gk; relu = true; }
    else { bias = bv; outp = gv; relu = false; }
    mma_gemm_body<1>(a2, B, bias, outp, relu);
}

__global__ __launch_bounds__(256, 2) void out_mma_kernel(
    const __nv_bfloat16* __restrict__ a2, const __nv_bfloat16* __restrict__ b2,
    const float* __restrict__ bias, float* __restrict__ out) {
    mma_gemm_body<0>(a2, b2, bias, out, false);
}

// ======================= fp32 -> split-bf16 concat =======================
template <int MODEA>
__device__ __forceinline__ void split_one(const float* __restrict__ in,
                                          __nv_bfloat16* __restrict__ out,
                                          int i) {
    float4 v = *reinterpret_cast<const float4*>(in + i);
    float f[4] = {v.x, v.y, v.z, v.w};
    __nv_bfloat16 h[4], l[4];
#pragma unroll
    for (int j = 0; j < 4; j++) {
        h[j] = __float2bfloat16(f[j]);
        l[j] = __float2bfloat16(f[j] - __bfloat162float(h[j]));
    }
    int row = i >> 10;
    int k = i & 1023;
    __nv_bfloat16* base = out + (size_t)row * K3 + k;
    __nv_bfloat162 hp0(h[0], h[1]), hp1(h[2], h[3]);
    __nv_bfloat162 lp0(l[0], l[1]), lp1(l[2], l[3]);
    __nv_bfloat162* p0 = reinterpret_cast<__nv_bfloat162*>(base);
    __nv_bfloat162* p1 = reinterpret_cast<__nv_bfloat162*>(base + E_DIM);
    __nv_bfloat162* p2 = reinterpret_cast<__nv_bfloat162*>(base + 2 * E_DIM);
    p0[0] = hp0; p0[1] = hp1;
    if (MODEA) {
        p1[0] = lp0; p1[1] = lp1;
        p2[0] = hp0; p2[1] = hp1;
    } else {
        p1[0] = hp0; p1[1] = hp1;
        p2[0] = lp0; p2[1] = lp1;
    }
}

__global__ __launch_bounds__(256) void split_a_kernel(
    const float* __restrict__ in, __nv_bfloat16* __restrict__ out, int total) {
    int i = (blockIdx.x * 256 + threadIdx.x) * 4;
    if (i < total) split_one<1>(in, out, i);
}

__global__ __launch_bounds__(256) void split_w_kernel(
    const float* __restrict__ w0, const float* __restrict__ w1,
    const float* __restrict__ w2, const float* __restrict__ w3,
    __nv_bfloat16* __restrict__ out) {
    const float* w = (blockIdx.z == 0) ? w0
                     : (blockIdx.z == 1) ? w1
                     : (blockIdx.z == 2) ? w2 : w3;
    __nv_bfloat16* o = out + (size_t)blockIdx.z * E_DIM * K3;
    int i = (blockIdx.x * 256 + threadIdx.x) * 4;
    split_one<0>(w, o, i);
}

// ======================= fused retention (HMMA, split-bf16; R5-proven) =======================
__global__ __launch_bounds__(256, 2) void retention_kernel(
    const float* __restrict__ kArr, const float* __restrict__ vArr,
    const float* __restrict__ cArr, float* __restrict__ oF,
    __nv_bfloat16* __restrict__ oCat, int mode) {
    extern __shared__ char rsm[];
    const int tid = threadIdx.x;
    const int wid = tid >> 5;
    const int lane = tid & 31;
    const int b = blockIdx.x;
    const int n = b & 15;
    const int idx = b >> 4;

    size_t base;
    int rs;
    if (mode == 0) {
        base = (size_t)n * HWD + (size_t)idx * (WW * DH);
        rs = DH;
    } else {
        base = (size_t)n * HWD + (size_t)idx * DH;
        rs = WW * DH;
    }
    const float* kS = kArr + base;
    const float* vS = vArr + base;
    const float* cS = cArr + base;

    auto conv = [&](const float* src, __nv_bfloat16* dh, __nv_bfloat16* dl) {
#pragma unroll
        for (int i = 0; i < 8; i++) {
            int id = tid + i * 256;
            int w = id >> 4;
            int c = (id & 15) << 2;
            float4 v4 = *reinterpret_cast<const float4*>(src +
                                                         (size_t)w * rs + c);
            float r0, r1, r2, r3;
            __nv_bfloat162 h01 = split_hi2(v4.x, v4.y, r0, r1);
            __nv_bfloat162 h23 = split_hi2(v4.z, v4.w, r2, r3);
            *reinterpret_cast<__nv_bfloat162*>(dh + w * RLD + c) = h01;
            *reinterpret_cast<__nv_bfloat162*>(dh + w * RLD + c + 2) = h23;
            *reinterpret_cast<__nv_bfloat162*>(dl + w * RLD + c) =
                __nv_bfloat162(__float2bfloat16(r0), __float2bfloat16(r1));
            *reinterpret_cast<__nv_bfloat162*>(dl + w * RLD + c + 2) =
                __nv_bfloat162(__float2bfloat16(r2), __float2bfloat16(r3));
        }
    };
    conv(kS, reinterpret_cast<__nv_bfloat16*>(rsm + R_KBH),
         reinterpret_cast<__nv_bfloat16*>(rsm + R_KBL));
    conv(vS, reinterpret_cast<__nv_bfloat16*>(rsm + R_VBH),
         reinterpret_cast<__nv_bfloat16*>(rsm + R_VBL));
    __syncthreads();

    const uint32_t sb = smem_u32(rsm);
    const int g = lane >> 2;
    const int tq = lane & 3;

    // ---- phase A: kvT[e][d] (64x64) via trans ldmatrix ----
    const int e0 = (wid >> 1) * 16;
    const int d0 = (wid & 1) * 32;
    const int ta_row = (lane & 7) + ((lane >> 4) & 1) * 8;
    const int ta_col = ((lane >> 3) & 1) * 8;
    const int tb_row = (lane & 7) + ((lane >> 3) & 1) * 8;
    const int tb_col = ((lane >> 4) & 1) * 8;

    float acc1[4][4];
#pragma unroll
    for (int i = 0; i < 4; i++)
#pragma unroll
        for (int j = 0; j < 4; j++) acc1[i][j] = 0.f;

#pragma unroll
    for (int ks = 0; ks < 8; ks++) {
        const int k0 = ks * 16;
        uint32_t avh[4], avl[4];
        ldm_x4t(avh, sb + R_VBH + 2 * ((k0 + ta_row) * RLD + e0 + ta_col));
        ldm_x4t(avl, sb + R_VBL + 2 * ((k0 + ta_row) * RLD + e0 + ta_col));
        uint32_t bh[2][4], bl[2][4];
#pragma unroll
        for (int nq = 0; nq < 2; nq++) {
            ldm_x4t(bh[nq], sb + R_KBH +
                    2 * ((k0 + tb_row) * RLD + d0 + nq * 16 + tb_col));
            ldm_x4t(bl[nq], sb + R_KBL +
                    2 * ((k0 + tb_row) * RLD + d0 + nq * 16 + tb_col));
        }
#pragma unroll
        for (int nq = 0; nq < 2; nq++)
#pragma unroll
            for (int p = 0; p < 2; p++) {
                const int nt = nq * 2 + p;
                uint32_t bfh[2] = {bh[nq][2 * p], bh[nq][2 * p + 1]};
                uint32_t bfl[2] = {bl[nq][2 * p], bl[nq][2 * p + 1]};
                mma_bf16(acc1[nt], avh, bfh);
                mma_bf16(acc1[nt], avh, bfl);
                mma_bf16(acc1[nt], avl, bfh);
            }
    }
    __syncthreads();

    {
        __nv_bfloat16* kvh = reinterpret_cast<__nv_bfloat16*>(rsm + R_KVH);
        __nv_bfloat16* kvl = reinterpret_cast<__nv_bfloat16*>(rsm + R_KVL);
#pragma unroll
        for (int nt = 0; nt < 4; nt++)
#pragma unroll
            for (int half = 0; half < 2; half++) {
                const int e = e0 + g + half * 8;
                const int d = d0 + nt * 8 + 2 * tq;
                float r0, r1;
                __nv_bfloat162 hp = split_hi2(acc1[nt][half * 2],
                                              acc1[nt][half * 2 + 1], r0, r1);
                *reinterpret_cast<__nv_bfloat162*>(kvh + e * RLD + d) = hp;
                *reinterpret_cast<__nv_bfloat162*>(kvl + e * RLD + d) =
                    __nv_bfloat162(__float2bfloat16(r0), __float2bfloat16(r1));
            }
    }
    conv(cS, reinterpret_cast<__nv_bfloat16*>(rsm + R_QSH),
         reinterpret_cast<__nv_bfloat16*>(rsm + R_QSL));
    __syncthreads();

    // ---- phase B: out[r][e] (128x64) ----
    const int r0 = wid * 16;
    const int a_row = lane & 15;
    const int a_c8 = (lane >> 4) * 8;
    const int b_row = (lane & 7) | ((lane & 16) >> 1);
    const int b_c8 = ((lane >> 3) & 1) * 8;

    float acc2[8][4];
#pragma unroll
    for (int i = 0; i < 8; i++)
#pragma unroll
        for (int j = 0; j < 4; j++) acc2[i][j] = 0.f;

#pragma unroll
    for (int ks = 0; ks < 4; ks++) {
        const int k0 = ks * 16;
        uint32_t aqh[4], aql[4];
        ldm_x4(aqh, sb + R_QSH + 2 * ((r0 + a_row) * RLD + k0 + a_c8));
        ldm_x4(aql, sb + R_QSL + 2 * ((r0 + a_row) * RLD + k0 + a_c8));
        uint32_t kh[4][4], kl[4][4];
#pragma unroll
        for (int nq = 0; nq < 4; nq++) {
            ldm_x4(kh[nq], sb + R_KVH +
                   2 * ((nq * 16 + b_row) * RLD + k0 + b_c8));
            ldm_x4(kl[nq], sb + R_KVL +
                   2 * ((nq * 16 + b_row) * RLD + k0 + b_c8));
        }
#pragma unroll
        for (int nt = 0; nt < 8; nt++) {
            const int nq = nt >> 1;
            const int p = nt & 1;
            uint32_t bfh[2] = {kh[nq][2 * p], kh[nq][2 * p + 1]};
            uint32_t bfl[2] = {kl[nq][2 * p], kl[nq][2 * p + 1]};
            mma_bf16(acc2[nt], aqh, bfh);
            mma_bf16(acc2[nt], aqh, bfl);
            mma_bf16(acc2[nt], aql, bfh);
        }
    }

#pragma unroll
    for (int nt = 0; nt < 8; nt++) {
        const int e = nt * 8 + 2 * tq;
#pragma unroll
        for (int half = 0; half < 2; half++) {
            const int r = r0 + g + half * 8;
            float v0 = acc2[nt][half * 2];
            float v1 = acc2[nt][half * 2 + 1];
            if (mode == 0) {
                *reinterpret_cast<float2*>(oF + base + (size_t)r * DH + e) =
                    make_float2(v0, v1);
            } else {
                const int m = r * WW + idx;
                float rr0, rr1;
                __nv_bfloat162 hp = split_hi2(v0, v1, rr0, rr1);
                __nv_bfloat162 lp(__float2bfloat16(rr0), __float2bfloat16(rr1));
                __nv_bfloat16* bp = oCat + (size_t)m * K3 + n * DH + e;
                *reinterpret_cast<__nv_bfloat162*>(bp) = hp;
                *reinterpret_cast<__nv_bfloat162*>(bp + E_DIM) = lp;
                *reinterpret_cast<__nv_bfloat162*>(bp + 2 * E_DIM) = hp;
            }
        }
    }
}

// =======================================================================
extern "C" void kernel_launch(void* const* d_in, const int* in_sizes, int n_in,
                              void* d_out, int out_size) {
    const float* x  = (const float*)d_in[0];
    const float* Wq = (const float*)d_in[1];
    const float* bq = (const float*)d_in[2];
    const float* Wk = (const float*)d_in[3];
    const float* bk = (const float*)d_in[4];
    const float* Wv = (const float*)d_in[5];
    const float* bv = (const float*)d_in[6];
    const float* Wo = (const float*)d_in[7];
    const float* bo = (const float*)d_in[8];
    float* out = (float*)d_out;

    __nv_bfloat16 *a2, *b2, *o2cat;
    float *gq, *gk, *gv, *go1;
    cudaGetSymbolAddress((void**)&a2, g_a2);
    cudaGetSymbolAddress((void**)&b2, g_b2);
    cudaGetSymbolAddress((void**)&o2cat, g_o2cat);
    cudaGetSymbolAddress((void**)&gq, g_q);
    cudaGetSymbolAddress((void**)&gk, g_k);
    cudaGetSymbolAddress((void**)&gv, g_v);
    cudaGetSymbolAddress((void**)&go1, g_o1);

    const size_t WSZ = (size_t)E_DIM * K3;
    const int WTOT = E_DIM * E_DIM;

    cudaFuncSetAttribute(qkv_mma_kernel,
                         cudaFuncAttributeMaxDynamicSharedMemorySize,
                         SMEM_TOTAL);
    cudaFuncSetAttribute(out_mma_kernel,
                         cudaFuncAttributeMaxDynamicSharedMemorySize,
                         SMEM_TOTAL);
    cudaFuncSetAttribute(retention_kernel,
                         cudaFuncAttributeMaxDynamicSharedMemorySize,
                         RET_SMEM);

    // splits (launches 1,2)
    int nx = MROWS * E_DIM;
    split_a_kernel<<<nx / 1024, 256>>>(x, a2, nx);
    dim3 gsw(WTOT / 1024, 1, 4);
    split_w_kernel<<<gsw, 256>>>(Wq, Wk, Wv, Wo, b2);

    // q/k/v projections (launch 3)
    dim3 gqkv(E_DIM / 128, MROWS / 128, 3);
    qkv_mma_kernel<<<gqkv, 256, SMEM_TOTAL>>>(a2, b2, bq, bk, bv, gq, gk, gv);

    // retention (launches 4,5)
    retention_kernel<<<HH * NHEADS, 256, RET_SMEM>>>(gk, gv, gq, go1, nullptr,
                                                     0);
    retention_kernel<<<WW * NHEADS, 256, RET_SMEM>>>(gk, gv, go1, nullptr,
                                                     o2cat, 1);

    // output projection (launch 6 — ncu -s 5 captures this)
    dim3 gout(E_DIM / 128, MROWS / 128, 1);
    out_mma_kernel<<<gout, 256, SMEM_TOTAL>>>(o2cat, b2 + 3 * WSZ, bo, out);
}

// round 10
// speedup vs baseline: 1.2500x; 1.0909x over previous
#include <cuda_runtime.h>
#include <cuda_bf16.h>
#include <cuda_fp16.h>
#include <cstdint>

#define E_DIM 1024
#define K3 (3 * E_DIM)               /* 3072 concat-K (bf16 3-term) */
#define K2 (2 * E_DIM)               /* 2048 concat-K (fp16 2-term) */
#define NHEADS 16
#define DH 64
#define HH 128
#define WW 128
#define MROWS (HH * WW)              /* 16384 */
#define HWD ((size_t)MROWS * DH)

#define BK 64
#define ROWP 72                       /* padded row (elems), 144B */
#define TILE_ROWS 128
#define STAGE_HALF (TILE_ROWS * ROWP)
#define STAGE_BYTES (2 * STAGE_HALF * 2)   /* 36864 */
#define SMEM_TOTAL (2 * STAGE_BYTES)       /* 73728 */

/* retention smem layout (dynamic, bytes) */
#define RLD 72                        /* bf16 row pitch (144B) */
#define R_KBH 0
#define R_KBL 18432
#define R_VBH 36864
#define R_VBL 55296
#define R_KVH 0
#define R_KVL 9216
#define R_QSH 18432
#define R_QSL 36864
#define RET_SMEM 73728

// ---------------- scratch (static device arrays; no allocation) ----------------
__device__ __nv_bfloat16 g_a2[(size_t)MROWS * K3];        // [Ah|Al|Ah] of x
__device__ __nv_bfloat16 g_b2[3][(size_t)E_DIM * K3];     // [Wh|Wh|Wl] q,k,v
__device__ __half g_o2f[(size_t)MROWS * K2];              // [hi|lo] fp16 of o2
__device__ __half g_wo2[(size_t)E_DIM * K2];              // [Wh|Wh] fp16 of Wo
__device__ float g_q[(size_t)NHEADS * MROWS * DH];
__device__ float g_k[(size_t)NHEADS * MROWS * DH];
__device__ float g_v[(size_t)NHEADS * MROWS * DH];
__device__ float g_o1[(size_t)NHEADS * MROWS * DH];

// ======================= helpers =======================
__device__ __forceinline__ uint32_t smem_u32(const void* p) {
    uint32_t a;
    asm("{ .reg .u64 t; cvta.to.shared.u64 t, %1; cvt.u32.u64 %0, t; }"
        : "=r"(a) : "l"(p));
    return a;
}

__device__ __forceinline__ void cp_async16(uint32_t dst, const void* src) {
    asm volatile("cp.async.cg.shared.global [%0], [%1], 16;\n"
                 :: "r"(dst), "l"(src) : "memory");
}

template <int N>
__device__ __forceinline__ void cp_wait() {
    asm volatile("cp.async.wait_group %0;\n" :: "n"(N) : "memory");
}

__device__ __forceinline__ void ldm_x4(uint32_t* r, uint32_t addr) {
    asm volatile(
        "ldmatrix.sync.aligned.m8n8.x4.shared.b16 {%0,%1,%2,%3}, [%4];"
        : "=r"(r[0]), "=r"(r[1]), "=r"(r[2]), "=r"(r[3]) : "r"(addr));
}

__device__ __forceinline__ void ldm_x4t(uint32_t* r, uint32_t addr) {
    asm volatile(
        "ldmatrix.sync.aligned.m8n8.x4.trans.shared.b16 {%0,%1,%2,%3}, [%4];"
        : "=r"(r[0]), "=r"(r[1]), "=r"(r[2]), "=r"(r[3]) : "r"(addr));
}

__device__ __forceinline__ void mma_bf16(float* c, const uint32_t* a,
                                         const uint32_t* b) {
    asm volatile(
        "mma.sync.aligned.m16n8k16.row.col.f32.bf16.bf16.f32 "
        "{%0,%1,%2,%3}, {%4,%5,%6,%7}, {%8,%9}, {%0,%1,%2,%3};"
        : "+f"(c[0]), "+f"(c[1]), "+f"(c[2]), "+f"(c[3])
        : "r"(a[0]), "r"(a[1]), "r"(a[2]), "r"(a[3]), "r"(b[0]), "r"(b[1]));
}

__device__ __forceinline__ void mma_fp16(float* c, const uint32_t* a,
                                         const uint32_t* b) {
    asm volatile(
        "mma.sync.aligned.m16n8k16.row.col.f32.f16.f16.f32 "
        "{%0,%1,%2,%3}, {%4,%5,%6,%7}, {%8,%9}, {%0,%1,%2,%3};"
        : "+f"(c[0]), "+f"(c[1]), "+f"(c[2]), "+f"(c[3])
        : "r"(a[0]), "r"(a[1]), "r"(a[2]), "r"(a[3]), "r"(b[0]), "r"(b[1]));
}

__device__ __forceinline__ __nv_bfloat162 split_hi2(float a, float b,
                                                    float& ra, float& rb) {
    __nv_bfloat16 ha = __float2bfloat16(a);
    __nv_bfloat16 hb = __float2bfloat16(b);
    ra = a - __bfloat162float(ha);
    rb = b - __bfloat162float(hb);
    return __nv_bfloat162(ha, hb);
}

// ======================= HMMA GEMM (proven R4/R5 config, templated K/type) ==
// D[m,n] = sum_{k<KLEN} A2[m,k] * B2[n,k] + bias[n]
// CTA 128x128, 256 threads (8 warps: 4m x 2n), warp tile 32x64.
// K-chunk 64, double-buffered cp.async.
template <int HEADLAYOUT, int KLEN, bool FP16, typename T>
__device__ __forceinline__ void mma_gemm_body(
    const T* __restrict__ A2, const T* __restrict__ B2,
    const float* __restrict__ bias, float* __restrict__ out, bool relu) {
    extern __shared__ char smem[];
    const int tid = threadIdx.x;
    const int wid = tid >> 5;
    const int lane = tid & 31;
    const int wm = wid & 3;
    const int wn = wid >> 2;
    const int m0 = blockIdx.y * 128;
    const int n0 = blockIdx.x * 128;
    constexpr int NCH = KLEN / BK;

    float acc[2][8][4];
#pragma unroll
    for (int i = 0; i < 2; i++)
#pragma unroll
        for (int j = 0; j < 8; j++)
#pragma unroll
            for (int c = 0; c < 4; c++) acc[i][j][c] = 0.f;

    auto stA = [&](int s) {
        return reinterpret_cast<T*>(smem + s * STAGE_BYTES);
    };
    auto stB = [&](int s) {
        return reinterpret_cast<T*>(smem + s * STAGE_BYTES) + STAGE_HALF;
    };

    auto load_chunk = [&](int s, int k0) {
        T* a = stA(s);
        T* b = stB(s);
#pragma unroll
        for (int i = 0; i < 4; i++) {
            int c = tid + i * 256;
            int row = c >> 3;
            int seg = (c & 7) * 8;
            cp_async16(smem_u32(a + row * ROWP + seg),
                       A2 + (size_t)(m0 + row) * KLEN + k0 + seg);
            cp_async16(smem_u32(b + row * ROWP + seg),
                       B2 + (size_t)(n0 + row) * KLEN + k0 + seg);
        }
        asm volatile("cp.async.commit_group;\n" ::: "memory");
    };

    load_chunk(0, 0);

    const int a_row = lane & 15;
    const int a_c8 = (lane >> 4) * 8;
    const int b_row = (lane & 7) | ((lane & 16) >> 1);
    const int b_c8 = ((lane >> 3) & 1) * 8;

    for (int ch = 0; ch < NCH; ch++) {
        if (ch + 1 < NCH) {
            load_chunk((ch + 1) & 1, (ch + 1) * BK);
            cp_wait<1>();
        } else {
            cp_wait<0>();
        }
        __syncthreads();

        const int buf = ch & 1;
        const uint32_t sbA = smem_u32(stA(buf));
        const uint32_t sbB = smem_u32(stB(buf));

#pragma unroll
        for (int kk = 0; kk < 4; kk++) {
            uint32_t a[2][4], b[8][2];
#pragma unroll
            for (int mt = 0; mt < 2; mt++) {
                uint32_t addr = sbA +
                    2 * ((32 * wm + 16 * mt + a_row) * ROWP + kk * 16 + a_c8);
                ldm_x4(a[mt], addr);
            }
#pragma unroll
            for (int np = 0; np < 4; np++) {
                uint32_t r[4];
                uint32_t addr = sbB +
                    2 * ((64 * wn + 16 * np + b_row) * ROWP + kk * 16 + b_c8);
                ldm_x4(r, addr);
                b[np * 2][0] = r[0]; b[np * 2][1] = r[1];
                b[np * 2 + 1][0] = r[2]; b[np * 2 + 1][1] = r[3];
            }
#pragma unroll
            for (int mt = 0; mt < 2; mt++)
#pragma unroll
                for (int nt = 0; nt < 8; nt++) {
                    if (FP16)
                        mma_fp16(acc[mt][nt], a[mt], b[nt]);
                    else
                        mma_bf16(acc[mt][nt], a[mt], b[nt]);
                }
        }
        __syncthreads();
    }

    const int g = lane >> 2;
    const int tq = lane & 3;
#pragma unroll
    for (int nt = 0; nt < 8; nt++) {
        const int n = n0 + 64 * wn + 8 * nt + 2 * tq;
        const float b0 = __ldg(bias + n);
        const float b1 = __ldg(bias + n + 1);
#pragma unroll
        for (int mt = 0; mt < 2; mt++) {
            const int mbase = m0 + 32 * wm + 16 * mt + g;
#pragma unroll
            for (int half = 0; half < 2; half++) {
                const int m = mbase + half * 8;
                float v0 = acc[mt][nt][half * 2] + b0;
                float v1 = acc[mt][nt][half * 2 + 1] + b1;
                if (relu) { v0 = fmaxf(v0, 0.f); v1 = fmaxf(v1, 0.f); }
                float2 t = make_float2(v0, v1);
                if (HEADLAYOUT) {
                    *reinterpret_cast<float2*>(
                        out + (size_t)(n >> 6) * HWD + (size_t)m * 64 +
                        (n & 63)) = t;
                } else {
                    *reinterpret_cast<float2*>(out + (size_t)m * E_DIM + n) = t;
                }
            }
        }
    }
}

__global__ __launch_bounds__(256, 2) void qkv_mma_kernel(
    const __nv_bfloat16* __restrict__ a2, const __nv_bfloat16* __restrict__ b2,
    const float* __restrict__ bq, const float* __restrict__ bk,
    const float* __restrict__ bv, float* gq, float* gk, float* gv) {
    const size_t WSZ = (size_t)E_DIM * K3;
    const __nv_bfloat16* B = b2 + (size_t)blockIdx.z * WSZ;
    const float* bias;
    float* outp;
    bool relu;
    if (blockIdx.z == 0) { bias = bq; outp = gq; relu = true; }
    else if (blockIdx.z == 1) { bias = bk; outp = gk; relu = true; }
    else { bias = bv; outp = gv; relu = false; }
    mma_gemm_body<1, K3, false>(a2, B, bias, outp, relu);
}

__global__ __launch_bounds__(256, 2) void out_mma_kernel(
    const __half* __restrict__ a2, const __half* __restrict__ b2,
    const float* __restrict__ bias, float* __restrict__ out) {
    mma_gemm_body<0, K2, true>(a2, b2, bias, out, false);
}

// ======================= fp32 -> split concat kernels =======================
template <int MODEA>
__device__ __forceinline__ void split_one(const float* __restrict__ in,
                                          __nv_bfloat16* __restrict__ out,
                                          int i) {
    float4 v = *reinterpret_cast<const float4*>(in + i);
    float f[4] = {v.x, v.y, v.z, v.w};
    __nv_bfloat16 h[4], l[4];
#pragma unroll
    for (int j = 0; j < 4; j++) {
        h[j] = __float2bfloat16(f[j]);
        l[j] = __float2bfloat16(f[j] - __bfloat162float(h[j]));
    }
    int row = i >> 10;
    int k = i & 1023;
    __nv_bfloat16* base = out + (size_t)row * K3 + k;
    __nv_bfloat162 hp0(h[0], h[1]), hp1(h[2], h[3]);
    __nv_bfloat162 lp0(l[0], l[1]), lp1(l[2], l[3]);
    __nv_bfloat162* p0 = reinterpret_cast<__nv_bfloat162*>(base);
    __nv_bfloat162* p1 = reinterpret_cast<__nv_bfloat162*>(base + E_DIM);
    __nv_bfloat162* p2 = reinterpret_cast<__nv_bfloat162*>(base + 2 * E_DIM);
    p0[0] = hp0; p0[1] = hp1;
    if (MODEA) {
        p1[0] = lp0; p1[1] = lp1;
        p2[0] = hp0; p2[1] = hp1;
    } else {
        p1[0] = hp0; p1[1] = hp1;
        p2[0] = lp0; p2[1] = lp1;
    }
}

__global__ __launch_bounds__(256) void split_a_kernel(
    const float* __restrict__ in, __nv_bfloat16* __restrict__ out, int total) {
    int i = (blockIdx.x * 256 + threadIdx.x) * 4;
    if (i < total) split_one<1>(in, out, i);
}

__global__ __launch_bounds__(256) void split_w_kernel(
    const float* __restrict__ w0, const float* __restrict__ w1,
    const float* __restrict__ w2, __nv_bfloat16* __restrict__ out) {
    const float* w = (blockIdx.z == 0) ? w0
                     : (blockIdx.z == 1) ? w1 : w2;
    __nv_bfloat16* o = out + (size_t)blockIdx.z * E_DIM * K3;
    int i = (blockIdx.x * 256 + threadIdx.x) * 4;
    split_one<0>(w, o, i);
}

// Wo -> fp16 [Wh | Wh] (duplicated hi), K2 layout
__global__ __launch_bounds__(256) void split_wo_kernel(
    const float* __restrict__ w, __half* __restrict__ out) {
    int i = (blockIdx.x * 256 + threadIdx.x) * 4;
    float4 v = *reinterpret_cast<const float4*>(w + i);
    __half2 p0(__float2half(v.x), __float2half(v.y));
    __half2 p1(__float2half(v.z), __float2half(v.w));
    int row = i >> 10;
    int k = i & 1023;
    __half* base = out + (size_t)row * K2 + k;
    reinterpret_cast<__half2*>(base)[0] = p0;
    reinterpret_cast<__half2*>(base)[1] = p1;
    reinterpret_cast<__half2*>(base + E_DIM)[0] = p0;
    reinterpret_cast<__half2*>(base + E_DIM)[1] = p1;
}

// ======================= fused retention (HMMA, split-bf16; R5-proven) ======
__global__ __launch_bounds__(256, 2) void retention_kernel(
    const float* __restrict__ kArr, const float* __restrict__ vArr,
    const float* __restrict__ cArr, float* __restrict__ oF,
    __half* __restrict__ oCat, int mode) {
    extern __shared__ char rsm[];
    const int tid = threadIdx.x;
    const int wid = tid >> 5;
    const int lane = tid & 31;
    const int b = blockIdx.x;
    const int n = b & 15;
    const int idx = b >> 4;

    size_t base;
    int rs;
    if (mode == 0) {
        base = (size_t)n * HWD + (size_t)idx * (WW * DH);
        rs = DH;
    } else {
        base = (size_t)n * HWD + (size_t)idx * DH;
        rs = WW * DH;
    }
    const float* kS = kArr + base;
    const float* vS = vArr + base;
    const float* cS = cArr + base;

    auto conv = [&](const float* src, __nv_bfloat16* dh, __nv_bfloat16* dl) {
#pragma unroll
        for (int i = 0; i < 8; i++) {
            int id = tid + i * 256;
            int w = id >> 4;
            int c = (id & 15) << 2;
            float4 v4 = *reinterpret_cast<const float4*>(src +
                                                         (size_t)w * rs + c);
            float r0, r1, r2, r3;
            __nv_bfloat162 h01 = split_hi2(v4.x, v4.y, r0, r1);
            __nv_bfloat162 h23 = split_hi2(v4.z, v4.w, r2, r3);
            *reinterpret_cast<__nv_bfloat162*>(dh + w * RLD + c) = h01;
            *reinterpret_cast<__nv_bfloat162*>(dh + w * RLD + c + 2) = h23;
            *reinterpret_cast<__nv_bfloat162*>(dl + w * RLD + c) =
                __nv_bfloat162(__float2bfloat16(r0), __float2bfloat16(r1));
            *reinterpret_cast<__nv_bfloat162*>(dl + w * RLD + c + 2) =
                __nv_bfloat162(__float2bfloat16(r2), __float2bfloat16(r3));
        }
    };
    conv(kS, reinterpret_cast<__nv_bfloat16*>(rsm + R_KBH),
         reinterpret_cast<__nv_bfloat16*>(rsm + R_KBL));
    conv(vS, reinterpret_cast<__nv_bfloat16*>(rsm + R_VBH),
         reinterpret_cast<__nv_bfloat16*>(rsm + R_VBL));
    __syncthreads();

    const uint32_t sb = smem_u32(rsm);
    const int g = lane >> 2;
    const int tq = lane & 3;

    // ---- phase A: kvT[e][d] (64x64) via trans ldmatrix ----
    const int e0 = (wid >> 1) * 16;
    const int d0 = (wid & 1) * 32;
    const int ta_row = (lane & 7) + ((lane >> 4) & 1) * 8;
    const int ta_col = ((lane >> 3) & 1) * 8;
    const int tb_row = (lane & 7) + ((lane >> 3) & 1) * 8;
    const int tb_col = ((lane >> 4) & 1) * 8;

    float acc1[4][4];
#pragma unroll
    for (int i = 0; i < 4; i++)
#pragma unroll
        for (int j = 0; j < 4; j++) acc1[i][j] = 0.f;

#pragma unroll
    for (int ks = 0; ks < 8; ks++) {
        const int k0 = ks * 16;
        uint32_t avh[4], avl[4];
        ldm_x4t(avh, sb + R_VBH + 2 * ((k0 + ta_row) * RLD + e0 + ta_col));
        ldm_x4t(avl, sb + R_VBL + 2 * ((k0 + ta_row) * RLD + e0 + ta_col));
        uint32_t bh[2][4], bl[2][4];
#pragma unroll
        for (int nq = 0; nq < 2; nq++) {
            ldm_x4t(bh[nq], sb + R_KBH +
                    2 * ((k0 + tb_row) * RLD + d0 + nq * 16 + tb_col));
            ldm_x4t(bl[nq], sb + R_KBL +
                    2 * ((k0 + tb_row) * RLD + d0 + nq * 16 + tb_col));
        }
#pragma unroll
        for (int nq = 0; nq < 2; nq++)
#pragma unroll
            for (int p = 0; p < 2; p++) {
                const int nt = nq * 2 + p;
                uint32_t bfh[2] = {bh[nq][2 * p], bh[nq][2 * p + 1]};
                uint32_t bfl[2] = {bl[nq][2 * p], bl[nq][2 * p + 1]};
                mma_bf16(acc1[nt], avh, bfh);
                mma_bf16(acc1[nt], avh, bfl);
                mma_bf16(acc1[nt], avl, bfh);
            }
    }
    __syncthreads();

    {
        __nv_bfloat16* kvh = reinterpret_cast<__nv_bfloat16*>(rsm + R_KVH);
        __nv_bfloat16* kvl = reinterpret_cast<__nv_bfloat16*>(rsm + R_KVL);
#pragma unroll
        for (int nt = 0; nt < 4; nt++)
#pragma unroll
            for (int half = 0; half < 2; half++) {
                const int e = e0 + g + half * 8;
                const int d = d0 + nt * 8 + 2 * tq;
                float r0, r1;
                __nv_bfloat162 hp = split_hi2(acc1[nt][half * 2],
                                              acc1[nt][half * 2 + 1], r0, r1);
                *reinterpret_cast<__nv_bfloat162*>(kvh + e * RLD + d) = hp;
                *reinterpret_cast<__nv_bfloat162*>(kvl + e * RLD + d) =
                    __nv_bfloat162(__float2bfloat16(r0), __float2bfloat16(r1));
            }
    }
    conv(cS, reinterpret_cast<__nv_bfloat16*>(rsm + R_QSH),
         reinterpret_cast<__nv_bfloat16*>(rsm + R_QSL));
    __syncthreads();

    // ---- phase B: out[r][e] (128x64) ----
    const int r0 = wid * 16;
    const int a_row = lane & 15;
    const int a_c8 = (lane >> 4) * 8;
    const int b_row = (lane & 7) | ((lane & 16) >> 1);
    const int b_c8 = ((lane >> 3) & 1) * 8;

    float acc2[8][4];
#pragma unroll
    for (int i = 0; i < 8; i++)
#pragma unroll
        for (int j = 0; j < 4; j++) acc2[i][j] = 0.f;

#pragma unroll
    for (int ks = 0; ks < 4; ks++) {
        const int k0 = ks * 16;
        uint32_t aqh[4], aql[4];
        ldm_x4(aqh, sb + R_QSH + 2 * ((r0 + a_row) * RLD + k0 + a_c8));
        ldm_x4(aql, sb + R_QSL + 2 * ((r0 + a_row) * RLD + k0 + a_c8));
        uint32_t kh[4][4], kl[4][4];
#pragma unroll
        for (int nq = 0; nq < 4; nq++) {
            ldm_x4(kh[nq], sb + R_KVH +
                   2 * ((nq * 16 + b_row) * RLD + k0 + b_c8));
            ldm_x4(kl[nq], sb + R_KVL +
                   2 * ((nq * 16 + b_row) * RLD + k0 + b_c8));
        }
#pragma unroll
        for (int nt = 0; nt < 8; nt++) {
            const int nq = nt >> 1;
            const int p = nt & 1;
            uint32_t bfh[2] = {kh[nq][2 * p], kh[nq][2 * p + 1]};
            uint32_t bfl[2] = {kl[nq][2 * p], kl[nq][2 * p + 1]};
            mma_bf16(acc2[nt], aqh, bfh);
            mma_bf16(acc2[nt], aqh, bfl);
            mma_bf16(acc2[nt], aql, bfh);
        }
    }

#pragma unroll
    for (int nt = 0; nt < 8; nt++) {
        const int e = nt * 8 + 2 * tq;
#pragma unroll
        for (int half = 0; half < 2; half++) {
            const int r = r0 + g + half * 8;
            float v0 = acc2[nt][half * 2];
            float v1 = acc2[nt][half * 2 + 1];
            if (mode == 0) {
                *reinterpret_cast<float2*>(oF + base + (size_t)r * DH + e) =
                    make_float2(v0, v1);
            } else {
                const int m = r * WW + idx;
                __half h0 = __float2half(v0), h1 = __float2half(v1);
                float l0 = v0 - __half2float(h0);
                float l1 = v1 - __half2float(h1);
                __half* bp = oCat + (size_t)m * K2 + n * DH + e;
                *reinterpret_cast<__half2*>(bp) = __half2(h0, h1);
                *reinterpret_cast<__half2*>(bp + E_DIM) =
                    __half2(__float2half(l0), __float2half(l1));
            }
        }
    }
}

// =======================================================================
extern "C" void kernel_launch(void* const* d_in, const int* in_sizes, int n_in,
                              void* d_out, int out_size) {
    const float* x  = (const float*)d_in[0];
    const float* Wq = (const float*)d_in[1];
    const float* bq = (const float*)d_in[2];
    const float* Wk = (const float*)d_in[3];
    const float* bk = (const float*)d_in[4];
    const float* Wv = (const float*)d_in[5];
    const float* bv = (const float*)d_in[6];
    const float* Wo = (const float*)d_in[7];
    const float* bo = (const float*)d_in[8];
    float* out = (float*)d_out;

    __nv_bfloat16 *a2, *b2;
    __half *o2f, *wo2;
    float *gq, *gk, *gv, *go1;
    cudaGetSymbolAddress((void**)&a2, g_a2);
    cudaGetSymbolAddress((void**)&b2, g_b2);
    cudaGetSymbolAddress((void**)&o2f, g_o2f);
    cudaGetSymbolAddress((void**)&wo2, g_wo2);
    cudaGetSymbolAddress((void**)&gq, g_q);
    cudaGetSymbolAddress((void**)&gk, g_k);
    cudaGetSymbolAddress((void**)&gv, g_v);
    cudaGetSymbolAddress((void**)&go1, g_o1);

    const int WTOT = E_DIM * E_DIM;

    cudaFuncSetAttribute(qkv_mma_kernel,
                         cudaFuncAttributeMaxDynamicSharedMemorySize,
                         SMEM_TOTAL);
    cudaFuncSetAttribute(out_mma_kernel,
                         cudaFuncAttributeMaxDynamicSharedMemorySize,
                         SMEM_TOTAL);
    cudaFuncSetAttribute(retention_kernel,
                         cudaFuncAttributeMaxDynamicSharedMemorySize,
                         RET_SMEM);

    // splits
    int nx = MROWS * E_DIM;
    split_a_kernel<<<nx / 1024, 256>>>(x, a2, nx);
    dim3 gsw(WTOT / 1024, 1, 3);
    split_w_kernel<<<gsw, 256>>>(Wq, Wk, Wv, b2);
    split_wo_kernel<<<WTOT / 1024, 256>>>(Wo, wo2);

    // q/k/v projections (bf16 3-term, K=3072)
    dim3 gqkv(E_DIM / 128, MROWS / 128, 3);
    qkv_mma_kernel<<<gqkv, 256, SMEM_TOTAL>>>(a2, b2, bq, bk, bv, gq, gk, gv);

    // retention (HMMA split-bf16); mode 1 writes fp16 [hi|lo]
    retention_kernel<<<HH * NHEADS, 256, RET_SMEM>>>(gk, gv, gq, go1, nullptr,
                                                     0);
    retention_kernel<<<WW * NHEADS, 256, RET_SMEM>>>(gk, gv, go1, nullptr,
                                                     o2f, 1);

    // output projection (fp16 2-term, K=2048)
    dim3 gout(E_DIM / 128, MROWS / 128, 1);
    out_mma_kernel<<<gout, 256, SMEM_TOTAL>>>(o2f, wo2, bo, out);
}

// round 11
// speedup vs baseline: 1.3150x; 1.0520x over previous
#include <cuda_runtime.h>
#include <cuda_bf16.h>
#include <cuda_fp16.h>
#include <cstdint>

#define E_DIM 1024
#define K3 (3 * E_DIM)               /* 3072 concat-K (bf16 3-term) */
#define K2 (2 * E_DIM)               /* 2048 concat-K (fp16 2-term) */
#define NHEADS 16
#define DH 64
#define HH 128
#define WW 128
#define MROWS (HH * WW)              /* 16384 */
#define HWD ((size_t)MROWS * DH)

#define BK 64
#define ROWP 72                       /* padded row (elems), 144B */
#define TILE_ROWS 128
#define STAGE_HALF (TILE_ROWS * ROWP)
#define STAGE_BYTES (2 * STAGE_HALF * 2)   /* 36864 */
#define SMEM_TOTAL (2 * STAGE_BYTES)       /* 73728 */

/* retention smem layout (dynamic, bytes) */
#define RLD 72                        /* bf16 row pitch (144B) */
#define R_KBH 0
#define R_KBL 18432
#define R_VBH 36864
#define R_VBL 55296
#define R_KVH 0
#define R_KVL 9216
#define R_QSH 18432
#define R_QSL 36864
#define RET_SMEM 73728

// ---------------- scratch (static device arrays; no allocation) ----------------
__device__ __nv_bfloat16 g_a2[(size_t)MROWS * K3];        // [Ah|Al|Ah] of x (bf16)
__device__ __half g_af[(size_t)MROWS * K2];               // [hi|lo] fp16 of x
__device__ __nv_bfloat16 g_b2[2][(size_t)E_DIM * K3];     // [Wh|Wh|Wl] q,k
__device__ __half g_wv2[(size_t)E_DIM * K2];              // [Wh|Wh] fp16 of Wv
__device__ __half g_o2f[(size_t)MROWS * K2];              // [hi|lo] fp16 of o2
__device__ __half g_wo2[(size_t)E_DIM * K2];              // [Wh|Wh] fp16 of Wo
__device__ float g_q[(size_t)NHEADS * MROWS * DH];
__device__ float g_k[(size_t)NHEADS * MROWS * DH];
__device__ float g_v[(size_t)NHEADS * MROWS * DH];
__device__ float g_o1[(size_t)NHEADS * MROWS * DH];

// ======================= helpers =======================
__device__ __forceinline__ uint32_t smem_u32(const void* p) {
    uint32_t a;
    asm("{ .reg .u64 t; cvta.to.shared.u64 t, %1; cvt.u32.u64 %0, t; }"
        : "=r"(a) : "l"(p));
    return a;
}

__device__ __forceinline__ void cp_async16(uint32_t dst, const void* src) {
    asm volatile("cp.async.cg.shared.global [%0], [%1], 16;\n"
                 :: "r"(dst), "l"(src) : "memory");
}

template <int N>
__device__ __forceinline__ void cp_wait() {
    asm volatile("cp.async.wait_group %0;\n" :: "n"(N) : "memory");
}

__device__ __forceinline__ void ldm_x4(uint32_t* r, uint32_t addr) {
    asm volatile(
        "ldmatrix.sync.aligned.m8n8.x4.shared.b16 {%0,%1,%2,%3}, [%4];"
        : "=r"(r[0]), "=r"(r[1]), "=r"(r[2]), "=r"(r[3]) : "r"(addr));
}

__device__ __forceinline__ void ldm_x4t(uint32_t* r, uint32_t addr) {
    asm volatile(
        "ldmatrix.sync.aligned.m8n8.x4.trans.shared.b16 {%0,%1,%2,%3}, [%4];"
        : "=r"(r[0]), "=r"(r[1]), "=r"(r[2]), "=r"(r[3]) : "r"(addr));
}

__device__ __forceinline__ void mma_bf16(float* c, const uint32_t* a,
                                         const uint32_t* b) {
    asm volatile(
        "mma.sync.aligned.m16n8k16.row.col.f32.bf16.bf16.f32 "
        "{%0,%1,%2,%3}, {%4,%5,%6,%7}, {%8,%9}, {%0,%1,%2,%3};"
        : "+f"(c[0]), "+f"(c[1]), "+f"(c[2]), "+f"(c[3])
        : "r"(a[0]), "r"(a[1]), "r"(a[2]), "r"(a[3]), "r"(b[0]), "r"(b[1]));
}

__device__ __forceinline__ void mma_fp16(float* c, const uint32_t* a,
                                         const uint32_t* b) {
    asm volatile(
        "mma.sync.aligned.m16n8k16.row.col.f32.f16.f16.f32 "
        "{%0,%1,%2,%3}, {%4,%5,%6,%7}, {%8,%9}, {%0,%1,%2,%3};"
        : "+f"(c[0]), "+f"(c[1]), "+f"(c[2]), "+f"(c[3])
        : "r"(a[0]), "r"(a[1]), "r"(a[2]), "r"(a[3]), "r"(b[0]), "r"(b[1]));
}

__device__ __forceinline__ __nv_bfloat162 split_hi2(float a, float b,
                                                    float& ra, float& rb) {
    __nv_bfloat16 ha = __float2bfloat16(a);
    __nv_bfloat16 hb = __float2bfloat16(b);
    ra = a - __bfloat162float(ha);
    rb = b - __bfloat162float(hb);
    return __nv_bfloat162(ha, hb);
}

// ======================= HMMA GEMM (proven R4/R5 config, templated K/type) ==
// D[m,n] = sum_{k<KLEN} A2[m,k] * B2[n,k] + bias[n]
// CTA 128x128, 256 threads (8 warps: 4m x 2n), warp tile 32x64.
// K-chunk 64, double-buffered cp.async.
template <int HEADLAYOUT, int KLEN, bool FP16, typename T>
__device__ __forceinline__ void mma_gemm_body(
    const T* __restrict__ A2, const T* __restrict__ B2,
    const float* __restrict__ bias, float* __restrict__ out, bool relu) {
    extern __shared__ char smem[];
    const int tid = threadIdx.x;
    const int wid = tid >> 5;
    const int lane = tid & 31;
    const int wm = wid & 3;
    const int wn = wid >> 2;
    const int m0 = blockIdx.y * 128;
    const int n0 = blockIdx.x * 128;
    constexpr int NCH = KLEN / BK;

    float acc[2][8][4];
#pragma unroll
    for (int i = 0; i < 2; i++)
#pragma unroll
        for (int j = 0; j < 8; j++)
#pragma unroll
            for (int c = 0; c < 4; c++) acc[i][j][c] = 0.f;

    auto stA = [&](int s) {
        return reinterpret_cast<T*>(smem + s * STAGE_BYTES);
    };
    auto stB = [&](int s) {
        return reinterpret_cast<T*>(smem + s * STAGE_BYTES) + STAGE_HALF;
    };

    auto load_chunk = [&](int s, int k0) {
        T* a = stA(s);
        T* b = stB(s);
#pragma unroll
        for (int i = 0; i < 4; i++) {
            int c = tid + i * 256;
            int row = c >> 3;
            int seg = (c & 7) * 8;
            cp_async16(smem_u32(a + row * ROWP + seg),
                       A2 + (size_t)(m0 + row) * KLEN + k0 + seg);
            cp_async16(smem_u32(b + row * ROWP + seg),
                       B2 + (size_t)(n0 + row) * KLEN + k0 + seg);
        }
        asm volatile("cp.async.commit_group;\n" ::: "memory");
    };

    load_chunk(0, 0);

    const int a_row = lane & 15;
    const int a_c8 = (lane >> 4) * 8;
    const int b_row = (lane & 7) | ((lane & 16) >> 1);
    const int b_c8 = ((lane >> 3) & 1) * 8;

    for (int ch = 0; ch < NCH; ch++) {
        if (ch + 1 < NCH) {
            load_chunk((ch + 1) & 1, (ch + 1) * BK);
            cp_wait<1>();
        } else {
            cp_wait<0>();
        }
        __syncthreads();

        const int buf = ch & 1;
        const uint32_t sbA = smem_u32(stA(buf));
        const uint32_t sbB = smem_u32(stB(buf));

#pragma unroll
        for (int kk = 0; kk < 4; kk++) {
            uint32_t a[2][4], b[8][2];
#pragma unroll
            for (int mt = 0; mt < 2; mt++) {
                uint32_t addr = sbA +
                    2 * ((32 * wm + 16 * mt + a_row) * ROWP + kk * 16 + a_c8);
                ldm_x4(a[mt], addr);
            }
#pragma unroll
            for (int np = 0; np < 4; np++) {
                uint32_t r[4];
                uint32_t addr = sbB +
                    2 * ((64 * wn + 16 * np + b_row) * ROWP + kk * 16 + b_c8);
                ldm_x4(r, addr);
                b[np * 2][0] = r[0]; b[np * 2][1] = r[1];
                b[np * 2 + 1][0] = r[2]; b[np * 2 + 1][1] = r[3];
            }
#pragma unroll
            for (int mt = 0; mt < 2; mt++)
#pragma unroll
                for (int nt = 0; nt < 8; nt++) {
                    if (FP16)
                        mma_fp16(acc[mt][nt], a[mt], b[nt]);
                    else
                        mma_bf16(acc[mt][nt], a[mt], b[nt]);
                }
        }
        __syncthreads();
    }

    const int g = lane >> 2;
    const int tq = lane & 3;
#pragma unroll
    for (int nt = 0; nt < 8; nt++) {
        const int n = n0 + 64 * wn + 8 * nt + 2 * tq;
        const float b0 = __ldg(bias + n);
        const float b1 = __ldg(bias + n + 1);
#pragma unroll
        for (int mt = 0; mt < 2; mt++) {
            const int mbase = m0 + 32 * wm + 16 * mt + g;
#pragma unroll
            for (int half = 0; half < 2; half++) {
                const int m = mbase + half * 8;
                float v0 = acc[mt][nt][half * 2] + b0;
                float v1 = acc[mt][nt][half * 2 + 1] + b1;
                if (relu) { v0 = fmaxf(v0, 0.f); v1 = fmaxf(v1, 0.f); }
                float2 t = make_float2(v0, v1);
                if (HEADLAYOUT) {
                    *reinterpret_cast<float2*>(
                        out + (size_t)(n >> 6) * HWD + (size_t)m * 64 +
                        (n & 63)) = t;
                } else {
                    *reinterpret_cast<float2*>(out + (size_t)m * E_DIM + n) = t;
                }
            }
        }
    }
}

__global__ __launch_bounds__(256, 2) void qkv_mma_kernel(
    const __nv_bfloat16* __restrict__ a2, const __nv_bfloat16* __restrict__ b2,
    const float* __restrict__ bq, const float* __restrict__ bk, float* gq,
    float* gk) {
    const size_t WSZ = (size_t)E_DIM * K3;
    const __nv_bfloat16* B = b2 + (size_t)blockIdx.z * WSZ;
    const float* bias = (blockIdx.z == 0) ? bq : bk;
    float* outp = (blockIdx.z == 0) ? gq : gk;
    mma_gemm_body<1, K3, false>(a2, B, bias, outp, true);
}

__global__ __launch_bounds__(256, 2) void v_mma_kernel(
    const __half* __restrict__ af, const __half* __restrict__ wv2,
    const float* __restrict__ bv, float* gv) {
    mma_gemm_body<1, K2, true>(af, wv2, bv, gv, false);
}

__global__ __launch_bounds__(256, 2) void out_mma_kernel(
    const __half* __restrict__ a2, const __half* __restrict__ b2,
    const float* __restrict__ bias, float* __restrict__ out) {
    mma_gemm_body<0, K2, true>(a2, b2, bias, out, false);
}

// ======================= fp32 -> split concat kernels =======================
template <int MODEA>
__device__ __forceinline__ void split_one(const float* __restrict__ in,
                                          __nv_bfloat16* __restrict__ out,
                                          int i) {
    float4 v = *reinterpret_cast<const float4*>(in + i);
    float f[4] = {v.x, v.y, v.z, v.w};
    __nv_bfloat16 h[4], l[4];
#pragma unroll
    for (int j = 0; j < 4; j++) {
        h[j] = __float2bfloat16(f[j]);
        l[j] = __float2bfloat16(f[j] - __bfloat162float(h[j]));
    }
    int row = i >> 10;
    int k = i & 1023;
    __nv_bfloat16* base = out + (size_t)row * K3 + k;
    __nv_bfloat162 hp0(h[0], h[1]), hp1(h[2], h[3]);
    __nv_bfloat162 lp0(l[0], l[1]), lp1(l[2], l[3]);
    __nv_bfloat162* p0 = reinterpret_cast<__nv_bfloat162*>(base);
    __nv_bfloat162* p1 = reinterpret_cast<__nv_bfloat162*>(base + E_DIM);
    __nv_bfloat162* p2 = reinterpret_cast<__nv_bfloat162*>(base + 2 * E_DIM);
    p0[0] = hp0; p0[1] = hp1;
    if (MODEA) {
        p1[0] = lp0; p1[1] = lp1;
        p2[0] = hp0; p2[1] = hp1;
    } else {
        p1[0] = hp0; p1[1] = hp1;
        p2[0] = lp0; p2[1] = lp1;
    }
}

__global__ __launch_bounds__(256) void split_a_kernel(
    const float* __restrict__ in, __nv_bfloat16* __restrict__ out, int total) {
    int i = (blockIdx.x * 256 + threadIdx.x) * 4;
    if (i < total) split_one<1>(in, out, i);
}

// x -> fp16 [hi | lo], K2 layout
__global__ __launch_bounds__(256) void split_af_kernel(
    const float* __restrict__ in, __half* __restrict__ out) {
    int i = (blockIdx.x * 256 + threadIdx.x) * 4;
    float4 v = *reinterpret_cast<const float4*>(in + i);
    float f[4] = {v.x, v.y, v.z, v.w};
    __half h[4], l[4];
#pragma unroll
    for (int j = 0; j < 4; j++) {
        h[j] = __float2half(f[j]);
        l[j] = __float2half(f[j] - __half2float(h[j]));
    }
    int row = i >> 10;
    int k = i & 1023;
    __half* base = out + (size_t)row * K2 + k;
    reinterpret_cast<__half2*>(base)[0] = __half2(h[0], h[1]);
    reinterpret_cast<__half2*>(base)[1] = __half2(h[2], h[3]);
    reinterpret_cast<__half2*>(base + E_DIM)[0] = __half2(l[0], l[1]);
    reinterpret_cast<__half2*>(base + E_DIM)[1] = __half2(l[2], l[3]);
}

__global__ __launch_bounds__(256) void split_w_kernel(
    const float* __restrict__ w0, const float* __restrict__ w1,
    __nv_bfloat16* __restrict__ out) {
    const float* w = (blockIdx.z == 0) ? w0 : w1;
    __nv_bfloat16* o = out + (size_t)blockIdx.z * E_DIM * K3;
    int i = (blockIdx.x * 256 + threadIdx.x) * 4;
    split_one<0>(w, o, i);
}

// W -> fp16 [Wh | Wh] (duplicated hi), K2 layout
__global__ __launch_bounds__(256) void split_wo_kernel(
    const float* __restrict__ w, __half* __restrict__ out) {
    int i = (blockIdx.x * 256 + threadIdx.x) * 4;
    float4 v = *reinterpret_cast<const float4*>(w + i);
    __half2 p0(__float2half(v.x), __float2half(v.y));
    __half2 p1(__float2half(v.z), __float2half(v.w));
    int row = i >> 10;
    int k = i & 1023;
    __half* base = out + (size_t)row * K2 + k;
    reinterpret_cast<__half2*>(base)[0] = p0;
    reinterpret_cast<__half2*>(base)[1] = p1;
    reinterpret_cast<__half2*>(base + E_DIM)[0] = p0;
    reinterpret_cast<__half2*>(base + E_DIM)[1] = p1;
}

// ======================= fused retention (HMMA, split-bf16; R5-proven) ======
__global__ __launch_bounds__(256, 2) void retention_kernel(
    const float* __restrict__ kArr, const float* __restrict__ vArr,
    const float* __restrict__ cArr, float* __restrict__ oF,
    __half* __restrict__ oCat, int mode) {
    extern __shared__ char rsm[];
    const int tid = threadIdx.x;
    const int wid = tid >> 5;
    const int lane = tid & 31;
    const int b = blockIdx.x;
    const int n = b & 15;
    const int idx = b >> 4;

    size_t base;
    int rs;
    if (mode == 0) {
        base = (size_t)n * HWD + (size_t)idx * (WW * DH);
        rs = DH;
    } else {
        base = (size_t)n * HWD + (size_t)idx * DH;
        rs = WW * DH;
    }
    const float* kS = kArr + base;
    const float* vS = vArr + base;
    const float* cS = cArr + base;

    auto conv = [&](const float* src, __nv_bfloat16* dh, __nv_bfloat16* dl) {
#pragma unroll
        for (int i = 0; i < 8; i++) {
            int id = tid + i * 256;
            int w = id >> 4;
            int c = (id & 15) << 2;
            float4 v4 = *reinterpret_cast<const float4*>(src +
                                                         (size_t)w * rs + c);
            float r0, r1, r2, r3;
            __nv_bfloat162 h01 = split_hi2(v4.x, v4.y, r0, r1);
            __nv_bfloat162 h23 = split_hi2(v4.z, v4.w, r2, r3);
            *reinterpret_cast<__nv_bfloat162*>(dh + w * RLD + c) = h01;
            *reinterpret_cast<__nv_bfloat162*>(dh + w * RLD + c + 2) = h23;
            *reinterpret_cast<__nv_bfloat162*>(dl + w * RLD + c) =
                __nv_bfloat162(__float2bfloat16(r0), __float2bfloat16(r1));
            *reinterpret_cast<__nv_bfloat162*>(dl + w * RLD + c + 2) =
                __nv_bfloat162(__float2bfloat16(r2), __float2bfloat16(r3));
        }
    };
    conv(kS, reinterpret_cast<__nv_bfloat16*>(rsm + R_KBH),
         reinterpret_cast<__nv_bfloat16*>(rsm + R_KBL));
    conv(vS, reinterpret_cast<__nv_bfloat16*>(rsm + R_VBH),
         reinterpret_cast<__nv_bfloat16*>(rsm + R_VBL));
    __syncthreads();

    const uint32_t sb = smem_u32(rsm);
    const int g = lane >> 2;
    const int tq = lane & 3;

    // ---- phase A: kvT[e][d] (64x64) via trans ldmatrix ----
    const int e0 = (wid >> 1) * 16;
    const int d0 = (wid & 1) * 32;
    const int ta_row = (lane & 7) + ((lane >> 4) & 1) * 8;
    const int ta_col = ((lane >> 3) & 1) * 8;
    const int tb_row = (lane & 7) + ((lane >> 3) & 1) * 8;
    const int tb_col = ((lane >> 4) & 1) * 8;

    float acc1[4][4];
#pragma unroll
    for (int i = 0; i < 4; i++)
#pragma unroll
        for (int j = 0; j < 4; j++) acc1[i][j] = 0.f;

#pragma unroll
    for (int ks = 0; ks < 8; ks++) {
        const int k0 = ks * 16;
        uint32_t avh[4], avl[4];
        ldm_x4t(avh, sb + R_VBH + 2 * ((k0 + ta_row) * RLD + e0 + ta_col));
        ldm_x4t(avl, sb + R_VBL + 2 * ((k0 + ta_row) * RLD + e0 + ta_col));
        uint32_t bh[2][4], bl[2][4];
#pragma unroll
        for (int nq = 0; nq < 2; nq++) {
            ldm_x4t(bh[nq], sb + R_KBH +
                    2 * ((k0 + tb_row) * RLD + d0 + nq * 16 + tb_col));
            ldm_x4t(bl[nq], sb + R_KBL +
                    2 * ((k0 + tb_row) * RLD + d0 + nq * 16 + tb_col));
        }
#pragma unroll
        for (int nq = 0; nq < 2; nq++)
#pragma unroll
            for (int p = 0; p < 2; p++) {
                const int nt = nq * 2 + p;
                uint32_t bfh[2] = {bh[nq][2 * p], bh[nq][2 * p + 1]};
                uint32_t bfl[2] = {bl[nq][2 * p], bl[nq][2 * p + 1]};
                mma_bf16(acc1[nt], avh, bfh);
                mma_bf16(acc1[nt], avh, bfl);
                mma_bf16(acc1[nt], avl, bfh);
            }
    }
    __syncthreads();

    {
        __nv_bfloat16* kvh = reinterpret_cast<__nv_bfloat16*>(rsm + R_KVH);
        __nv_bfloat16* kvl = reinterpret_cast<__nv_bfloat16*>(rsm + R_KVL);
#pragma unroll
        for (int nt = 0; nt < 4; nt++)
#pragma unroll
            for (int half = 0; half < 2; half++) {
                const int e = e0 + g + half * 8;
                const int d = d0 + nt * 8 + 2 * tq;
                float r0, r1;
                __nv_bfloat162 hp = split_hi2(acc1[nt][half * 2],
                                              acc1[nt][half * 2 + 1], r0, r1);
                *reinterpret_cast<__nv_bfloat162*>(kvh + e * RLD + d) = hp;
                *reinterpret_cast<__nv_bfloat162*>(kvl + e * RLD + d) =
                    __nv_bfloat162(__float2bfloat16(r0), __float2bfloat16(r1));
            }
    }
    conv(cS, reinterpret_cast<__nv_bfloat16*>(rsm + R_QSH),
         reinterpret_cast<__nv_bfloat16*>(rsm + R_QSL));
    __syncthreads();

    // ---- phase B: out[r][e] (128x64) ----
    const int r0 = wid * 16;
    const int a_row = lane & 15;
    const int a_c8 = (lane >> 4) * 8;
    const int b_row = (lane & 7) | ((lane & 16) >> 1);
    const int b_c8 = ((lane >> 3) & 1) * 8;

    float acc2[8][4];
#pragma unroll
    for (int i = 0; i < 8; i++)
#pragma unroll
        for (int j = 0; j < 4; j++) acc2[i][j] = 0.f;

#pragma unroll
    for (int ks = 0; ks < 4; ks++) {
        const int k0 = ks * 16;
        uint32_t aqh[4], aql[4];
        ldm_x4(aqh, sb + R_QSH + 2 * ((r0 + a_row) * RLD + k0 + a_c8));
        ldm_x4(aql, sb + R_QSL + 2 * ((r0 + a_row) * RLD + k0 + a_c8));
        uint32_t kh[4][4], kl[4][4];
#pragma unroll
        for (int nq = 0; nq < 4; nq++) {
            ldm_x4(kh[nq], sb + R_KVH +
                   2 * ((nq * 16 + b_row) * RLD + k0 + b_c8));
            ldm_x4(kl[nq], sb + R_KVL +
                   2 * ((nq * 16 + b_row) * RLD + k0 + b_c8));
        }
#pragma unroll
        for (int nt = 0; nt < 8; nt++) {
            const int nq = nt >> 1;
            const int p = nt & 1;
            uint32_t bfh[2] = {kh[nq][2 * p], kh[nq][2 * p + 1]};
            uint32_t bfl[2] = {kl[nq][2 * p], kl[nq][2 * p + 1]};
            mma_bf16(acc2[nt], aqh, bfh);
            mma_bf16(acc2[nt], aqh, bfl);
            mma_bf16(acc2[nt], aql, bfh);
        }
    }

#pragma unroll
    for (int nt = 0; nt < 8; nt++) {
        const int e = nt * 8 + 2 * tq;
#pragma unroll
        for (int half = 0; half < 2; half++) {
            const int r = r0 + g + half * 8;
            float v0 = acc2[nt][half * 2];
            float v1 = acc2[nt][half * 2 + 1];
            if (mode == 0) {
                *reinterpret_cast<float2*>(oF + base + (size_t)r * DH + e) =
                    make_float2(v0, v1);
            } else {
                const int m = r * WW + idx;
                __half h0 = __float2half(v0), h1 = __float2half(v1);
                float l0 = v0 - __half2float(h0);
                float l1 = v1 - __half2float(h1);
                __half* bp = oCat + (size_t)m * K2 + n * DH + e;
                *reinterpret_cast<__half2*>(bp) = __half2(h0, h1);
                *reinterpret_cast<__half2*>(bp + E_DIM) =
                    __half2(__float2half(l0), __float2half(l1));
            }
        }
    }
}

// =======================================================================
extern "C" void kernel_launch(void* const* d_in, const int* in_sizes, int n_in,
                              void* d_out, int out_size) {
    const float* x  = (const float*)d_in[0];
    const float* Wq = (const float*)d_in[1];
    const float* bq = (const float*)d_in[2];
    const float* Wk = (const float*)d_in[3];
    const float* bk = (const float*)d_in[4];
    const float* Wv = (const float*)d_in[5];
    const float* bv = (const float*)d_in[6];
    const float* Wo = (const float*)d_in[7];
    const float* bo = (const float*)d_in[8];
    float* out = (float*)d_out;

    __nv_bfloat16 *a2, *b2;
    __half *af, *wv2, *o2f, *wo2;
    float *gq, *gk, *gv, *go1;
    cudaGetSymbolAddress((void**)&a2, g_a2);
    cudaGetSymbolAddress((void**)&af, g_af);
    cudaGetSymbolAddress((void**)&b2, g_b2);
    cudaGetSymbolAddress((void**)&wv2, g_wv2);
    cudaGetSymbolAddress((void**)&o2f, g_o2f);
    cudaGetSymbolAddress((void**)&wo2, g_wo2);
    cudaGetSymbolAddress((void**)&gq, g_q);
    cudaGetSymbolAddress((void**)&gk, g_k);
    cudaGetSymbolAddress((void**)&gv, g_v);
    cudaGetSymbolAddress((void**)&go1, g_o1);

    const int WTOT = E_DIM * E_DIM;

    cudaFuncSetAttribute(qkv_mma_kernel,
                         cudaFuncAttributeMaxDynamicSharedMemorySize,
                         SMEM_TOTAL);
    cudaFuncSetAttribute(v_mma_kernel,
                         cudaFuncAttributeMaxDynamicSharedMemorySize,
                         SMEM_TOTAL);
    cudaFuncSetAttribute(out_mma_kernel,
                         cudaFuncAttributeMaxDynamicSharedMemorySize,
                         SMEM_TOTAL);
    cudaFuncSetAttribute(retention_kernel,
                         cudaFuncAttributeMaxDynamicSharedMemorySize,
                         RET_SMEM);

    // splits
    int nx = MROWS * E_DIM;
    split_a_kernel<<<nx / 1024, 256>>>(x, a2, nx);
    split_af_kernel<<<nx / 1024, 256>>>(x, af);
    dim3 gsw(WTOT / 1024, 1, 2);
    split_w_kernel<<<gsw, 256>>>(Wq, Wk, b2);
    split_wo_kernel<<<WTOT / 1024, 256>>>(Wv, wv2);
    split_wo_kernel<<<WTOT / 1024, 256>>>(Wo, wo2);

    // q/k projections (bf16 3-term, K=3072)
    dim3 gqk(E_DIM / 128, MROWS / 128, 2);
    qkv_mma_kernel<<<gqk, 256, SMEM_TOTAL>>>(a2, b2, bq, bk, gq, gk);

    // v projection (fp16 2-term, K=2048)
    dim3 gv_(E_DIM / 128, MROWS / 128, 1);
    v_mma_kernel<<<gv_, 256, SMEM_TOTAL>>>(af, wv2, bv, gv);

    // retention (HMMA split-bf16); mode 1 writes fp16 [hi|lo]
    retention_kernel<<<HH * NHEADS, 256, RET_SMEM>>>(gk, gv, gq, go1, nullptr,
                                                     0);
    retention_kernel<<<WW * NHEADS, 256, RET_SMEM>>>(gk, gv, go1, nullptr,
                                                     o2f, 1);

    // output projection (fp16 2-term, K=2048)
    dim3 gout(E_DIM / 128, MROWS / 128, 1);
    out_mma_kernel<<<gout, 256, SMEM_TOTAL>>>(o2f, wo2, bo, out);
}

// round 12
// speedup vs baseline: 1.6241x; 1.2351x over previous
#include <cuda_runtime.h>
#include <cuda_bf16.h>
#include <cuda_fp16.h>
#include <cstdint>

#define E_DIM 1024
#define K2 (2 * E_DIM)               /* 2048 concat-K (fp16 2-term) */
#define NHEADS 16
#define DH 64
#define HH 128
#define WW 128
#define MROWS (HH * WW)              /* 16384 */
#define HWD ((size_t)MROWS * DH)

#define BK 64
#define ROWP 72                       /* padded row (elems), 144B */
#define TILE_ROWS 128
#define STAGE_HALF (TILE_ROWS * ROWP)
#define STAGE_BYTES (2 * STAGE_HALF * 2)   /* 36864 */
#define SMEM_TOTAL (2 * STAGE_BYTES)       /* 73728 */

/* retention smem layout (dynamic, bytes) */
#define RLD 72                        /* bf16 row pitch (144B) */
#define R_KBH 0
#define R_KBL 18432
#define R_VBH 36864
#define R_VBL 55296
#define R_KVH 0
#define R_KVL 9216
#define R_QSH 18432
#define R_QSL 36864
#define RET_SMEM 73728

// ---------------- scratch (static device arrays; no allocation) ----------------
__device__ __half g_af[(size_t)MROWS * K2];               // [hi|lo] fp16 of x
__device__ __half g_w4[4][(size_t)E_DIM * K2];            // [Wh|Wh] fp16 q,k,v,o
__device__ __half g_o2f[(size_t)MROWS * K2];              // [hi|lo] fp16 of o2
__device__ float g_q[(size_t)NHEADS * MROWS * DH];
__device__ float g_k[(size_t)NHEADS * MROWS * DH];
__device__ float g_v[(size_t)NHEADS * MROWS * DH];
__device__ float g_o1[(size_t)NHEADS * MROWS * DH];

// ======================= helpers =======================
__device__ __forceinline__ uint32_t smem_u32(const void* p) {
    uint32_t a;
    asm("{ .reg .u64 t; cvta.to.shared.u64 t, %1; cvt.u32.u64 %0, t; }"
        : "=r"(a) : "l"(p));
    return a;
}

__device__ __forceinline__ void cp_async16(uint32_t dst, const void* src) {
    asm volatile("cp.async.cg.shared.global [%0], [%1], 16;\n"
                 :: "r"(dst), "l"(src) : "memory");
}

template <int N>
__device__ __forceinline__ void cp_wait() {
    asm volatile("cp.async.wait_group %0;\n" :: "n"(N) : "memory");
}

__device__ __forceinline__ void ldm_x4(uint32_t* r, uint32_t addr) {
    asm volatile(
        "ldmatrix.sync.aligned.m8n8.x4.shared.b16 {%0,%1,%2,%3}, [%4];"
        : "=r"(r[0]), "=r"(r[1]), "=r"(r[2]), "=r"(r[3]) : "r"(addr));
}

__device__ __forceinline__ void ldm_x4t(uint32_t* r, uint32_t addr) {
    asm volatile(
        "ldmatrix.sync.aligned.m8n8.x4.trans.shared.b16 {%0,%1,%2,%3}, [%4];"
        : "=r"(r[0]), "=r"(r[1]), "=r"(r[2]), "=r"(r[3]) : "r"(addr));
}

__device__ __forceinline__ void mma_bf16(float* c, const uint32_t* a,
                                         const uint32_t* b) {
    asm volatile(
        "mma.sync.aligned.m16n8k16.row.col.f32.bf16.bf16.f32 "
        "{%0,%1,%2,%3}, {%4,%5,%6,%7}, {%8,%9}, {%0,%1,%2,%3};"
        : "+f"(c[0]), "+f"(c[1]), "+f"(c[2]), "+f"(c[3])
        : "r"(a[0]), "r"(a[1]), "r"(a[2]), "r"(a[3]), "r"(b[0]), "r"(b[1]));
}

__device__ __forceinline__ void mma_fp16(float* c, const uint32_t* a,
                                         const uint32_t* b) {
    asm volatile(
        "mma.sync.aligned.m16n8k16.row.col.f32.f16.f16.f32 "
        "{%0,%1,%2,%3}, {%4,%5,%6,%7}, {%8,%9}, {%0,%1,%2,%3};"
        : "+f"(c[0]), "+f"(c[1]), "+f"(c[2]), "+f"(c[3])
        : "r"(a[0]), "r"(a[1]), "r"(a[2]), "r"(a[3]), "r"(b[0]), "r"(b[1]));
}

__device__ __forceinline__ __nv_bfloat162 split_hi2(float a, float b,
                                                    float& ra, float& rb) {
    __nv_bfloat16 ha = __float2bfloat16(a);
    __nv_bfloat16 hb = __float2bfloat16(b);
    ra = a - __bfloat162float(ha);
    rb = b - __bfloat162float(hb);
    return __nv_bfloat162(ha, hb);
}

// ======================= fp16 HMMA GEMM (proven config, K=2048) =============
// D[m,n] = sum_{k<K2} A2[m,k] * B2[n,k] + bias[n]
// CTA 128x128, 256 threads (8 warps: 4m x 2n), warp tile 32x64.
// K-chunk 64, double-buffered cp.async.
template <int HEADLAYOUT>
__device__ __forceinline__ void mma_gemm_body(
    const __half* __restrict__ A2, const __half* __restrict__ B2,
    const float* __restrict__ bias, float* __restrict__ out, bool relu) {
    extern __shared__ char smem[];
    const int tid = threadIdx.x;
    const int wid = tid >> 5;
    const int lane = tid & 31;
    const int wm = wid & 3;
    const int wn = wid >> 2;
    const int m0 = blockIdx.y * 128;
    const int n0 = blockIdx.x * 128;
    constexpr int NCH = K2 / BK;

    float acc[2][8][4];
#pragma unroll
    for (int i = 0; i < 2; i++)
#pragma unroll
        for (int j = 0; j < 8; j++)
#pragma unroll
            for (int c = 0; c < 4; c++) acc[i][j][c] = 0.f;

    auto stA = [&](int s) {
        return reinterpret_cast<__half*>(smem + s * STAGE_BYTES);
    };
    auto stB = [&](int s) {
        return reinterpret_cast<__half*>(smem + s * STAGE_BYTES) + STAGE_HALF;
    };

    auto load_chunk = [&](int s, int k0) {
        __half* a = stA(s);
        __half* b = stB(s);
#pragma unroll
        for (int i = 0; i < 4; i++) {
            int c = tid + i * 256;
            int row = c >> 3;
            int seg = (c & 7) * 8;
            cp_async16(smem_u32(a + row * ROWP + seg),
                       A2 + (size_t)(m0 + row) * K2 + k0 + seg);
            cp_async16(smem_u32(b + row * ROWP + seg),
                       B2 + (size_t)(n0 + row) * K2 + k0 + seg);
        }
        asm volatile("cp.async.commit_group;\n" ::: "memory");
    };

    load_chunk(0, 0);

    const int a_row = lane & 15;
    const int a_c8 = (lane >> 4) * 8;
    const int b_row = (lane & 7) | ((lane & 16) >> 1);
    const int b_c8 = ((lane >> 3) & 1) * 8;

    for (int ch = 0; ch < NCH; ch++) {
        if (ch + 1 < NCH) {
            load_chunk((ch + 1) & 1, (ch + 1) * BK);
            cp_wait<1>();
        } else {
            cp_wait<0>();
        }
        __syncthreads();

        const int buf = ch & 1;
        const uint32_t sbA = smem_u32(stA(buf));
        const uint32_t sbB = smem_u32(stB(buf));

#pragma unroll
        for (int kk = 0; kk < 4; kk++) {
            uint32_t a[2][4], b[8][2];
#pragma unroll
            for (int mt = 0; mt < 2; mt++) {
                uint32_t addr = sbA +
                    2 * ((32 * wm + 16 * mt + a_row) * ROWP + kk * 16 + a_c8);
                ldm_x4(a[mt], addr);
            }
#pragma unroll
            for (int np = 0; np < 4; np++) {
                uint32_t r[4];
                uint32_t addr = sbB +
                    2 * ((64 * wn + 16 * np + b_row) * ROWP + kk * 16 + b_c8);
                ldm_x4(r, addr);
                b[np * 2][0] = r[0]; b[np * 2][1] = r[1];
                b[np * 2 + 1][0] = r[2]; b[np * 2 + 1][1] = r[3];
            }
#pragma unroll
            for (int mt = 0; mt < 2; mt++)
#pragma unroll
                for (int nt = 0; nt < 8; nt++)
                    mma_fp16(acc[mt][nt], a[mt], b[nt]);
        }
        __syncthreads();
    }

    const int g = lane >> 2;
    const int tq = lane & 3;
#pragma unroll
    for (int nt = 0; nt < 8; nt++) {
        const int n = n0 + 64 * wn + 8 * nt + 2 * tq;
        const float b0 = __ldg(bias + n);
        const float b1 = __ldg(bias + n + 1);
#pragma unroll
        for (int mt = 0; mt < 2; mt++) {
            const int mbase = m0 + 32 * wm + 16 * mt + g;
#pragma unroll
            for (int half = 0; half < 2; half++) {
                const int m = mbase + half * 8;
                float v0 = acc[mt][nt][half * 2] + b0;
                float v1 = acc[mt][nt][half * 2 + 1] + b1;
                if (relu) { v0 = fmaxf(v0, 0.f); v1 = fmaxf(v1, 0.f); }
                float2 t = make_float2(v0, v1);
                if (HEADLAYOUT) {
                    *reinterpret_cast<float2*>(
                        out + (size_t)(n >> 6) * HWD + (size_t)m * 64 +
                        (n & 63)) = t;
                } else {
                    *reinterpret_cast<float2*>(out + (size_t)m * E_DIM + n) = t;
                }
            }
        }
    }
}

__global__ __launch_bounds__(256, 2) void qkv_mma_kernel(
    const __half* __restrict__ af, const __half* __restrict__ w4,
    const float* __restrict__ bq, const float* __restrict__ bk,
    const float* __restrict__ bv, float* gq, float* gk, float* gv) {
    const size_t WSZ = (size_t)E_DIM * K2;
    const __half* B = w4 + (size_t)blockIdx.z * WSZ;
    const float* bias;
    float* outp;
    bool relu;
    if (blockIdx.z == 0) { bias = bq; outp = gq; relu = true; }
    else if (blockIdx.z == 1) { bias = bk; outp = gk; relu = true; }
    else { bias = bv; outp = gv; relu = false; }
    mma_gemm_body<1>(af, B, bias, outp, relu);
}

__global__ __launch_bounds__(256, 2) void out_mma_kernel(
    const __half* __restrict__ a2, const __half* __restrict__ b2,
    const float* __restrict__ bias, float* __restrict__ out) {
    mma_gemm_body<0>(a2, b2, bias, out, false);
}

// ======================= fp32 -> fp16 split kernels =======================
// x -> fp16 [hi | lo], K2 layout
__global__ __launch_bounds__(256) void split_af_kernel(
    const float* __restrict__ in, __half* __restrict__ out) {
    int i = (blockIdx.x * 256 + threadIdx.x) * 4;
    float4 v = *reinterpret_cast<const float4*>(in + i);
    float f[4] = {v.x, v.y, v.z, v.w};
    __half h[4], l[4];
#pragma unroll
    for (int j = 0; j < 4; j++) {
        h[j] = __float2half(f[j]);
        l[j] = __float2half(f[j] - __half2float(h[j]));
    }
    int row = i >> 10;
    int k = i & 1023;
    __half* base = out + (size_t)row * K2 + k;
    reinterpret_cast<__half2*>(base)[0] = __half2(h[0], h[1]);
    reinterpret_cast<__half2*>(base)[1] = __half2(h[2], h[3]);
    reinterpret_cast<__half2*>(base + E_DIM)[0] = __half2(l[0], l[1]);
    reinterpret_cast<__half2*>(base + E_DIM)[1] = __half2(l[2], l[3]);
}

// W -> fp16 [Wh | Wh] (duplicated hi), K2 layout; z selects weight
__global__ __launch_bounds__(256) void split_w4_kernel(
    const float* __restrict__ w0, const float* __restrict__ w1,
    const float* __restrict__ w2, const float* __restrict__ w3,
    __half* __restrict__ out) {
    const float* w = (blockIdx.z == 0) ? w0
                     : (blockIdx.z == 1) ? w1
                     : (blockIdx.z == 2) ? w2 : w3;
    __half* o = out + (size_t)blockIdx.z * E_DIM * K2;
    int i = (blockIdx.x * 256 + threadIdx.x) * 4;
    float4 v = *reinterpret_cast<const float4*>(w + i);
    __half2 p0(__float2half(v.x), __float2half(v.y));
    __half2 p1(__float2half(v.z), __float2half(v.w));
    int row = i >> 10;
    int k = i & 1023;
    __half* base = o + (size_t)row * K2 + k;
    reinterpret_cast<__half2*>(base)[0] = p0;
    reinterpret_cast<__half2*>(base)[1] = p1;
    reinterpret_cast<__half2*>(base + E_DIM)[0] = p0;
    reinterpret_cast<__half2*>(base + E_DIM)[1] = p1;
}

// ======================= fused retention (HMMA, split-bf16; R5-proven) ======
__global__ __launch_bounds__(256, 2) void retention_kernel(
    const float* __restrict__ kArr, const float* __restrict__ vArr,
    const float* __restrict__ cArr, float* __restrict__ oF,
    __half* __restrict__ oCat, int mode) {
    extern __shared__ char rsm[];
    const int tid = threadIdx.x;
    const int wid = tid >> 5;
    const int lane = tid & 31;
    const int b = blockIdx.x;
    const int n = b & 15;
    const int idx = b >> 4;

    size_t base;
    int rs;
    if (mode == 0) {
        base = (size_t)n * HWD + (size_t)idx * (WW * DH);
        rs = DH;
    } else {
        base = (size_t)n * HWD + (size_t)idx * DH;
        rs = WW * DH;
    }
    const float* kS = kArr + base;
    const float* vS = vArr + base;
    const float* cS = cArr + base;

    auto conv = [&](const float* src, __nv_bfloat16* dh, __nv_bfloat16* dl) {
#pragma unroll
        for (int i = 0; i < 8; i++) {
            int id = tid + i * 256;
            int w = id >> 4;
            int c = (id & 15) << 2;
            float4 v4 = *reinterpret_cast<const float4*>(src +
                                                         (size_t)w * rs + c);
            float r0, r1, r2, r3;
            __nv_bfloat162 h01 = split_hi2(v4.x, v4.y, r0, r1);
            __nv_bfloat162 h23 = split_hi2(v4.z, v4.w, r2, r3);
            *reinterpret_cast<__nv_bfloat162*>(dh + w * RLD + c) = h01;
            *reinterpret_cast<__nv_bfloat162*>(dh + w * RLD + c + 2) = h23;
            *reinterpret_cast<__nv_bfloat162*>(dl + w * RLD + c) =
                __nv_bfloat162(__float2bfloat16(r0), __float2bfloat16(r1));
            *reinterpret_cast<__nv_bfloat162*>(dl + w * RLD + c + 2) =
                __nv_bfloat162(__float2bfloat16(r2), __float2bfloat16(r3));
        }
    };
    conv(kS, reinterpret_cast<__nv_bfloat16*>(rsm + R_KBH),
         reinterpret_cast<__nv_bfloat16*>(rsm + R_KBL));
    conv(vS, reinterpret_cast<__nv_bfloat16*>(rsm + R_VBH),
         reinterpret_cast<__nv_bfloat16*>(rsm + R_VBL));
    __syncthreads();

    const uint32_t sb = smem_u32(rsm);
    const int g = lane >> 2;
    const int tq = lane & 3;

    // ---- phase A: kvT[e][d] (64x64) via trans ldmatrix ----
    const int e0 = (wid >> 1) * 16;
    const int d0 = (wid & 1) * 32;
    const int ta_row = (lane & 7) + ((lane >> 4) & 1) * 8;
    const int ta_col = ((lane >> 3) & 1) * 8;
    const int tb_row = (lane & 7) + ((lane >> 3) & 1) * 8;
    const int tb_col = ((lane >> 4) & 1) * 8;

    float acc1[4][4];
#pragma unroll
    for (int i = 0; i < 4; i++)
#pragma unroll
        for (int j = 0; j < 4; j++) acc1[i][j] = 0.f;

#pragma unroll
    for (int ks = 0; ks < 8; ks++) {
        const int k0 = ks * 16;
        uint32_t avh[4], avl[4];
        ldm_x4t(avh, sb + R_VBH + 2 * ((k0 + ta_row) * RLD + e0 + ta_col));
        ldm_x4t(avl, sb + R_VBL + 2 * ((k0 + ta_row) * RLD + e0 + ta_col));
        uint32_t bh[2][4], bl[2][4];
#pragma unroll
        for (int nq = 0; nq < 2; nq++) {
            ldm_x4t(bh[nq], sb + R_KBH +
                    2 * ((k0 + tb_row) * RLD + d0 + nq * 16 + tb_col));
            ldm_x4t(bl[nq], sb + R_KBL +
                    2 * ((k0 + tb_row) * RLD + d0 + nq * 16 + tb_col));
        }
#pragma unroll
        for (int nq = 0; nq < 2; nq++)
#pragma unroll
            for (int p = 0; p < 2; p++) {
                const int nt = nq * 2 + p;
                uint32_t bfh[2] = {bh[nq][2 * p], bh[nq][2 * p + 1]};
                uint32_t bfl[2] = {bl[nq][2 * p], bl[nq][2 * p + 1]};
                mma_bf16(acc1[nt], avh, bfh);
                mma_bf16(acc1[nt], avh, bfl);
                mma_bf16(acc1[nt], avl, bfh);
            }
    }
    __syncthreads();

    {
        __nv_bfloat16* kvh = reinterpret_cast<__nv_bfloat16*>(rsm + R_KVH);
        __nv_bfloat16* kvl = reinterpret_cast<__nv_bfloat16*>(rsm + R_KVL);
#pragma unroll
        for (int nt = 0; nt < 4; nt++)
#pragma unroll
            for (int half = 0; half < 2; half++) {
                const int e = e0 + g + half * 8;
                const int d = d0 + nt * 8 + 2 * tq;
                float r0, r1;
                __nv_bfloat162 hp = split_hi2(acc1[nt][half * 2],
                                              acc1[nt][half * 2 + 1], r0, r1);
                *reinterpret_cast<__nv_bfloat162*>(kvh + e * RLD + d) = hp;
                *reinterpret_cast<__nv_bfloat162*>(kvl + e * RLD + d) =
                    __nv_bfloat162(__float2bfloat16(r0), __float2bfloat16(r1));
            }
    }
    conv(cS, reinterpret_cast<__nv_bfloat16*>(rsm + R_QSH),
         reinterpret_cast<__nv_bfloat16*>(rsm + R_QSL));
    __syncthreads();

    // ---- phase B: out[r][e] (128x64) ----
    const int r0 = wid * 16;
    const int a_row = lane & 15;
    const int a_c8 = (lane >> 4) * 8;
    const int b_row = (lane & 7) | ((lane & 16) >> 1);
    const int b_c8 = ((lane >> 3) & 1) * 8;

    float acc2[8][4];
#pragma unroll
    for (int i = 0; i < 8; i++)
#pragma unroll
        for (int j = 0; j < 4; j++) acc2[i][j] = 0.f;

#pragma unroll
    for (int ks = 0; ks < 4; ks++) {
        const int k0 = ks * 16;
        uint32_t aqh[4], aql[4];
        ldm_x4(aqh, sb + R_QSH + 2 * ((r0 + a_row) * RLD + k0 + a_c8));
        ldm_x4(aql, sb + R_QSL + 2 * ((r0 + a_row) * RLD + k0 + a_c8));
        uint32_t kh[4][4], kl[4][4];
#pragma unroll
        for (int nq = 0; nq < 4; nq++) {
            ldm_x4(kh[nq], sb + R_KVH +
                   2 * ((nq * 16 + b_row) * RLD + k0 + b_c8));
            ldm_x4(kl[nq], sb + R_KVL +
                   2 * ((nq * 16 + b_row) * RLD + k0 + b_c8));
        }
#pragma unroll
        for (int nt = 0; nt < 8; nt++) {
            const int nq = nt >> 1;
            const int p = nt & 1;
            uint32_t bfh[2] = {kh[nq][2 * p], kh[nq][2 * p + 1]};
            uint32_t bfl[2] = {kl[nq][2 * p], kl[nq][2 * p + 1]};
            mma_bf16(acc2[nt], aqh, bfh);
            mma_bf16(acc2[nt], aqh, bfl);
            mma_bf16(acc2[nt], aql, bfh);
        }
    }

#pragma unroll
    for (int nt = 0; nt < 8; nt++) {
        const int e = nt * 8 + 2 * tq;
#pragma unroll
        for (int half = 0; half < 2; half++) {
            const int r = r0 + g + half * 8;
            float v0 = acc2[nt][half * 2];
            float v1 = acc2[nt][half * 2 + 1];
            if (mode == 0) {
                *reinterpret_cast<float2*>(oF + base + (size_t)r * DH + e) =
                    make_float2(v0, v1);
            } else {
                const int m = r * WW + idx;
                __half h0 = __float2half(v0), h1 = __float2half(v1);
                float l0 = v0 - __half2float(h0);
                float l1 = v1 - __half2float(h1);
                __half* bp = oCat + (size_t)m * K2 + n * DH + e;
                *reinterpret_cast<__half2*>(bp) = __half2(h0, h1);
                *reinterpret_cast<__half2*>(bp + E_DIM) =
                    __half2(__float2half(l0), __float2half(l1));
            }
        }
    }
}

// =======================================================================
extern "C" void kernel_launch(void* const* d_in, const int* in_sizes, int n_in,
                              void* d_out, int out_size) {
    const float* x  = (const float*)d_in[0];
    const float* Wq = (const float*)d_in[1];
    const float* bq = (const float*)d_in[2];
    const float* Wk = (const float*)d_in[3];
    const float* bk = (const float*)d_in[4];
    const float* Wv = (const float*)d_in[5];
    const float* bv = (const float*)d_in[6];
    const float* Wo = (const float*)d_in[7];
    const float* bo = (const float*)d_in[8];
    float* out = (float*)d_out;

    __half *af, *w4, *o2f;
    float *gq, *gk, *gv, *go1;
    cudaGetSymbolAddress((void**)&af, g_af);
    cudaGetSymbolAddress((void**)&w4, g_w4);
    cudaGetSymbolAddress((void**)&o2f, g_o2f);
    cudaGetSymbolAddress((void**)&gq, g_q);
    cudaGetSymbolAddress((void**)&gk, g_k);
    cudaGetSymbolAddress((void**)&gv, g_v);
    cudaGetSymbolAddress((void**)&go1, g_o1);

    const int WTOT = E_DIM * E_DIM;
    const size_t WSZ = (size_t)E_DIM * K2;

    cudaFuncSetAttribute(qkv_mma_kernel,
                         cudaFuncAttributeMaxDynamicSharedMemorySize,
                         SMEM_TOTAL);
    cudaFuncSetAttribute(out_mma_kernel,
                         cudaFuncAttributeMaxDynamicSharedMemorySize,
                         SMEM_TOTAL);
    cudaFuncSetAttribute(retention_kernel,
                         cudaFuncAttributeMaxDynamicSharedMemorySize,
                         RET_SMEM);

    // splits
    int nx = MROWS * E_DIM;
    split_af_kernel<<<nx / 1024, 256>>>(x, af);
    dim3 gsw(WTOT / 1024, 1, 4);
    split_w4_kernel<<<gsw, 256>>>(Wq, Wk, Wv, Wo, w4);

    // q/k/v projections (fp16 2-term, K=2048)
    dim3 gqkv(E_DIM / 128, MROWS / 128, 3);
    qkv_mma_kernel<<<gqkv, 256, SMEM_TOTAL>>>(af, w4, bq, bk, bv, gq, gk, gv);

    // retention (HMMA split-bf16); mode 1 writes fp16 [hi|lo]
    retention_kernel<<<HH * NHEADS, 256, RET_SMEM>>>(gk, gv, gq, go1, nullptr,
                                                     0);
    retention_kernel<<<WW * NHEADS, 256, RET_SMEM>>>(gk, gv, go1, nullptr,
                                                     o2f, 1);

    // output projection (fp16 2-term, K=2048)
    dim3 gout(E_DIM / 128, MROWS / 128, 1);
    out_mma_kernel<<<gout, 256, SMEM_TOTAL>>>(o2f, w4 + 3 * WSZ, bo, out);
}

// round 13
// speedup vs baseline: 2.0285x; 1.2490x over previous
#include <cuda_runtime.h>
#include <cuda_bf16.h>
#include <cuda_fp16.h>
#include <cstdint>

#define E_DIM 1024
#define K2 (2 * E_DIM)               /* 2048: [hi|lo] row stride */
#define NHEADS 16
#define DH 64
#define HH 128
#define WW 128
#define MROWS (HH * WW)              /* 16384 */
#define HWD ((size_t)MROWS * DH)

#define BK 64
#define ROWP 72                       /* padded row (elems), 144B */
#define TILE_ROWS 128
#define STAGE_HALF (TILE_ROWS * ROWP)
#define STAGE_BYTES (2 * STAGE_HALF * 2)   /* 36864 */
#define SMEM_TOTAL (2 * STAGE_BYTES)       /* 73728 */

/* retention smem layout (dynamic, bytes) */
#define RLD 72                        /* bf16 row pitch (144B) */
#define R_KBH 0
#define R_KBL 18432
#define R_VBH 36864
#define R_VBL 55296
#define R_KVH 0
#define R_KVL 9216
#define R_QSH 18432
#define R_QSL 36864
#define RET_SMEM 73728

// ---------------- scratch (static device arrays; no allocation) ----------------
__device__ __half g_af[(size_t)MROWS * K2];               // [hi|lo] fp16 of x
__device__ __half g_w4[4][(size_t)E_DIM * K2];            // [Wh|Wh] fp16 q,k,v,o
__device__ __half g_o2f[(size_t)MROWS * K2];              // [hi|--] fp16 of o2
__device__ float g_q[(size_t)NHEADS * MROWS * DH];
__device__ float g_k[(size_t)NHEADS * MROWS * DH];
__device__ float g_v[(size_t)NHEADS * MROWS * DH];
__device__ float g_o1[(size_t)NHEADS * MROWS * DH];

// ======================= helpers =======================
__device__ __forceinline__ uint32_t smem_u32(const void* p) {
    uint32_t a;
    asm("{ .reg .u64 t; cvta.to.shared.u64 t, %1; cvt.u32.u64 %0, t; }"
        : "=r"(a) : "l"(p));
    return a;
}

__device__ __forceinline__ void cp_async16(uint32_t dst, const void* src) {
    asm volatile("cp.async.cg.shared.global [%0], [%1], 16;\n"
                 :: "r"(dst), "l"(src) : "memory");
}

template <int N>
__device__ __forceinline__ void cp_wait() {
    asm volatile("cp.async.wait_group %0;\n" :: "n"(N) : "memory");
}

__device__ __forceinline__ void ldm_x4(uint32_t* r, uint32_t addr) {
    asm volatile(
        "ldmatrix.sync.aligned.m8n8.x4.shared.b16 {%0,%1,%2,%3}, [%4];"
        : "=r"(r[0]), "=r"(r[1]), "=r"(r[2]), "=r"(r[3]) : "r"(addr));
}

__device__ __forceinline__ void ldm_x4t(uint32_t* r, uint32_t addr) {
    asm volatile(
        "ldmatrix.sync.aligned.m8n8.x4.trans.shared.b16 {%0,%1,%2,%3}, [%4];"
        : "=r"(r[0]), "=r"(r[1]), "=r"(r[2]), "=r"(r[3]) : "r"(addr));
}

__device__ __forceinline__ void mma_bf16(float* c, const uint32_t* a,
                                         const uint32_t* b) {
    asm volatile(
        "mma.sync.aligned.m16n8k16.row.col.f32.bf16.bf16.f32 "
        "{%0,%1,%2,%3}, {%4,%5,%6,%7}, {%8,%9}, {%0,%1,%2,%3};"
        : "+f"(c[0]), "+f"(c[1]), "+f"(c[2]), "+f"(c[3])
        : "r"(a[0]), "r"(a[1]), "r"(a[2]), "r"(a[3]), "r"(b[0]), "r"(b[1]));
}

__device__ __forceinline__ void mma_fp16(float* c, const uint32_t* a,
                                         const uint32_t* b) {
    asm volatile(
        "mma.sync.aligned.m16n8k16.row.col.f32.f16.f16.f32 "
        "{%0,%1,%2,%3}, {%4,%5,%6,%7}, {%8,%9}, {%0,%1,%2,%3};"
        : "+f"(c[0]), "+f"(c[1]), "+f"(c[2]), "+f"(c[3])
        : "r"(a[0]), "r"(a[1]), "r"(a[2]), "r"(a[3]), "r"(b[0]), "r"(b[1]));
}

__device__ __forceinline__ __nv_bfloat162 split_hi2(float a, float b,
                                                    float& ra, float& rb) {
    __nv_bfloat16 ha = __float2bfloat16(a);
    __nv_bfloat16 hb = __float2bfloat16(b);
    ra = a - __bfloat162float(ha);
    rb = b - __bfloat162float(hb);
    return __nv_bfloat162(ha, hb);
}

// ======================= fp16 HMMA GEMM (proven config) =====================
// D[m,n] = sum_{k<KITER} A2[m*LDA + k] * B2[n*LDB + k] + bias[n]
// CTA 128x128, 256 threads (8 warps: 4m x 2n), warp tile 32x64.
// K-chunk 64, double-buffered cp.async.
template <int HEADLAYOUT, int KITER, int LDA, int LDB>
__device__ __forceinline__ void mma_gemm_body(
    const __half* __restrict__ A2, const __half* __restrict__ B2,
    const float* __restrict__ bias, float* __restrict__ out, bool relu) {
    extern __shared__ char smem[];
    const int tid = threadIdx.x;
    const int wid = tid >> 5;
    const int lane = tid & 31;
    const int wm = wid & 3;
    const int wn = wid >> 2;
    const int m0 = blockIdx.y * 128;
    const int n0 = blockIdx.x * 128;
    constexpr int NCH = KITER / BK;

    float acc[2][8][4];
#pragma unroll
    for (int i = 0; i < 2; i++)
#pragma unroll
        for (int j = 0; j < 8; j++)
#pragma unroll
            for (int c = 0; c < 4; c++) acc[i][j][c] = 0.f;

    auto stA = [&](int s) {
        return reinterpret_cast<__half*>(smem + s * STAGE_BYTES);
    };
    auto stB = [&](int s) {
        return reinterpret_cast<__half*>(smem + s * STAGE_BYTES) + STAGE_HALF;
    };

    auto load_chunk = [&](int s, int k0) {
        __half* a = stA(s);
        __half* b = stB(s);
#pragma unroll
        for (int i = 0; i < 4; i++) {
            int c = tid + i * 256;
            int row = c >> 3;
            int seg = (c & 7) * 8;
            cp_async16(smem_u32(a + row * ROWP + seg),
                       A2 + (size_t)(m0 + row) * LDA + k0 + seg);
            cp_async16(smem_u32(b + row * ROWP + seg),
                       B2 + (size_t)(n0 + row) * LDB + k0 + seg);
        }
        asm volatile("cp.async.commit_group;\n" ::: "memory");
    };

    load_chunk(0, 0);

    const int a_row = lane & 15;
    const int a_c8 = (lane >> 4) * 8;
    const int b_row = (lane & 7) | ((lane & 16) >> 1);
    const int b_c8 = ((lane >> 3) & 1) * 8;

    for (int ch = 0; ch < NCH; ch++) {
        if (ch + 1 < NCH) {
            load_chunk((ch + 1) & 1, (ch + 1) * BK);
            cp_wait<1>();
        } else {
            cp_wait<0>();
        }
        __syncthreads();

        const int buf = ch & 1;
        const uint32_t sbA = smem_u32(stA(buf));
        const uint32_t sbB = smem_u32(stB(buf));

#pragma unroll
        for (int kk = 0; kk < 4; kk++) {
            uint32_t a[2][4], b[8][2];
#pragma unroll
            for (int mt = 0; mt < 2; mt++) {
                uint32_t addr = sbA +
                    2 * ((32 * wm + 16 * mt + a_row) * ROWP + kk * 16 + a_c8);
                ldm_x4(a[mt], addr);
            }
#pragma unroll
            for (int np = 0; np < 4; np++) {
                uint32_t r[4];
                uint32_t addr = sbB +
                    2 * ((64 * wn + 16 * np + b_row) * ROWP + kk * 16 + b_c8);
                ldm_x4(r, addr);
                b[np * 2][0] = r[0]; b[np * 2][1] = r[1];
                b[np * 2 + 1][0] = r[2]; b[np * 2 + 1][1] = r[3];
            }
#pragma unroll
            for (int mt = 0; mt < 2; mt++)
#pragma unroll
                for (int nt = 0; nt < 8; nt++)
                    mma_fp16(acc[mt][nt], a[mt], b[nt]);
        }
        __syncthreads();
    }

    const int g = lane >> 2;
    const int tq = lane & 3;
#pragma unroll
    for (int nt = 0; nt < 8; nt++) {
        const int n = n0 + 64 * wn + 8 * nt + 2 * tq;
        const float b0 = __ldg(bias + n);
        const float b1 = __ldg(bias + n + 1);
#pragma unroll
        for (int mt = 0; mt < 2; mt++) {
            const int mbase = m0 + 32 * wm + 16 * mt + g;
#pragma unroll
            for (int half = 0; half < 2; half++) {
                const int m = mbase + half * 8;
                float v0 = acc[mt][nt][half * 2] + b0;
                float v1 = acc[mt][nt][half * 2 + 1] + b1;
                if (relu) { v0 = fmaxf(v0, 0.f); v1 = fmaxf(v1, 0.f); }
                float2 t = make_float2(v0, v1);
                if (HEADLAYOUT) {
                    *reinterpret_cast<float2*>(
                        out + (size_t)(n >> 6) * HWD + (size_t)m * 64 +
                        (n & 63)) = t;
                } else {
                    *reinterpret_cast<float2*>(out + (size_t)m * E_DIM + n) = t;
                }
            }
        }
    }
}

// q,k: 2-term (K=2048). v: single-term (K=1024, hi halves only).
__global__ __launch_bounds__(256, 2) void qk_mma_kernel(
    const __half* __restrict__ af, const __half* __restrict__ w4,
    const float* __restrict__ bq, const float* __restrict__ bk, float* gq,
    float* gk) {
    const size_t WSZ = (size_t)E_DIM * K2;
    const __half* B = w4 + (size_t)blockIdx.z * WSZ;
    const float* bias = (blockIdx.z == 0) ? bq : bk;
    float* outp = (blockIdx.z == 0) ? gq : gk;
    mma_gemm_body<1, K2, K2, K2>(af, B, bias, outp, true);
}

__global__ __launch_bounds__(256, 2) void v_mma_kernel(
    const __half* __restrict__ af, const __half* __restrict__ wv,
    const float* __restrict__ bv, float* gv) {
    mma_gemm_body<1, E_DIM, K2, K2>(af, wv, bv, gv, false);
}

__global__ __launch_bounds__(256, 2) void out_mma_kernel(
    const __half* __restrict__ a2, const __half* __restrict__ b2,
    const float* __restrict__ bias, float* __restrict__ out) {
    mma_gemm_body<0, E_DIM, K2, K2>(a2, b2, bias, out, false);
}

// ======================= fp32 -> fp16 split kernels =======================
// x -> fp16 [hi | lo], K2 layout
__global__ __launch_bounds__(256) void split_af_kernel(
    const float* __restrict__ in, __half* __restrict__ out) {
    int i = (blockIdx.x * 256 + threadIdx.x) * 4;
    float4 v = *reinterpret_cast<const float4*>(in + i);
    float f[4] = {v.x, v.y, v.z, v.w};
    __half h[4], l[4];
#pragma unroll
    for (int j = 0; j < 4; j++) {
        h[j] = __float2half(f[j]);
        l[j] = __float2half(f[j] - __half2float(h[j]));
    }
    int row = i >> 10;
    int k = i & 1023;
    __half* base = out + (size_t)row * K2 + k;
    reinterpret_cast<__half2*>(base)[0] = __half2(h[0], h[1]);
    reinterpret_cast<__half2*>(base)[1] = __half2(h[2], h[3]);
    reinterpret_cast<__half2*>(base + E_DIM)[0] = __half2(l[0], l[1]);
    reinterpret_cast<__half2*>(base + E_DIM)[1] = __half2(l[2], l[3]);
}

// W -> fp16 [Wh | Wh] (duplicated hi), K2 layout; z selects weight
__global__ __launch_bounds__(256) void split_w4_kernel(
    const float* __restrict__ w0, const float* __restrict__ w1,
    const float* __restrict__ w2, const float* __restrict__ w3,
    __half* __restrict__ out) {
    const float* w = (blockIdx.z == 0) ? w0
                     : (blockIdx.z == 1) ? w1
                     : (blockIdx.z == 2) ? w2 : w3;
    __half* o = out + (size_t)blockIdx.z * E_DIM * K2;
    int i = (blockIdx.x * 256 + threadIdx.x) * 4;
    float4 v = *reinterpret_cast<const float4*>(w + i);
    __half2 p0(__float2half(v.x), __float2half(v.y));
    __half2 p1(__float2half(v.z), __float2half(v.w));
    int row = i >> 10;
    int k = i & 1023;
    __half* base = o + (size_t)row * K2 + k;
    reinterpret_cast<__half2*>(base)[0] = p0;
    reinterpret_cast<__half2*>(base)[1] = p1;
    reinterpret_cast<__half2*>(base + E_DIM)[0] = p0;
    reinterpret_cast<__half2*>(base + E_DIM)[1] = p1;
}

// ======================= fused retention (HMMA, split-bf16; R5-proven) ======
__global__ __launch_bounds__(256, 2) void retention_kernel(
    const float* __restrict__ kArr, const float* __restrict__ vArr,
    const float* __restrict__ cArr, float* __restrict__ oF,
    __half* __restrict__ oCat, int mode) {
    extern __shared__ char rsm[];
    const int tid = threadIdx.x;
    const int wid = tid >> 5;
    const int lane = tid & 31;
    const int b = blockIdx.x;
    const int n = b & 15;
    const int idx = b >> 4;

    size_t base;
    int rs;
    if (mode == 0) {
        base = (size_t)n * HWD + (size_t)idx * (WW * DH);
        rs = DH;
    } else {
        base = (size_t)n * HWD + (size_t)idx * DH;
        rs = WW * DH;
    }
    const float* kS = kArr + base;
    const float* vS = vArr + base;
    const float* cS = cArr + base;

    auto conv = [&](const float* src, __nv_bfloat16* dh, __nv_bfloat16* dl) {
#pragma unroll
        for (int i = 0; i < 8; i++) {
            int id = tid + i * 256;
            int w = id >> 4;
            int c = (id & 15) << 2;
            float4 v4 = *reinterpret_cast<const float4*>(src +
                                                         (size_t)w * rs + c);
            float r0, r1, r2, r3;
            __nv_bfloat162 h01 = split_hi2(v4.x, v4.y, r0, r1);
            __nv_bfloat162 h23 = split_hi2(v4.z, v4.w, r2, r3);
            *reinterpret_cast<__nv_bfloat162*>(dh + w * RLD + c) = h01;
            *reinterpret_cast<__nv_bfloat162*>(dh + w * RLD + c + 2) = h23;
            *reinterpret_cast<__nv_bfloat162*>(dl + w * RLD + c) =
                __nv_bfloat162(__float2bfloat16(r0), __float2bfloat16(r1));
            *reinterpret_cast<__nv_bfloat162*>(dl + w * RLD + c + 2) =
                __nv_bfloat162(__float2bfloat16(r2), __float2bfloat16(r3));
        }
    };
    conv(kS, reinterpret_cast<__nv_bfloat16*>(rsm + R_KBH),
         reinterpret_cast<__nv_bfloat16*>(rsm + R_KBL));
    conv(vS, reinterpret_cast<__nv_bfloat16*>(rsm + R_VBH),
         reinterpret_cast<__nv_bfloat16*>(rsm + R_VBL));
    __syncthreads();

    const uint32_t sb = smem_u32(rsm);
    const int g = lane >> 2;
    const int tq = lane & 3;

    // ---- phase A: kvT[e][d] (64x64) via trans ldmatrix ----
    const int e0 = (wid >> 1) * 16;
    const int d0 = (wid & 1) * 32;
    const int ta_row = (lane & 7) + ((lane >> 4) & 1) * 8;
    const int ta_col = ((lane >> 3) & 1) * 8;
    const int tb_row = (lane & 7) + ((lane >> 3) & 1) * 8;
    const int tb_col = ((lane >> 4) & 1) * 8;

    float acc1[4][4];
#pragma unroll
    for (int i = 0; i < 4; i++)
#pragma unroll
        for (int j = 0; j < 4; j++) acc1[i][j] = 0.f;

#pragma unroll
    for (int ks = 0; ks < 8; ks++) {
        const int k0 = ks * 16;
        uint32_t avh[4], avl[4];
        ldm_x4t(avh, sb + R_VBH + 2 * ((k0 + ta_row) * RLD + e0 + ta_col));
        ldm_x4t(avl, sb + R_VBL + 2 * ((k0 + ta_row) * RLD + e0 + ta_col));
        uint32_t bh[2][4], bl[2][4];
#pragma unroll
        for (int nq = 0; nq < 2; nq++) {
            ldm_x4t(bh[nq], sb + R_KBH +
                    2 * ((k0 + tb_row) * RLD + d0 + nq * 16 + tb_col));
            ldm_x4t(bl[nq], sb + R_KBL +
                    2 * ((k0 + tb_row) * RLD + d0 + nq * 16 + tb_col));
        }
#pragma unroll
        for (int nq = 0; nq < 2; nq++)
#pragma unroll
            for (int p = 0; p < 2; p++) {
                const int nt = nq * 2 + p;
                uint32_t bfh[2] = {bh[nq][2 * p], bh[nq][2 * p + 1]};
                uint32_t bfl[2] = {bl[nq][2 * p], bl[nq][2 * p + 1]};
                mma_bf16(acc1[nt], avh, bfh);
                mma_bf16(acc1[nt], avh, bfl);
                mma_bf16(acc1[nt], avl, bfh);
            }
    }
    __syncthreads();

    {
        __nv_bfloat16* kvh = reinterpret_cast<__nv_bfloat16*>(rsm + R_KVH);
        __nv_bfloat16* kvl = reinterpret_cast<__nv_bfloat16*>(rsm + R_KVL);
#pragma unroll
        for (int nt = 0; nt < 4; nt++)
#pragma unroll
            for (int half = 0; half < 2; half++) {
                const int e = e0 + g + half * 8;
                const int d = d0 + nt * 8 + 2 * tq;
                float r0, r1;
                __nv_bfloat162 hp = split_hi2(acc1[nt][half * 2],
                                              acc1[nt][half * 2 + 1], r0, r1);
                *reinterpret_cast<__nv_bfloat162*>(kvh + e * RLD + d) = hp;
                *reinterpret_cast<__nv_bfloat162*>(kvl + e * RLD + d) =
                    __nv_bfloat162(__float2bfloat16(r0), __float2bfloat16(r1));
            }
    }
    conv(cS, reinterpret_cast<__nv_bfloat16*>(rsm + R_QSH),
         reinterpret_cast<__nv_bfloat16*>(rsm + R_QSL));
    __syncthreads();

    // ---- phase B: out[r][e] (128x64) ----
    const int r0 = wid * 16;
    const int a_row = lane & 15;
    const int a_c8 = (lane >> 4) * 8;
    const int b_row = (lane & 7) | ((lane & 16) >> 1);
    const int b_c8 = ((lane >> 3) & 1) * 8;

    float acc2[8][4];
#pragma unroll
    for (int i = 0; i < 8; i++)
#pragma unroll
        for (int j = 0; j < 4; j++) acc2[i][j] = 0.f;

#pragma unroll
    for (int ks = 0; ks < 4; ks++) {
        const int k0 = ks * 16;
        uint32_t aqh[4], aql[4];
        ldm_x4(aqh, sb + R_QSH + 2 * ((r0 + a_row) * RLD + k0 + a_c8));
        ldm_x4(aql, sb + R_QSL + 2 * ((r0 + a_row) * RLD + k0 + a_c8));
        uint32_t kh[4][4], kl[4][4];
#pragma unroll
        for (int nq = 0; nq < 4; nq++) {
            ldm_x4(kh[nq], sb + R_KVH +
                   2 * ((nq * 16 + b_row) * RLD + k0 + b_c8));
            ldm_x4(kl[nq], sb + R_KVL +
                   2 * ((nq * 16 + b_row) * RLD + k0 + b_c8));
        }
#pragma unroll
        for (int nt = 0; nt < 8; nt++) {
            const int nq = nt >> 1;
            const int p = nt & 1;
            uint32_t bfh[2] = {kh[nq][2 * p], kh[nq][2 * p + 1]};
            uint32_t bfl[2] = {kl[nq][2 * p], kl[nq][2 * p + 1]};
            mma_bf16(acc2[nt], aqh, bfh);
            mma_bf16(acc2[nt], aqh, bfl);
            mma_bf16(acc2[nt], aql, bfh);
        }
    }

#pragma unroll
    for (int nt = 0; nt < 8; nt++) {
        const int e = nt * 8 + 2 * tq;
#pragma unroll
        for (int half = 0; half < 2; half++) {
            const int r = r0 + g + half * 8;
            float v0 = acc2[nt][half * 2];
            float v1 = acc2[nt][half * 2 + 1];
            if (mode == 0) {
                *reinterpret_cast<float2*>(oF + base + (size_t)r * DH + e) =
                    make_float2(v0, v1);
            } else {
                // single-term consumer: store hi only
                const int m = r * WW + idx;
                __half* bp = oCat + (size_t)m * K2 + n * DH + e;
                *reinterpret_cast<__half2*>(bp) =
                    __half2(__float2half(v0), __float2half(v1));
            }
        }
    }
}

// =======================================================================
extern "C" void kernel_launch(void* const* d_in, const int* in_sizes, int n_in,
                              void* d_out, int out_size) {
    const float* x  = (const float*)d_in[0];
    const float* Wq = (const float*)d_in[1];
    const float* bq = (const float*)d_in[2];
    const float* Wk = (const float*)d_in[3];
    const float* bk = (const float*)d_in[4];
    const float* Wv = (const float*)d_in[5];
    const float* bv = (const float*)d_in[6];
    const float* Wo = (const float*)d_in[7];
    const float* bo = (const float*)d_in[8];
    float* out = (float*)d_out;

    __half *af, *w4, *o2f;
    float *gq, *gk, *gv, *go1;
    cudaGetSymbolAddress((void**)&af, g_af);
    cudaGetSymbolAddress((void**)&w4, g_w4);
    cudaGetSymbolAddress((void**)&o2f, g_o2f);
    cudaGetSymbolAddress((void**)&gq, g_q);
    cudaGetSymbolAddress((void**)&gk, g_k);
    cudaGetSymbolAddress((void**)&gv, g_v);
    cudaGetSymbolAddress((void**)&go1, g_o1);

    const int WTOT = E_DIM * E_DIM;
    const size_t WSZ = (size_t)E_DIM * K2;

    cudaFuncSetAttribute(qk_mma_kernel,
                         cudaFuncAttributeMaxDynamicSharedMemorySize,
                         SMEM_TOTAL);
    cudaFuncSetAttribute(v_mma_kernel,
                         cudaFuncAttributeMaxDynamicSharedMemorySize,
                         SMEM_TOTAL);
    cudaFuncSetAttribute(out_mma_kernel,
                         cudaFuncAttributeMaxDynamicSharedMemorySize,
                         SMEM_TOTAL);
    cudaFuncSetAttribute(retention_kernel,
                         cudaFuncAttributeMaxDynamicSharedMemorySize,
                         RET_SMEM);

    // splits
    int nx = MROWS * E_DIM;
    split_af_kernel<<<nx / 1024, 256>>>(x, af);
    dim3 gsw(WTOT / 1024, 1, 4);
    split_w4_kernel<<<gsw, 256>>>(Wq, Wk, Wv, Wo, w4);

    // q/k projections (fp16 2-term, K=2048)
    dim3 gqk(E_DIM / 128, MROWS / 128, 2);
    qk_mma_kernel<<<gqk, 256, SMEM_TOTAL>>>(af, w4, bq, bk, gq, gk);

    // v projection (fp16 single-term, K=1024)
    dim3 g1(E_DIM / 128, MROWS / 128, 1);
    v_mma_kernel<<<g1, 256, SMEM_TOTAL>>>(af, w4 + 2 * WSZ, bv, gv);

    // retention (HMMA split-bf16); mode 1 writes fp16 hi
    retention_kernel<<<HH * NHEADS, 256, RET_SMEM>>>(gk, gv, gq, go1, nullptr,
                                                     0);
    retention_kernel<<<WW * NHEADS, 256, RET_SMEM>>>(gk, gv, go1, nullptr,
                                                     o2f, 1);

    // output projection (fp16 single-term, K=1024)
    out_mma_kernel<<<g1, 256, SMEM_TOTAL>>>(o2f, w4 + 3 * WSZ, bo, out);
}

// round 14
// speedup vs baseline: 2.7045x; 1.3332x over previous
#include <cuda_runtime.h>
#include <cuda_bf16.h>
#include <cuda_fp16.h>
#include <cstdint>

#define E_DIM 1024
#define NHEADS 16
#define DH 64
#define HH 128
#define WW 128
#define MROWS (HH * WW)              /* 16384 */
#define HWD ((size_t)MROWS * DH)

#define BK 64
#define NCH (E_DIM / BK)              /* 16 */
#define ROWP 72                       /* padded row (elems), 144B */
#define TILE_ROWS 128
#define STAGE_HALF (TILE_ROWS * ROWP)
#define STAGE_BYTES (2 * STAGE_HALF * 2)   /* 36864 */
#define SMEM_TOTAL (2 * STAGE_BYTES)       /* 73728 */

/* retention smem layout (dynamic, bytes) */
#define RLD 72                        /* bf16 row pitch (144B) */
#define R_KBH 0
#define R_KBL 18432
#define R_VBH 36864
#define R_VBL 55296
#define R_KVH 0
#define R_KVL 9216
#define R_QSH 18432
#define R_QSL 36864
#define RET_SMEM 73728

// ---------------- scratch (static device arrays; no allocation) ----------------
__device__ __half g_af[(size_t)MROWS * E_DIM];            // fp16 cast of x
__device__ __half g_w4[4][(size_t)E_DIM * E_DIM];         // fp16 casts q,k,v,o
__device__ __half g_o2f[(size_t)MROWS * E_DIM];           // fp16 of o2
__device__ float g_q[(size_t)NHEADS * MROWS * DH];
__device__ float g_k[(size_t)NHEADS * MROWS * DH];
__device__ float g_v[(size_t)NHEADS * MROWS * DH];
__device__ float g_o1[(size_t)NHEADS * MROWS * DH];

// ======================= helpers =======================
__device__ __forceinline__ uint32_t smem_u32(const void* p) {
    uint32_t a;
    asm("{ .reg .u64 t; cvta.to.shared.u64 t, %1; cvt.u32.u64 %0, t; }"
        : "=r"(a) : "l"(p));
    return a;
}

__device__ __forceinline__ void cp_async16(uint32_t dst, const void* src) {
    asm volatile("cp.async.cg.shared.global [%0], [%1], 16;\n"
                 :: "r"(dst), "l"(src) : "memory");
}

template <int N>
__device__ __forceinline__ void cp_wait() {
    asm volatile("cp.async.wait_group %0;\n" :: "n"(N) : "memory");
}

__device__ __forceinline__ void ldm_x4(uint32_t* r, uint32_t addr) {
    asm volatile(
        "ldmatrix.sync.aligned.m8n8.x4.shared.b16 {%0,%1,%2,%3}, [%4];"
        : "=r"(r[0]), "=r"(r[1]), "=r"(r[2]), "=r"(r[3]) : "r"(addr));
}

__device__ __forceinline__ void ldm_x4t(uint32_t* r, uint32_t addr) {
    asm volatile(
        "ldmatrix.sync.aligned.m8n8.x4.trans.shared.b16 {%0,%1,%2,%3}, [%4];"
        : "=r"(r[0]), "=r"(r[1]), "=r"(r[2]), "=r"(r[3]) : "r"(addr));
}

__device__ __forceinline__ void mma_bf16(float* c, const uint32_t* a,
                                         const uint32_t* b) {
    asm volatile(
        "mma.sync.aligned.m16n8k16.row.col.f32.bf16.bf16.f32 "
        "{%0,%1,%2,%3}, {%4,%5,%6,%7}, {%8,%9}, {%0,%1,%2,%3};"
        : "+f"(c[0]), "+f"(c[1]), "+f"(c[2]), "+f"(c[3])
        : "r"(a[0]), "r"(a[1]), "r"(a[2]), "r"(a[3]), "r"(b[0]), "r"(b[1]));
}

__device__ __forceinline__ void mma_fp16(float* c, const uint32_t* a,
                                         const uint32_t* b) {
    asm volatile(
        "mma.sync.aligned.m16n8k16.row.col.f32.f16.f16.f32 "
        "{%0,%1,%2,%3}, {%4,%5,%6,%7}, {%8,%9}, {%0,%1,%2,%3};"
        : "+f"(c[0]), "+f"(c[1]), "+f"(c[2]), "+f"(c[3])
        : "r"(a[0]), "r"(a[1]), "r"(a[2]), "r"(a[3]), "r"(b[0]), "r"(b[1]));
}

__device__ __forceinline__ __nv_bfloat162 split_hi2(float a, float b,
                                                    float& ra, float& rb) {
    __nv_bfloat16 ha = __float2bfloat16(a);
    __nv_bfloat16 hb = __float2bfloat16(b);
    ra = a - __bfloat162float(ha);
    rb = b - __bfloat162float(hb);
    return __nv_bfloat162(ha, hb);
}

// ======================= fp16 HMMA GEMM (proven config, K=1024) =============
// D[m,n] = sum_{k<E_DIM} A[m,k] * B[n,k] + bias[n]
// CTA 128x128, 256 threads (8 warps: 4m x 2n), warp tile 32x64.
// K-chunk 64, double-buffered cp.async.
template <int HEADLAYOUT>
__device__ __forceinline__ void mma_gemm_body(
    const __half* __restrict__ A2, const __half* __restrict__ B2,
    const float* __restrict__ bias, float* __restrict__ out, bool relu) {
    extern __shared__ char smem[];
    const int tid = threadIdx.x;
    const int wid = tid >> 5;
    const int lane = tid & 31;
    const int wm = wid & 3;
    const int wn = wid >> 2;
    const int m0 = blockIdx.y * 128;
    const int n0 = blockIdx.x * 128;

    float acc[2][8][4];
#pragma unroll
    for (int i = 0; i < 2; i++)
#pragma unroll
        for (int j = 0; j < 8; j++)
#pragma unroll
            for (int c = 0; c < 4; c++) acc[i][j][c] = 0.f;

    auto stA = [&](int s) {
        return reinterpret_cast<__half*>(smem + s * STAGE_BYTES);
    };
    auto stB = [&](int s) {
        return reinterpret_cast<__half*>(smem + s * STAGE_BYTES) + STAGE_HALF;
    };

    auto load_chunk = [&](int s, int k0) {
        __half* a = stA(s);
        __half* b = stB(s);
#pragma unroll
        for (int i = 0; i < 4; i++) {
            int c = tid + i * 256;
            int row = c >> 3;
            int seg = (c & 7) * 8;
            cp_async16(smem_u32(a + row * ROWP + seg),
                       A2 + (size_t)(m0 + row) * E_DIM + k0 + seg);
            cp_async16(smem_u32(b + row * ROWP + seg),
                       B2 + (size_t)(n0 + row) * E_DIM + k0 + seg);
        }
        asm volatile("cp.async.commit_group;\n" ::: "memory");
    };

    load_chunk(0, 0);

    const int a_row = lane & 15;
    const int a_c8 = (lane >> 4) * 8;
    const int b_row = (lane & 7) | ((lane & 16) >> 1);
    const int b_c8 = ((lane >> 3) & 1) * 8;

    for (int ch = 0; ch < NCH; ch++) {
        if (ch + 1 < NCH) {
            load_chunk((ch + 1) & 1, (ch + 1) * BK);
            cp_wait<1>();
        } else {
            cp_wait<0>();
        }
        __syncthreads();

        const int buf = ch & 1;
        const uint32_t sbA = smem_u32(stA(buf));
        const uint32_t sbB = smem_u32(stB(buf));

#pragma unroll
        for (int kk = 0; kk < 4; kk++) {
            uint32_t a[2][4], b[8][2];
#pragma unroll
            for (int mt = 0; mt < 2; mt++) {
                uint32_t addr = sbA +
                    2 * ((32 * wm + 16 * mt + a_row) * ROWP + kk * 16 + a_c8);
                ldm_x4(a[mt], addr);
            }
#pragma unroll
            for (int np = 0; np < 4; np++) {
                uint32_t r[4];
                uint32_t addr = sbB +
                    2 * ((64 * wn + 16 * np + b_row) * ROWP + kk * 16 + b_c8);
                ldm_x4(r, addr);
                b[np * 2][0] = r[0]; b[np * 2][1] = r[1];
                b[np * 2 + 1][0] = r[2]; b[np * 2 + 1][1] = r[3];
            }
#pragma unroll
            for (int mt = 0; mt < 2; mt++)
#pragma unroll
                for (int nt = 0; nt < 8; nt++)
                    mma_fp16(acc[mt][nt], a[mt], b[nt]);
        }
        __syncthreads();
    }

    const int g = lane >> 2;
    const int tq = lane & 3;
#pragma unroll
    for (int nt = 0; nt < 8; nt++) {
        const int n = n0 + 64 * wn + 8 * nt + 2 * tq;
        const float b0 = __ldg(bias + n);
        const float b1 = __ldg(bias + n + 1);
#pragma unroll
        for (int mt = 0; mt < 2; mt++) {
            const int mbase = m0 + 32 * wm + 16 * mt + g;
#pragma unroll
            for (int half = 0; half < 2; half++) {
                const int m = mbase + half * 8;
                float v0 = acc[mt][nt][half * 2] + b0;
                float v1 = acc[mt][nt][half * 2 + 1] + b1;
                if (relu) { v0 = fmaxf(v0, 0.f); v1 = fmaxf(v1, 0.f); }
                float2 t = make_float2(v0, v1);
                if (HEADLAYOUT) {
                    *reinterpret_cast<float2*>(
                        out + (size_t)(n >> 6) * HWD + (size_t)m * 64 +
                        (n & 63)) = t;
                } else {
                    *reinterpret_cast<float2*>(out + (size_t)m * E_DIM + n) = t;
                }
            }
        }
    }
}

__global__ __launch_bounds__(256, 2) void qkv_mma_kernel(
    const __half* __restrict__ af, const __half* __restrict__ w4,
    const float* __restrict__ bq, const float* __restrict__ bk,
    const float* __restrict__ bv, float* gq, float* gk, float* gv) {
    const size_t WSZ = (size_t)E_DIM * E_DIM;
    const __half* B = w4 + (size_t)blockIdx.z * WSZ;
    const float* bias;
    float* outp;
    bool relu;
    if (blockIdx.z == 0) { bias = bq; outp = gq; relu = true; }
    else if (blockIdx.z == 1) { bias = bk; outp = gk; relu = true; }
    else { bias = bv; outp = gv; relu = false; }
    mma_gemm_body<1>(af, B, bias, outp, relu);
}

__global__ __launch_bounds__(256, 2) void out_mma_kernel(
    const __half* __restrict__ a2, const __half* __restrict__ b2,
    const float* __restrict__ bias, float* __restrict__ out) {
    mma_gemm_body<0>(a2, b2, bias, out, false);
}

// ======================= fp32 -> fp16 cast kernels =======================
__global__ __launch_bounds__(256) void cast_x_kernel(
    const float* __restrict__ in, __half* __restrict__ out) {
    int i = (blockIdx.x * 256 + threadIdx.x) * 4;
    float4 v = *reinterpret_cast<const float4*>(in + i);
    __half2* p = reinterpret_cast<__half2*>(out + i);
    p[0] = __half2(__float2half(v.x), __float2half(v.y));
    p[1] = __half2(__float2half(v.z), __float2half(v.w));
}

__global__ __launch_bounds__(256) void cast_w4_kernel(
    const float* __restrict__ w0, const float* __restrict__ w1,
    const float* __restrict__ w2, const float* __restrict__ w3,
    __half* __restrict__ out) {
    const float* w = (blockIdx.z == 0) ? w0
                     : (blockIdx.z == 1) ? w1
                     : (blockIdx.z == 2) ? w2 : w3;
    __half* o = out + (size_t)blockIdx.z * E_DIM * E_DIM;
    int i = (blockIdx.x * 256 + threadIdx.x) * 4;
    float4 v = *reinterpret_cast<const float4*>(w + i);
    __half2* p = reinterpret_cast<__half2*>(o + i);
    p[0] = __half2(__float2half(v.x), __float2half(v.y));
    p[1] = __half2(__float2half(v.z), __float2half(v.w));
}

// ======================= fused retention (HMMA, split-bf16; R5-proven) ======
__global__ __launch_bounds__(256, 2) void retention_kernel(
    const float* __restrict__ kArr, const float* __restrict__ vArr,
    const float* __restrict__ cArr, float* __restrict__ oF,
    __half* __restrict__ oCat, int mode) {
    extern __shared__ char rsm[];
    const int tid = threadIdx.x;
    const int wid = tid >> 5;
    const int lane = tid & 31;
    const int b = blockIdx.x;
    const int n = b & 15;
    const int idx = b >> 4;

    size_t base;
    int rs;
    if (mode == 0) {
        base = (size_t)n * HWD + (size_t)idx * (WW * DH);
        rs = DH;
    } else {
        base = (size_t)n * HWD + (size_t)idx * DH;
        rs = WW * DH;
    }
    const float* kS = kArr + base;
    const float* vS = vArr + base;
    const float* cS = cArr + base;

    auto conv = [&](const float* src, __nv_bfloat16* dh, __nv_bfloat16* dl) {
#pragma unroll
        for (int i = 0; i < 8; i++) {
            int id = tid + i * 256;
            int w = id >> 4;
            int c = (id & 15) << 2;
            float4 v4 = *reinterpret_cast<const float4*>(src +
                                                         (size_t)w * rs + c);
            float r0, r1, r2, r3;
            __nv_bfloat162 h01 = split_hi2(v4.x, v4.y, r0, r1);
            __nv_bfloat162 h23 = split_hi2(v4.z, v4.w, r2, r3);
            *reinterpret_cast<__nv_bfloat162*>(dh + w * RLD + c) = h01;
            *reinterpret_cast<__nv_bfloat162*>(dh + w * RLD + c + 2) = h23;
            *reinterpret_cast<__nv_bfloat162*>(dl + w * RLD + c) =
                __nv_bfloat162(__float2bfloat16(r0), __float2bfloat16(r1));
            *reinterpret_cast<__nv_bfloat162*>(dl + w * RLD + c + 2) =
                __nv_bfloat162(__float2bfloat16(r2), __float2bfloat16(r3));
        }
    };
    conv(kS, reinterpret_cast<__nv_bfloat16*>(rsm + R_KBH),
         reinterpret_cast<__nv_bfloat16*>(rsm + R_KBL));
    conv(vS, reinterpret_cast<__nv_bfloat16*>(rsm + R_VBH),
         reinterpret_cast<__nv_bfloat16*>(rsm + R_VBL));
    __syncthreads();

    const uint32_t sb = smem_u32(rsm);
    const int g = lane >> 2;
    const int tq = lane & 3;

    // ---- phase A: kvT[e][d] (64x64) via trans ldmatrix ----
    const int e0 = (wid >> 1) * 16;
    const int d0 = (wid & 1) * 32;
    const int ta_row = (lane & 7) + ((lane >> 4) & 1) * 8;
    const int ta_col = ((lane >> 3) & 1) * 8;
    const int tb_row = (lane & 7) + ((lane >> 3) & 1) * 8;
    const int tb_col = ((lane >> 4) & 1) * 8;

    float acc1[4][4];
#pragma unroll
    for (int i = 0; i < 4; i++)
#pragma unroll
        for (int j = 0; j < 4; j++) acc1[i][j] = 0.f;

#pragma unroll
    for (int ks = 0; ks < 8; ks++) {
        const int k0 = ks * 16;
        uint32_t avh[4], avl[4];
        ldm_x4t(avh, sb + R_VBH + 2 * ((k0 + ta_row) * RLD + e0 + ta_col));
        ldm_x4t(avl, sb + R_VBL + 2 * ((k0 + ta_row) * RLD + e0 + ta_col));
        uint32_t bh[2][4], bl[2][4];
#pragma unroll
        for (int nq = 0; nq < 2; nq++) {
            ldm_x4t(bh[nq], sb + R_KBH +
                    2 * ((k0 + tb_row) * RLD + d0 + nq * 16 + tb_col));
            ldm_x4t(bl[nq], sb + R_KBL +
                    2 * ((k0 + tb_row) * RLD + d0 + nq * 16 + tb_col));
        }
#pragma unroll
        for (int nq = 0; nq < 2; nq++)
#pragma unroll
            for (int p = 0; p < 2; p++) {
                const int nt = nq * 2 + p;
                uint32_t bfh[2] = {bh[nq][2 * p], bh[nq][2 * p + 1]};
                uint32_t bfl[2] = {bl[nq][2 * p], bl[nq][2 * p + 1]};
                mma_bf16(acc1[nt], avh, bfh);
                mma_bf16(acc1[nt], avh, bfl);
                mma_bf16(acc1[nt], avl, bfh);
            }
    }
    __syncthreads();

    {
        __nv_bfloat16* kvh = reinterpret_cast<__nv_bfloat16*>(rsm + R_KVH);
        __nv_bfloat16* kvl = reinterpret_cast<__nv_bfloat16*>(rsm + R_KVL);
#pragma unroll
        for (int nt = 0; nt < 4; nt++)
#pragma unroll
            for (int half = 0; half < 2; half++) {
                const int e = e0 + g + half * 8;
                const int d = d0 + nt * 8 + 2 * tq;
                float r0, r1;
                __nv_bfloat162 hp = split_hi2(acc1[nt][half * 2],
                                              acc1[nt][half * 2 + 1], r0, r1);
                *reinterpret_cast<__nv_bfloat162*>(kvh + e * RLD + d) = hp;
                *reinterpret_cast<__nv_bfloat162*>(kvl + e * RLD + d) =
                    __nv_bfloat162(__float2bfloat16(r0), __float2bfloat16(r1));
            }
    }
    conv(cS, reinterpret_cast<__nv_bfloat16*>(rsm + R_QSH),
         reinterpret_cast<__nv_bfloat16*>(rsm + R_QSL));
    __syncthreads();

    // ---- phase B: out[r][e] (128x64) ----
    const int r0 = wid * 16;
    const int a_row = lane & 15;
    const int a_c8 = (lane >> 4) * 8;
    const int b_row = (lane & 7) | ((lane & 16) >> 1);
    const int b_c8 = ((lane >> 3) & 1) * 8;

    float acc2[8][4];
#pragma unroll
    for (int i = 0; i < 8; i++)
#pragma unroll
        for (int j = 0; j < 4; j++) acc2[i][j] = 0.f;

#pragma unroll
    for (int ks = 0; ks < 4; ks++) {
        const int k0 = ks * 16;
        uint32_t aqh[4], aql[4];
        ldm_x4(aqh, sb + R_QSH + 2 * ((r0 + a_row) * RLD + k0 + a_c8));
        ldm_x4(aql, sb + R_QSL + 2 * ((r0 + a_row) * RLD + k0 + a_c8));
        uint32_t kh[4][4], kl[4][4];
#pragma unroll
        for (int nq = 0; nq < 4; nq++) {
            ldm_x4(kh[nq], sb + R_KVH +
                   2 * ((nq * 16 + b_row) * RLD + k0 + b_c8));
            ldm_x4(kl[nq], sb + R_KVL +
                   2 * ((nq * 16 + b_row) * RLD + k0 + b_c8));
        }
#pragma unroll
        for (int nt = 0; nt < 8; nt++) {
            const int nq = nt >> 1;
            const int p = nt & 1;
            uint32_t bfh[2] = {kh[nq][2 * p], kh[nq][2 * p + 1]};
            uint32_t bfl[2] = {kl[nq][2 * p], kl[nq][2 * p + 1]};
            mma_bf16(acc2[nt], aqh, bfh);
            mma_bf16(acc2[nt], aqh, bfl);
            mma_bf16(acc2[nt], aql, bfh);
        }
    }

#pragma unroll
    for (int nt = 0; nt < 8; nt++) {
        const int e = nt * 8 + 2 * tq;
#pragma unroll
        for (int half = 0; half < 2; half++) {
            const int r = r0 + g + half * 8;
            float v0 = acc2[nt][half * 2];
            float v1 = acc2[nt][half * 2 + 1];
            if (mode == 0) {
                *reinterpret_cast<float2*>(oF + base + (size_t)r * DH + e) =
                    make_float2(v0, v1);
            } else {
                const int m = r * WW + idx;
                __half* bp = oCat + (size_t)m * E_DIM + n * DH + e;
                *reinterpret_cast<__half2*>(bp) =
                    __half2(__float2half(v0), __float2half(v1));
            }
        }
    }
}

// =======================================================================
extern "C" void kernel_launch(void* const* d_in, const int* in_sizes, int n_in,
                              void* d_out, int out_size) {
    const float* x  = (const float*)d_in[0];
    const float* Wq = (const float*)d_in[1];
    const float* bq = (const float*)d_in[2];
    const float* Wk = (const float*)d_in[3];
    const float* bk = (const float*)d_in[4];
    const float* Wv = (const float*)d_in[5];
    const float* bv = (const float*)d_in[6];
    const float* Wo = (const float*)d_in[7];
    const float* bo = (const float*)d_in[8];
    float* out = (float*)d_out;

    __half *af, *w4, *o2f;
    float *gq, *gk, *gv, *go1;
    cudaGetSymbolAddress((void**)&af, g_af);
    cudaGetSymbolAddress((void**)&w4, g_w4);
    cudaGetSymbolAddress((void**)&o2f, g_o2f);
    cudaGetSymbolAddress((void**)&gq, g_q);
    cudaGetSymbolAddress((void**)&gk, g_k);
    cudaGetSymbolAddress((void**)&gv, g_v);
    cudaGetSymbolAddress((void**)&go1, g_o1);

    const int WTOT = E_DIM * E_DIM;
    const size_t WSZ = (size_t)E_DIM * E_DIM;

    cudaFuncSetAttribute(qkv_mma_kernel,
                         cudaFuncAttributeMaxDynamicSharedMemorySize,
                         SMEM_TOTAL);
    cudaFuncSetAttribute(out_mma_kernel,
                         cudaFuncAttributeMaxDynamicSharedMemorySize,
                         SMEM_TOTAL);
    cudaFuncSetAttribute(retention_kernel,
                         cudaFuncAttributeMaxDynamicSharedMemorySize,
                         RET_SMEM);

    // casts
    int nx = MROWS * E_DIM;
    cast_x_kernel<<<nx / 1024, 256>>>(x, af);
    dim3 gcw(WTOT / 1024, 1, 4);
    cast_w4_kernel<<<gcw, 256>>>(Wq, Wk, Wv, Wo, w4);

    // q/k/v projections (fp16, K=1024)
    dim3 gqkv(E_DIM / 128, MROWS / 128, 3);
    qkv_mma_kernel<<<gqkv, 256, SMEM_TOTAL>>>(af, w4, bq, bk, bv, gq, gk, gv);

    // retention (HMMA split-bf16); mode 1 writes fp16
    retention_kernel<<<HH * NHEADS, 256, RET_SMEM>>>(gk, gv, gq, go1, nullptr,
                                                     0);
    retention_kernel<<<WW * NHEADS, 256, RET_SMEM>>>(gk, gv, go1, nullptr,
                                                     o2f, 1);

    // output projection (fp16, K=1024)
    dim3 g1(E_DIM / 128, MROWS / 128, 1);
    out_mma_kernel<<<g1, 256, SMEM_TOTAL>>>(o2f, w4 + 3 * WSZ, bo, out);
}

// round 15
// speedup vs baseline: 2.7842x; 1.0295x over previous
#include <cuda_runtime.h>
#include <cuda_bf16.h>
#include <cuda_fp16.h>
#include <cstdint>

#define E_DIM 1024
#define NHEADS 16
#define DH 64
#define HH 128
#define WW 128
#define MROWS (HH * WW)              /* 16384 */
#define HWD ((size_t)MROWS * DH)

#define BK 64
#define NCH (E_DIM / BK)              /* 16 */
#define ROWP 72                       /* padded row (elems), 144B */
#define TILE_ROWS 128
#define STAGE_HALF (TILE_ROWS * ROWP)
#define STAGE_BYTES (2 * STAGE_HALF * 2)   /* 36864 */
#define SMEM_TOTAL (2 * STAGE_BYTES)       /* 73728 */

/* retention smem layout (dynamic, bytes) */
#define RLD 72                        /* bf16 row pitch (144B) */
#define R_KBH 0
#define R_KBL 18432
#define R_VBH 36864
#define R_VBL 55296
#define R_KVH 0
#define R_KVL 9216
#define R_QSH 18432
#define R_QSL 36864
#define RET_SMEM 73728

// ---------------- scratch (static device arrays; no allocation) ----------------
__device__ __half g_af[(size_t)MROWS * E_DIM];            // fp16 cast of x
__device__ __half g_w4[4][(size_t)E_DIM * E_DIM];         // fp16 casts q,k,v,o
__device__ __half g_o2f[(size_t)MROWS * E_DIM];           // fp16 of o2
__device__ __half g_qh[(size_t)NHEADS * MROWS * DH];
__device__ __half g_kh[(size_t)NHEADS * MROWS * DH];
__device__ __half g_vh[(size_t)NHEADS * MROWS * DH];
__device__ __half g_o1h[(size_t)NHEADS * MROWS * DH];

// ======================= helpers =======================
__device__ __forceinline__ uint32_t smem_u32(const void* p) {
    uint32_t a;
    asm("{ .reg .u64 t; cvta.to.shared.u64 t, %1; cvt.u32.u64 %0, t; }"
        : "=r"(a) : "l"(p));
    return a;
}

__device__ __forceinline__ void cp_async16(uint32_t dst, const void* src) {
    asm volatile("cp.async.cg.shared.global [%0], [%1], 16;\n"
                 :: "r"(dst), "l"(src) : "memory");
}

template <int N>
__device__ __forceinline__ void cp_wait() {
    asm volatile("cp.async.wait_group %0;\n" :: "n"(N) : "memory");
}

__device__ __forceinline__ void ldm_x4(uint32_t* r, uint32_t addr) {
    asm volatile(
        "ldmatrix.sync.aligned.m8n8.x4.shared.b16 {%0,%1,%2,%3}, [%4];"
        : "=r"(r[0]), "=r"(r[1]), "=r"(r[2]), "=r"(r[3]) : "r"(addr));
}

__device__ __forceinline__ void ldm_x4t(uint32_t* r, uint32_t addr) {
    asm volatile(
        "ldmatrix.sync.aligned.m8n8.x4.trans.shared.b16 {%0,%1,%2,%3}, [%4];"
        : "=r"(r[0]), "=r"(r[1]), "=r"(r[2]), "=r"(r[3]) : "r"(addr));
}

__device__ __forceinline__ void mma_bf16(float* c, const uint32_t* a,
                                         const uint32_t* b) {
    asm volatile(
        "mma.sync.aligned.m16n8k16.row.col.f32.bf16.bf16.f32 "
        "{%0,%1,%2,%3}, {%4,%5,%6,%7}, {%8,%9}, {%0,%1,%2,%3};"
        : "+f"(c[0]), "+f"(c[1]), "+f"(c[2]), "+f"(c[3])
        : "r"(a[0]), "r"(a[1]), "r"(a[2]), "r"(a[3]), "r"(b[0]), "r"(b[1]));
}

__device__ __forceinline__ void mma_fp16(float* c, const uint32_t* a,
                                         const uint32_t* b) {
    asm volatile(
        "mma.sync.aligned.m16n8k16.row.col.f32.f16.f16.f32 "
        "{%0,%1,%2,%3}, {%4,%5,%6,%7}, {%8,%9}, {%0,%1,%2,%3};"
        : "+f"(c[0]), "+f"(c[1]), "+f"(c[2]), "+f"(c[3])
        : "r"(a[0]), "r"(a[1]), "r"(a[2]), "r"(a[3]), "r"(b[0]), "r"(b[1]));
}

__device__ __forceinline__ __nv_bfloat162 split_hi2(float a, float b,
                                                    float& ra, float& rb) {
    __nv_bfloat16 ha = __float2bfloat16(a);
    __nv_bfloat16 hb = __float2bfloat16(b);
    ra = a - __bfloat162float(ha);
    rb = b - __bfloat162float(hb);
    return __nv_bfloat162(ha, hb);
}

// ======================= fp16 HMMA GEMM (proven config, K=1024) =============
// D[m,n] = sum_{k<E_DIM} A[m,k] * B[n,k] + bias[n]
// CTA 128x128, 256 threads (8 warps: 4m x 2n), warp tile 32x64.
// HEADLAYOUT=1 -> fp16 head-layout output; else fp32 row-major output.
template <int HEADLAYOUT>
__device__ __forceinline__ void mma_gemm_body(
    const __half* __restrict__ A2, const __half* __restrict__ B2,
    const float* __restrict__ bias, void* __restrict__ outv, bool relu) {
    extern __shared__ char smem[];
    const int tid = threadIdx.x;
    const int wid = tid >> 5;
    const int lane = tid & 31;
    const int wm = wid & 3;
    const int wn = wid >> 2;
    const int m0 = blockIdx.y * 128;
    const int n0 = blockIdx.x * 128;

    float acc[2][8][4];
#pragma unroll
    for (int i = 0; i < 2; i++)
#pragma unroll
        for (int j = 0; j < 8; j++)
#pragma unroll
            for (int c = 0; c < 4; c++) acc[i][j][c] = 0.f;

    auto stA = [&](int s) {
        return reinterpret_cast<__half*>(smem + s * STAGE_BYTES);
    };
    auto stB = [&](int s) {
        return reinterpret_cast<__half*>(smem + s * STAGE_BYTES) + STAGE_HALF;
    };

    auto load_chunk = [&](int s, int k0) {
        __half* a = stA(s);
        __half* b = stB(s);
#pragma unroll
        for (int i = 0; i < 4; i++) {
            int c = tid + i * 256;
            int row = c >> 3;
            int seg = (c & 7) * 8;
            cp_async16(smem_u32(a + row * ROWP + seg),
                       A2 + (size_t)(m0 + row) * E_DIM + k0 + seg);
            cp_async16(smem_u32(b + row * ROWP + seg),
                       B2 + (size_t)(n0 + row) * E_DIM + k0 + seg);
        }
        asm volatile("cp.async.commit_group;\n" ::: "memory");
    };

    load_chunk(0, 0);

    const int a_row = lane & 15;
    const int a_c8 = (lane >> 4) * 8;
    const int b_row = (lane & 7) | ((lane & 16) >> 1);
    const int b_c8 = ((lane >> 3) & 1) * 8;

    for (int ch = 0; ch < NCH; ch++) {
        if (ch + 1 < NCH) {
            load_chunk((ch + 1) & 1, (ch + 1) * BK);
            cp_wait<1>();
        } else {
            cp_wait<0>();
        }
        __syncthreads();

        const int buf = ch & 1;
        const uint32_t sbA = smem_u32(stA(buf));
        const uint32_t sbB = smem_u32(stB(buf));

#pragma unroll
        for (int kk = 0; kk < 4; kk++) {
            uint32_t a[2][4], b[8][2];
#pragma unroll
            for (int mt = 0; mt < 2; mt++) {
                uint32_t addr = sbA +
                    2 * ((32 * wm + 16 * mt + a_row) * ROWP + kk * 16 + a_c8);
                ldm_x4(a[mt], addr);
            }
#pragma unroll
            for (int np = 0; np < 4; np++) {
                uint32_t r[4];
                uint32_t addr = sbB +
                    2 * ((64 * wn + 16 * np + b_row) * ROWP + kk * 16 + b_c8);
                ldm_x4(r, addr);
                b[np * 2][0] = r[0]; b[np * 2][1] = r[1];
                b[np * 2 + 1][0] = r[2]; b[np * 2 + 1][1] = r[3];
            }
#pragma unroll
            for (int mt = 0; mt < 2; mt++)
#pragma unroll
                for (int nt = 0; nt < 8; nt++)
                    mma_fp16(acc[mt][nt], a[mt], b[nt]);
        }
        __syncthreads();
    }

    const int g = lane >> 2;
    const int tq = lane & 3;
#pragma unroll
    for (int nt = 0; nt < 8; nt++) {
        const int n = n0 + 64 * wn + 8 * nt + 2 * tq;
        const float b0 = __ldg(bias + n);
        const float b1 = __ldg(bias + n + 1);
#pragma unroll
        for (int mt = 0; mt < 2; mt++) {
            const int mbase = m0 + 32 * wm + 16 * mt + g;
#pragma unroll
            for (int half = 0; half < 2; half++) {
                const int m = mbase + half * 8;
                float v0 = acc[mt][nt][half * 2] + b0;
                float v1 = acc[mt][nt][half * 2 + 1] + b1;
                if (relu) { v0 = fmaxf(v0, 0.f); v1 = fmaxf(v1, 0.f); }
                if (HEADLAYOUT) {
                    __half* out = reinterpret_cast<__half*>(outv);
                    *reinterpret_cast<__half2*>(
                        out + (size_t)(n >> 6) * HWD + (size_t)m * 64 +
                        (n & 63)) =
                        __half2(__float2half(v0), __float2half(v1));
                } else {
                    float* out = reinterpret_cast<float*>(outv);
                    *reinterpret_cast<float2*>(out + (size_t)m * E_DIM + n) =
                        make_float2(v0, v1);
                }
            }
        }
    }
}

__global__ __launch_bounds__(256, 2) void qkv_mma_kernel(
    const __half* __restrict__ af, const __half* __restrict__ w4,
    const float* __restrict__ bq, const float* __restrict__ bk,
    const float* __restrict__ bv, __half* gq, __half* gk, __half* gv) {
    const size_t WSZ = (size_t)E_DIM * E_DIM;
    const __half* B = w4 + (size_t)blockIdx.z * WSZ;
    const float* bias;
    __half* outp;
    bool relu;
    if (blockIdx.z == 0) { bias = bq; outp = gq; relu = true; }
    else if (blockIdx.z == 1) { bias = bk; outp = gk; relu = true; }
    else { bias = bv; outp = gv; relu = false; }
    mma_gemm_body<1>(af, B, bias, outp, relu);
}

__global__ __launch_bounds__(256, 2) void out_mma_kernel(
    const __half* __restrict__ a2, const __half* __restrict__ b2,
    const float* __restrict__ bias, float* __restrict__ out) {
    mma_gemm_body<0>(a2, b2, bias, out, false);
}

// ======================= fp32 -> fp16 cast kernels =======================
__global__ __launch_bounds__(256) void cast_x_kernel(
    const float* __restrict__ in, __half* __restrict__ out) {
    int i = (blockIdx.x * 256 + threadIdx.x) * 4;
    float4 v = *reinterpret_cast<const float4*>(in + i);
    __half2* p = reinterpret_cast<__half2*>(out + i);
    p[0] = __half2(__float2half(v.x), __float2half(v.y));
    p[1] = __half2(__float2half(v.z), __float2half(v.w));
}

__global__ __launch_bounds__(256) void cast_w4_kernel(
    const float* __restrict__ w0, const float* __restrict__ w1,
    const float* __restrict__ w2, const float* __restrict__ w3,
    __half* __restrict__ out) {
    const float* w = (blockIdx.z == 0) ? w0
                     : (blockIdx.z == 1) ? w1
                     : (blockIdx.z == 2) ? w2 : w3;
    __half* o = out + (size_t)blockIdx.z * E_DIM * E_DIM;
    int i = (blockIdx.x * 256 + threadIdx.x) * 4;
    float4 v = *reinterpret_cast<const float4*>(w + i);
    __half2* p = reinterpret_cast<__half2*>(o + i);
    p[0] = __half2(__float2half(v.x), __float2half(v.y));
    p[1] = __half2(__float2half(v.z), __float2half(v.w));
}

// ======================= fused retention (HMMA, split-bf16; fp16 I/O) ======
__global__ __launch_bounds__(256, 2) void retention_kernel(
    const __half* __restrict__ kArr, const __half* __restrict__ vArr,
    const __half* __restrict__ cArr, __half* __restrict__ oH,
    __half* __restrict__ oCat, int mode) {
    extern __shared__ char rsm[];
    const int tid = threadIdx.x;
    const int wid = tid >> 5;
    const int lane = tid & 31;
    const int b = blockIdx.x;
    const int n = b & 15;
    const int idx = b >> 4;

    size_t base;
    int rs;
    if (mode == 0) {
        base = (size_t)n * HWD + (size_t)idx * (WW * DH);
        rs = DH;
    } else {
        base = (size_t)n * HWD + (size_t)idx * DH;
        rs = WW * DH;
    }
    const __half* kS = kArr + base;
    const __half* vS = vArr + base;
    const __half* cS = cArr + base;

    // fp16 source -> split-bf16 hi/lo (exact: 8+8 mantissa bits >= fp16's 11)
    auto conv = [&](const __half* src, __nv_bfloat16* dh, __nv_bfloat16* dl) {
#pragma unroll
        for (int i = 0; i < 8; i++) {
            int id = tid + i * 256;
            int w = id >> 4;
            int c = (id & 15) << 2;
            const __half2* sp =
                reinterpret_cast<const __half2*>(src + (size_t)w * rs + c);
            __half2 p0 = sp[0];
            __half2 p1 = sp[1];
            float f0 = __low2float(p0), f1 = __high2float(p0);
            float f2 = __low2float(p1), f3 = __high2float(p1);
            float r0, r1, r2, r3;
            __nv_bfloat162 h01 = split_hi2(f0, f1, r0, r1);
            __nv_bfloat162 h23 = split_hi2(f2, f3, r2, r3);
            *reinterpret_cast<__nv_bfloat162*>(dh + w * RLD + c) = h01;
            *reinterpret_cast<__nv_bfloat162*>(dh + w * RLD + c + 2) = h23;
            *reinterpret_cast<__nv_bfloat162*>(dl + w * RLD + c) =
                __nv_bfloat162(__float2bfloat16(r0), __float2bfloat16(r1));
            *reinterpret_cast<__nv_bfloat162*>(dl + w * RLD + c + 2) =
                __nv_bfloat162(__float2bfloat16(r2), __float2bfloat16(r3));
        }
    };
    conv(kS, reinterpret_cast<__nv_bfloat16*>(rsm + R_KBH),
         reinterpret_cast<__nv_bfloat16*>(rsm + R_KBL));
    conv(vS, reinterpret_cast<__nv_bfloat16*>(rsm + R_VBH),
         reinterpret_cast<__nv_bfloat16*>(rsm + R_VBL));
    __syncthreads();

    const uint32_t sb = smem_u32(rsm);
    const int g = lane >> 2;
    const int tq = lane & 3;

    // ---- phase A: kvT[e][d] (64x64) via trans ldmatrix ----
    const int e0 = (wid >> 1) * 16;
    const int d0 = (wid & 1) * 32;
    const int ta_row = (lane & 7) + ((lane >> 4) & 1) * 8;
    const int ta_col = ((lane >> 3) & 1) * 8;
    const int tb_row = (lane & 7) + ((lane >> 3) & 1) * 8;
    const int tb_col = ((lane >> 4) & 1) * 8;

    float acc1[4][4];
#pragma unroll
    for (int i = 0; i < 4; i++)
#pragma unroll
        for (int j = 0; j < 4; j++) acc1[i][j] = 0.f;

#pragma unroll
    for (int ks = 0; ks < 8; ks++) {
        const int k0 = ks * 16;
        uint32_t avh[4], avl[4];
        ldm_x4t(avh, sb + R_VBH + 2 * ((k0 + ta_row) * RLD + e0 + ta_col));
        ldm_x4t(avl, sb + R_VBL + 2 * ((k0 + ta_row) * RLD + e0 + ta_col));
        uint32_t bh[2][4], bl[2][4];
#pragma unroll
        for (int nq = 0; nq < 2; nq++) {
            ldm_x4t(bh[nq], sb + R_KBH +
                    2 * ((k0 + tb_row) * RLD + d0 + nq * 16 + tb_col));
            ldm_x4t(bl[nq], sb + R_KBL +
                    2 * ((k0 + tb_row) * RLD + d0 + nq * 16 + tb_col));
        }
#pragma unroll
        for (int nq = 0; nq < 2; nq++)
#pragma unroll
            for (int p = 0; p < 2; p++) {
                const int nt = nq * 2 + p;
                uint32_t bfh[2] = {bh[nq][2 * p], bh[nq][2 * p + 1]};
                uint32_t bfl[2] = {bl[nq][2 * p], bl[nq][2 * p + 1]};
                mma_bf16(acc1[nt], avh, bfh);
                mma_bf16(acc1[nt], avh, bfl);
                mma_bf16(acc1[nt], avl, bfh);
            }
    }
    __syncthreads();

    {
        __nv_bfloat16* kvh = reinterpret_cast<__nv_bfloat16*>(rsm + R_KVH);
        __nv_bfloat16* kvl = reinterpret_cast<__nv_bfloat16*>(rsm + R_KVL);
#pragma unroll
        for (int nt = 0; nt < 4; nt++)
#pragma unroll
            for (int half = 0; half < 2; half++) {
                const int e = e0 + g + half * 8;
                const int d = d0 + nt * 8 + 2 * tq;
                float r0, r1;
                __nv_bfloat162 hp = split_hi2(acc1[nt][half * 2],
                                              acc1[nt][half * 2 + 1], r0, r1);
                *reinterpret_cast<__nv_bfloat162*>(kvh + e * RLD + d) = hp;
                *reinterpret_cast<__nv_bfloat162*>(kvl + e * RLD + d) =
                    __nv_bfloat162(__float2bfloat16(r0), __float2bfloat16(r1));
            }
    }
    conv(cS, reinterpret_cast<__nv_bfloat16*>(rsm + R_QSH),
         reinterpret_cast<__nv_bfloat16*>(rsm + R_QSL));
    __syncthreads();

    // ---- phase B: out[r][e] (128x64) ----
    const int r0 = wid * 16;
    const int a_row = lane & 15;
    const int a_c8 = (lane >> 4) * 8;
    const int b_row = (lane & 7) | ((lane & 16) >> 1);
    const int b_c8 = ((lane >> 3) & 1) * 8;

    float acc2[8][4];
#pragma unroll
    for (int i = 0; i < 8; i++)
#pragma unroll
        for (int j = 0; j < 4; j++) acc2[i][j] = 0.f;

#pragma unroll
    for (int ks = 0; ks < 4; ks++) {
        const int k0 = ks * 16;
        uint32_t aqh[4], aql[4];
        ldm_x4(aqh, sb + R_QSH + 2 * ((r0 + a_row) * RLD + k0 + a_c8));
        ldm_x4(aql, sb + R_QSL + 2 * ((r0 + a_row) * RLD + k0 + a_c8));
        uint32_t kh[4][4], kl[4][4];
#pragma unroll
        for (int nq = 0; nq < 4; nq++) {
            ldm_x4(kh[nq], sb + R_KVH +
                   2 * ((nq * 16 + b_row) * RLD + k0 + b_c8));
            ldm_x4(kl[nq], sb + R_KVL +
                   2 * ((nq * 16 + b_row) * RLD + k0 + b_c8));
        }
#pragma unroll
        for (int nt = 0; nt < 8; nt++) {
            const int nq = nt >> 1;
            const int p = nt & 1;
            uint32_t bfh[2] = {kh[nq][2 * p], kh[nq][2 * p + 1]};
            uint32_t bfl[2] = {kl[nq][2 * p], kl[nq][2 * p + 1]};
            mma_bf16(acc2[nt], aqh, bfh);
            mma_bf16(acc2[nt], aqh, bfl);
            mma_bf16(acc2[nt], aql, bfh);
        }
    }

#pragma unroll
    for (int nt = 0; nt < 8; nt++) {
        const int e = nt * 8 + 2 * tq;
#pragma unroll
        for (int half = 0; half < 2; half++) {
            const int r = r0 + g + half * 8;
            float v0 = acc2[nt][half * 2];
            float v1 = acc2[nt][half * 2 + 1];
            __half2 hv(__float2half(v0), __float2half(v1));
            if (mode == 0) {
                *reinterpret_cast<__half2*>(oH + base + (size_t)r * DH + e) =
                    hv;
            } else {
                const int m = r * WW + idx;
                *reinterpret_cast<__half2*>(oCat + (size_t)m * E_DIM +
                                            n * DH + e) = hv;
            }
        }
    }
}

// =======================================================================
extern "C" void kernel_launch(void* const* d_in, const int* in_sizes, int n_in,
                              void* d_out, int out_size) {
    const float* x  = (const float*)d_in[0];
    const float* Wq = (const float*)d_in[1];
    const float* bq = (const float*)d_in[2];
    const float* Wk = (const float*)d_in[3];
    const float* bk = (const float*)d_in[4];
    const float* Wv = (const float*)d_in[5];
    const float* bv = (const float*)d_in[6];
    const float* Wo = (const float*)d_in[7];
    const float* bo = (const float*)d_in[8];
    float* out = (float*)d_out;

    __half *af, *w4, *o2f, *gq, *gk, *gv, *go1;
    cudaGetSymbolAddress((void**)&af, g_af);
    cudaGetSymbolAddress((void**)&w4, g_w4);
    cudaGetSymbolAddress((void**)&o2f, g_o2f);
    cudaGetSymbolAddress((void**)&gq, g_qh);
    cudaGetSymbolAddress((void**)&gk, g_kh);
    cudaGetSymbolAddress((void**)&gv, g_vh);
    cudaGetSymbolAddress((void**)&go1, g_o1h);

    const int WTOT = E_DIM * E_DIM;
    const size_t WSZ = (size_t)E_DIM * E_DIM;

    cudaFuncSetAttribute(qkv_mma_kernel,
                         cudaFuncAttributeMaxDynamicSharedMemorySize,
                         SMEM_TOTAL);
    cudaFuncSetAttribute(out_mma_kernel,
                         cudaFuncAttributeMaxDynamicSharedMemorySize,
                         SMEM_TOTAL);
    cudaFuncSetAttribute(retention_kernel,
                         cudaFuncAttributeMaxDynamicSharedMemorySize,
                         RET_SMEM);

    // casts
    int nx = MROWS * E_DIM;
    cast_x_kernel<<<nx / 1024, 256>>>(x, af);
    dim3 gcw(WTOT / 1024, 1, 4);
    cast_w4_kernel<<<gcw, 256>>>(Wq, Wk, Wv, Wo, w4);

    // q/k/v projections (fp16, K=1024) -> fp16 head-layout outputs
    dim3 gqkv(E_DIM / 128, MROWS / 128, 3);
    qkv_mma_kernel<<<gqkv, 256, SMEM_TOTAL>>>(af, w4, bq, bk, bv, gq, gk, gv);

    // retention (fp16 I/O, split-bf16 internals)
    retention_kernel<<<HH * NHEADS, 256, RET_SMEM>>>(gk, gv, gq, go1, nullptr,
                                                     0);
    retention_kernel<<<WW * NHEADS, 256, RET_SMEM>>>(gk, gv, go1, nullptr,
                                                     o2f, 1);

    // output projection (fp16, K=1024) -> fp32
    dim3 g1(E_DIM / 128, MROWS / 128, 1);
    out_mma_kernel<<<g1, 256, SMEM_TOTAL>>>(o2f, w4 + 3 * WSZ, bo, out);
}

// round 16
// speedup vs baseline: 2.9793x; 1.0701x over previous
#include <cuda_runtime.h>
#include <cuda_bf16.h>
#include <cuda_fp16.h>
#include <cstdint>

#define E_DIM 1024
#define NHEADS 16
#define DH 64
#define HH 128
#define WW 128
#define MROWS (HH * WW)              /* 16384 */
#define HWD ((size_t)MROWS * DH)

#define BK 64
#define NCH (E_DIM / BK)              /* 16 */
#define ROWP 72                       /* padded row (elems), 144B */
#define TILE_ROWS 128
#define STAGE_HALF (TILE_ROWS * ROWP)
#define STAGE_BYTES (2 * STAGE_HALF * 2)   /* 36864 */
#define SMEM_TOTAL (2 * STAGE_BYTES)       /* 73728 */

/* retention smem layout (dynamic, bytes); all fp16, row pitch RLD halves */
#define RLD 72
#define R_K 0            /* 128 x RLD fp16 = 18432 B */
#define R_V 18432
#define R_Q 36864
#define R_KVH 55296      /* 64 x RLD fp16 = 9216 B */
#define R_KVL 64512
#define RET_SMEM 73728

// ---------------- scratch (static device arrays; no allocation) ----------------
__device__ __half g_af[(size_t)MROWS * E_DIM];            // fp16 cast of x
__device__ __half g_w4[4][(size_t)E_DIM * E_DIM];         // fp16 casts q,k,v,o
__device__ __half g_o2f[(size_t)MROWS * E_DIM];           // fp16 of o2
__device__ __half g_qh[(size_t)NHEADS * MROWS * DH];
__device__ __half g_kh[(size_t)NHEADS * MROWS * DH];
__device__ __half g_vh[(size_t)NHEADS * MROWS * DH];
__device__ __half g_o1h[(size_t)NHEADS * MROWS * DH];

// ======================= helpers =======================
__device__ __forceinline__ uint32_t smem_u32(const void* p) {
    uint32_t a;
    asm("{ .reg .u64 t; cvta.to.shared.u64 t, %1; cvt.u32.u64 %0, t; }"
        : "=r"(a) : "l"(p));
    return a;
}

__device__ __forceinline__ void cp_async16(uint32_t dst, const void* src) {
    asm volatile("cp.async.cg.shared.global [%0], [%1], 16;\n"
                 :: "r"(dst), "l"(src) : "memory");
}

template <int N>
__device__ __forceinline__ void cp_wait() {
    asm volatile("cp.async.wait_group %0;\n" :: "n"(N) : "memory");
}

__device__ __forceinline__ void ldm_x4(uint32_t* r, uint32_t addr) {
    asm volatile(
        "ldmatrix.sync.aligned.m8n8.x4.shared.b16 {%0,%1,%2,%3}, [%4];"
        : "=r"(r[0]), "=r"(r[1]), "=r"(r[2]), "=r"(r[3]) : "r"(addr));
}

__device__ __forceinline__ void ldm_x4t(uint32_t* r, uint32_t addr) {
    asm volatile(
        "ldmatrix.sync.aligned.m8n8.x4.trans.shared.b16 {%0,%1,%2,%3}, [%4];"
        : "=r"(r[0]), "=r"(r[1]), "=r"(r[2]), "=r"(r[3]) : "r"(addr));
}

__device__ __forceinline__ void mma_fp16(float* c, const uint32_t* a,
                                         const uint32_t* b) {
    asm volatile(
        "mma.sync.aligned.m16n8k16.row.col.f32.f16.f16.f32 "
        "{%0,%1,%2,%3}, {%4,%5,%6,%7}, {%8,%9}, {%0,%1,%2,%3};"
        : "+f"(c[0]), "+f"(c[1]), "+f"(c[2]), "+f"(c[3])
        : "r"(a[0]), "r"(a[1]), "r"(a[2]), "r"(a[3]), "r"(b[0]), "r"(b[1]));
}

// ======================= fp16 HMMA GEMM (proven config, K=1024) =============
template <int HEADLAYOUT>
__device__ __forceinline__ void mma_gemm_body(
    const __half* __restrict__ A2, const __half* __restrict__ B2,
    const float* __restrict__ bias, void* __restrict__ outv, bool relu) {
    extern __shared__ char smem[];
    const int tid = threadIdx.x;
    const int wid = tid >> 5;
    const int lane = tid & 31;
    const int wm = wid & 3;
    const int wn = wid >> 2;
    const int m0 = blockIdx.y * 128;
    const int n0 = blockIdx.x * 128;

    float acc[2][8][4];
#pragma unroll
    for (int i = 0; i < 2; i++)
#pragma unroll
        for (int j = 0; j < 8; j++)
#pragma unroll
            for (int c = 0; c < 4; c++) acc[i][j][c] = 0.f;

    auto stA = [&](int s) {
        return reinterpret_cast<__half*>(smem + s * STAGE_BYTES);
    };
    auto stB = [&](int s) {
        return reinterpret_cast<__half*>(smem + s * STAGE_BYTES) + STAGE_HALF;
    };

    auto load_chunk = [&](int s, int k0) {
        __half* a = stA(s);
        __half* b = stB(s);
#pragma unroll
        for (int i = 0; i < 4; i++) {
            int c = tid + i * 256;
            int row = c >> 3;
            int seg = (c & 7) * 8;
            cp_async16(smem_u32(a + row * ROWP + seg),
                       A2 + (size_t)(m0 + row) * E_DIM + k0 + seg);
            cp_async16(smem_u32(b + row * ROWP + seg),
                       B2 + (size_t)(n0 + row) * E_DIM + k0 + seg);
        }
        asm volatile("cp.async.commit_group;\n" ::: "memory");
    };

    load_chunk(0, 0);

    const int a_row = lane & 15;
    const int a_c8 = (lane >> 4) * 8;
    const int b_row = (lane & 7) | ((lane & 16) >> 1);
    const int b_c8 = ((lane >> 3) & 1) * 8;

    for (int ch = 0; ch < NCH; ch++) {
        if (ch + 1 < NCH) {
            load_chunk((ch + 1) & 1, (ch + 1) * BK);
            cp_wait<1>();
        } else {
            cp_wait<0>();
        }
        __syncthreads();

        const int buf = ch & 1;
        const uint32_t sbA = smem_u32(stA(buf));
        const uint32_t sbB = smem_u32(stB(buf));

#pragma unroll
        for (int kk = 0; kk < 4; kk++) {
            uint32_t a[2][4], b[8][2];
#pragma unroll
            for (int mt = 0; mt < 2; mt++) {
                uint32_t addr = sbA +
                    2 * ((32 * wm + 16 * mt + a_row) * ROWP + kk * 16 + a_c8);
                ldm_x4(a[mt], addr);
            }
#pragma unroll
            for (int np = 0; np < 4; np++) {
                uint32_t r[4];
                uint32_t addr = sbB +
                    2 * ((64 * wn + 16 * np + b_row) * ROWP + kk * 16 + b_c8);
                ldm_x4(r, addr);
                b[np * 2][0] = r[0]; b[np * 2][1] = r[1];
                b[np * 2 + 1][0] = r[2]; b[np * 2 + 1][1] = r[3];
            }
#pragma unroll
            for (int mt = 0; mt < 2; mt++)
#pragma unroll
                for (int nt = 0; nt < 8; nt++)
                    mma_fp16(acc[mt][nt], a[mt], b[nt]);
        }
        __syncthreads();
    }

    const int g = lane >> 2;
    const int tq = lane & 3;
#pragma unroll
    for (int nt = 0; nt < 8; nt++) {
        const int n = n0 + 64 * wn + 8 * nt + 2 * tq;
        const float b0 = __ldg(bias + n);
        const float b1 = __ldg(bias + n + 1);
#pragma unroll
        for (int mt = 0; mt < 2; mt++) {
            const int mbase = m0 + 32 * wm + 16 * mt + g;
#pragma unroll
            for (int half = 0; half < 2; half++) {
                const int m = mbase + half * 8;
                float v0 = acc[mt][nt][half * 2] + b0;
                float v1 = acc[mt][nt][half * 2 + 1] + b1;
                if (relu) { v0 = fmaxf(v0, 0.f); v1 = fmaxf(v1, 0.f); }
                if (HEADLAYOUT) {
                    __half* out = reinterpret_cast<__half*>(outv);
                    *reinterpret_cast<__half2*>(
                        out + (size_t)(n >> 6) * HWD + (size_t)m * 64 +
                        (n & 63)) =
                        __half2(__float2half(v0), __float2half(v1));
                } else {
                    float* out = reinterpret_cast<float*>(outv);
                    *reinterpret_cast<float2*>(out + (size_t)m * E_DIM + n) =
                        make_float2(v0, v1);
                }
            }
        }
    }
}

__global__ __launch_bounds__(256, 2) void qkv_mma_kernel(
    const __half* __restrict__ af, const __half* __restrict__ w4,
    const float* __restrict__ bq, const float* __restrict__ bk,
    const float* __restrict__ bv, __half* gq, __half* gk, __half* gv) {
    const size_t WSZ = (size_t)E_DIM * E_DIM;
    const __half* B = w4 + (size_t)blockIdx.z * WSZ;
    const float* bias;
    __half* outp;
    bool relu;
    if (blockIdx.z == 0) { bias = bq; outp = gq; relu = true; }
    else if (blockIdx.z == 1) { bias = bk; outp = gk; relu = true; }
    else { bias = bv; outp = gv; relu = false; }
    mma_gemm_body<1>(af, B, bias, outp, relu);
}

__global__ __launch_bounds__(256, 2) void out_mma_kernel(
    const __half* __restrict__ a2, const __half* __restrict__ b2,
    const float* __restrict__ bias, float* __restrict__ out) {
    mma_gemm_body<0>(a2, b2, bias, out, false);
}

// ======================= fp32 -> fp16 cast kernels =======================
__global__ __launch_bounds__(256) void cast_x_kernel(
    const float* __restrict__ in, __half* __restrict__ out) {
    int i = (blockIdx.x * 256 + threadIdx.x) * 4;
    float4 v = *reinterpret_cast<const float4*>(in + i);
    __half2* p = reinterpret_cast<__half2*>(out + i);
    p[0] = __half2(__float2half(v.x), __float2half(v.y));
    p[1] = __half2(__float2half(v.z), __float2half(v.w));
}

__global__ __launch_bounds__(256) void cast_w4_kernel(
    const float* __restrict__ w0, const float* __restrict__ w1,
    const float* __restrict__ w2, const float* __restrict__ w3,
    __half* __restrict__ out) {
    const float* w = (blockIdx.z == 0) ? w0
                     : (blockIdx.z == 1) ? w1
                     : (blockIdx.z == 2) ? w2 : w3;
    __half* o = out + (size_t)blockIdx.z * E_DIM * E_DIM;
    int i = (blockIdx.x * 256 + threadIdx.x) * 4;
    float4 v = *reinterpret_cast<const float4*>(w + i);
    __half2* p = reinterpret_cast<__half2*>(o + i);
    p[0] = __half2(__float2half(v.x), __float2half(v.y));
    p[1] = __half2(__float2half(v.z), __float2half(v.w));
}

// ======================= fused retention (native fp16 HMMA) =================
// Phase A: kvT[e][d] = sum_w v[w][e]*k[w][d]  (fp16 MMA, exact inputs)
// kv staged as split-fp16 hi+lo (2^-21 relative).
// Phase B: out[r][e] = q[r]*kvh + q[r]*kvl  (2 MMAs, q exact).
__global__ __launch_bounds__(256, 2) void retention_kernel(
    const __half* __restrict__ kArr, const __half* __restrict__ vArr,
    const __half* __restrict__ cArr, __half* __restrict__ oH,
    __half* __restrict__ oCat, int mode) {
    extern __shared__ char rsm[];
    const int tid = threadIdx.x;
    const int wid = tid >> 5;
    const int lane = tid & 31;
    const int b = blockIdx.x;
    const int n = b & 15;
    const int idx = b >> 4;

    size_t base;
    int rs;
    if (mode == 0) {
        base = (size_t)n * HWD + (size_t)idx * (WW * DH);
        rs = DH;
    } else {
        base = (size_t)n * HWD + (size_t)idx * DH;
        rs = WW * DH;
    }
    const __half* kS = kArr + base;
    const __half* vS = vArr + base;
    const __half* cS = cArr + base;

    // ---- async load k, v, q tiles (128 x 64 fp16 each; 8 cp16 per row) ----
    auto load_tile = [&](uint32_t dstOff, const __half* src) {
#pragma unroll
        for (int i = 0; i < 4; i++) {
            int c = tid + i * 256;        // 0..1023
            int row = c >> 3;
            int seg = (c & 7) * 8;        // halves
            cp_async16(smem_u32(rsm + dstOff + 2 * (row * RLD + seg)),
                       src + (size_t)row * rs + seg);
        }
    };
    load_tile(R_K, kS);
    load_tile(R_V, vS);
    load_tile(R_Q, cS);
    asm volatile("cp.async.commit_group;\n" ::: "memory");
    cp_wait<0>();
    __syncthreads();

    const uint32_t sb = smem_u32(rsm);
    const int g = lane >> 2;
    const int tq = lane & 3;

    // ---- phase A: kvT[e][d] (64x64) via trans ldmatrix, fp16 MMA ----
    const int e0 = (wid >> 1) * 16;
    const int d0 = (wid & 1) * 32;
    const int ta_row = (lane & 7) + ((lane >> 4) & 1) * 8;
    const int ta_col = ((lane >> 3) & 1) * 8;
    const int tb_row = (lane & 7) + ((lane >> 3) & 1) * 8;
    const int tb_col = ((lane >> 4) & 1) * 8;

    float acc1[4][4];
#pragma unroll
    for (int i = 0; i < 4; i++)
#pragma unroll
        for (int j = 0; j < 4; j++) acc1[i][j] = 0.f;

#pragma unroll
    for (int ks = 0; ks < 8; ks++) {
        const int k0 = ks * 16;
        uint32_t av[4];
        ldm_x4t(av, sb + R_V + 2 * ((k0 + ta_row) * RLD + e0 + ta_col));
        uint32_t bk_[2][4];
#pragma unroll
        for (int nq = 0; nq < 2; nq++)
            ldm_x4t(bk_[nq], sb + R_K +
                    2 * ((k0 + tb_row) * RLD + d0 + nq * 16 + tb_col));
#pragma unroll
        for (int nq = 0; nq < 2; nq++)
#pragma unroll
            for (int p = 0; p < 2; p++) {
                uint32_t bf[2] = {bk_[nq][2 * p], bk_[nq][2 * p + 1]};
                mma_fp16(acc1[nq * 2 + p], av, bf);
            }
    }
    __syncthreads();  // everyone done reading K/V region? (KV region separate,
                      // but ensures kv writes ordered before phase-B reads)

    // ---- stage kv as split-fp16 hi/lo ----
    {
        __half* kvh = reinterpret_cast<__half*>(rsm + R_KVH);
        __half* kvl = reinterpret_cast<__half*>(rsm + R_KVL);
#pragma unroll
        for (int nt = 0; nt < 4; nt++)
#pragma unroll
            for (int half = 0; half < 2; half++) {
                const int e = e0 + g + half * 8;
                const int d = d0 + nt * 8 + 2 * tq;
                float f0 = acc1[nt][half * 2];
                float f1 = acc1[nt][half * 2 + 1];
                __half h0 = __float2half(f0), h1 = __float2half(f1);
                float l0 = f0 - __half2float(h0);
                float l1 = f1 - __half2float(h1);
                *reinterpret_cast<__half2*>(kvh + e * RLD + d) = __half2(h0, h1);
                *reinterpret_cast<__half2*>(kvl + e * RLD + d) =
                    __half2(__float2half(l0), __float2half(l1));
            }
    }
    __syncthreads();

    // ---- phase B: out[r][e] (128x64) ----
    const int r0 = wid * 16;
    const int a_row = lane & 15;
    const int a_c8 = (lane >> 4) * 8;
    const int b_row = (lane & 7) | ((lane & 16) >> 1);
    const int b_c8 = ((lane >> 3) & 1) * 8;

    float acc2[8][4];
#pragma unroll
    for (int i = 0; i < 8; i++)
#pragma unroll
        for (int j = 0; j < 4; j++) acc2[i][j] = 0.f;

#pragma unroll
    for (int ks = 0; ks < 4; ks++) {
        const int k0 = ks * 16;
        uint32_t aq[4];
        ldm_x4(aq, sb + R_Q + 2 * ((r0 + a_row) * RLD + k0 + a_c8));
        uint32_t kh[4][4], kl[4][4];
#pragma unroll
        for (int nq = 0; nq < 4; nq++) {
            ldm_x4(kh[nq], sb + R_KVH +
                   2 * ((nq * 16 + b_row) * RLD + k0 + b_c8));
            ldm_x4(kl[nq], sb + R_KVL +
                   2 * ((nq * 16 + b_row) * RLD + k0 + b_c8));
        }
#pragma unroll
        for (int nt = 0; nt < 8; nt++) {
            const int nq = nt >> 1;
            const int p = nt & 1;
            uint32_t bfh[2] = {kh[nq][2 * p], kh[nq][2 * p + 1]};
            uint32_t bfl[2] = {kl[nq][2 * p], kl[nq][2 * p + 1]};
            mma_fp16(acc2[nt], aq, bfh);
            mma_fp16(acc2[nt], aq, bfl);
        }
    }

#pragma unroll
    for (int nt = 0; nt < 8; nt++) {
        const int e = nt * 8 + 2 * tq;
#pragma unroll
        for (int half = 0; half < 2; half++) {
            const int r = r0 + g + half * 8;
            float v0 = acc2[nt][half * 2];
            float v1 = acc2[nt][half * 2 + 1];
            __half2 hv(__float2half(v0), __float2half(v1));
            if (mode == 0) {
                *reinterpret_cast<__half2*>(oH + base + (size_t)r * DH + e) =
                    hv;
            } else {
                const int m = r * WW + idx;
                *reinterpret_cast<__half2*>(oCat + (size_t)m * E_DIM +
                                            n * DH + e) = hv;
            }
        }
    }
}

// =======================================================================
extern "C" void kernel_launch(void* const* d_in, const int* in_sizes, int n_in,
                              void* d_out, int out_size) {
    const float* x  = (const float*)d_in[0];
    const float* Wq = (const float*)d_in[1];
    const float* bq = (const float*)d_in[2];
    const float* Wk = (const float*)d_in[3];
    const float* bk = (const float*)d_in[4];
    const float* Wv = (const float*)d_in[5];
    const float* bv = (const float*)d_in[6];
    const float* Wo = (const float*)d_in[7];
    const float* bo = (const float*)d_in[8];
    float* out = (float*)d_out;

    __half *af, *w4, *o2f, *gq, *gk, *gv, *go1;
    cudaGetSymbolAddress((void**)&af, g_af);
    cudaGetSymbolAddress((void**)&w4, g_w4);
    cudaGetSymbolAddress((void**)&o2f, g_o2f);
    cudaGetSymbolAddress((void**)&gq, g_qh);
    cudaGetSymbolAddress((void**)&gk, g_kh);
    cudaGetSymbolAddress((void**)&gv, g_vh);
    cudaGetSymbolAddress((void**)&go1, g_o1h);

    const int WTOT = E_DIM * E_DIM;
    const size_t WSZ = (size_t)E_DIM * E_DIM;

    cudaFuncSetAttribute(qkv_mma_kernel,
                         cudaFuncAttributeMaxDynamicSharedMemorySize,
                         SMEM_TOTAL);
    cudaFuncSetAttribute(out_mma_kernel,
                         cudaFuncAttributeMaxDynamicSharedMemorySize,
                         SMEM_TOTAL);
    cudaFuncSetAttribute(retention_kernel,
                         cudaFuncAttributeMaxDynamicSharedMemorySize,
                         RET_SMEM);

    // casts
    int nx = MROWS * E_DIM;
    cast_x_kernel<<<nx / 1024, 256>>>(x, af);
    dim3 gcw(WTOT / 1024, 1, 4);
    cast_w4_kernel<<<gcw, 256>>>(Wq, Wk, Wv, Wo, w4);

    // q/k/v projections (fp16, K=1024) -> fp16 head-layout outputs
    dim3 gqkv(E_DIM / 128, MROWS / 128, 3);
    qkv_mma_kernel<<<gqkv, 256, SMEM_TOTAL>>>(af, w4, bq, bk, bv, gq, gk, gv);

    // retention (native fp16)
    retention_kernel<<<HH * NHEADS, 256, RET_SMEM>>>(gk, gv, gq, go1, nullptr,
                                                     0);
    retention_kernel<<<WW * NHEADS, 256, RET_SMEM>>>(gk, gv, go1, nullptr,
                                                     o2f, 1);

    // output projection (fp16, K=1024) -> fp32
    dim3 g1(E_DIM / 128, MROWS / 128, 1);
    out_mma_kernel<<<g1, 256, SMEM_TOTAL>>>(o2f, w4 + 3 * WSZ, bo, out);
}

// round 17
// speedup vs baseline: 3.0169x; 1.0126x over previous
#include <cuda_runtime.h>
#include <cuda_bf16.h>
#include <cuda_fp16.h>
#include <cstdint>

#define E_DIM 1024
#define NHEADS 16
#define DH 64
#define HH 128
#define WW 128
#define MROWS (HH * WW)              /* 16384 */
#define HWD ((size_t)MROWS * DH)

#define BK 64
#define NCH (E_DIM / BK)              /* 16 */
#define ROWP 72                       /* padded row (elems), 144B */
#define TILE_ROWS 128
#define STAGE_HALF (TILE_ROWS * ROWP)
#define STAGE_BYTES (2 * STAGE_HALF * 2)   /* 36864 */
#define SMEM_TOTAL (2 * STAGE_BYTES)       /* 73728 */

/* retention smem layout (dynamic, bytes); all fp16 */
#define RLD 72
#define R_K 0            /* 128 x RLD fp16 = 18432 B */
#define R_V 18432
#define R_Q 36864
#define R_KVH 55296      /* 64 x RLD fp16 = 9216 B */
#define R_KVL 64512
#define RET_SMEM 73728

// ---------------- scratch (static device arrays; no allocation) ----------------
__device__ __half g_af[(size_t)MROWS * E_DIM];            // fp16 cast of x
__device__ __half g_w4[4][(size_t)E_DIM * E_DIM];         // fp16 casts q,k,v,o
__device__ __half g_o2f[(size_t)MROWS * E_DIM];           // fp16 of o2
__device__ __half g_qh[(size_t)NHEADS * MROWS * DH];
__device__ __half g_kh[(size_t)NHEADS * MROWS * DH];
__device__ __half g_vh[(size_t)NHEADS * MROWS * DH];
__device__ __half g_o1h[(size_t)NHEADS * MROWS * DH];

// ======================= helpers =======================
__device__ __forceinline__ uint32_t smem_u32(const void* p) {
    uint32_t a;
    asm("{ .reg .u64 t; cvta.to.shared.u64 t, %1; cvt.u32.u64 %0, t; }"
        : "=r"(a) : "l"(p));
    return a;
}

__device__ __forceinline__ void cp_async16(uint32_t dst, const void* src) {
    asm volatile("cp.async.cg.shared.global [%0], [%1], 16;\n"
                 :: "r"(dst), "l"(src) : "memory");
}

template <int N>
__device__ __forceinline__ void cp_wait() {
    asm volatile("cp.async.wait_group %0;\n" :: "n"(N) : "memory");
}

__device__ __forceinline__ void ldm_x4(uint32_t* r, uint32_t addr) {
    asm volatile(
        "ldmatrix.sync.aligned.m8n8.x4.shared.b16 {%0,%1,%2,%3}, [%4];"
        : "=r"(r[0]), "=r"(r[1]), "=r"(r[2]), "=r"(r[3]) : "r"(addr));
}

__device__ __forceinline__ void ldm_x4t(uint32_t* r, uint32_t addr) {
    asm volatile(
        "ldmatrix.sync.aligned.m8n8.x4.trans.shared.b16 {%0,%1,%2,%3}, [%4];"
        : "=r"(r[0]), "=r"(r[1]), "=r"(r[2]), "=r"(r[3]) : "r"(addr));
}

__device__ __forceinline__ void mma_fp16(float* c, const uint32_t* a,
                                         const uint32_t* b) {
    asm volatile(
        "mma.sync.aligned.m16n8k16.row.col.f32.f16.f16.f32 "
        "{%0,%1,%2,%3}, {%4,%5,%6,%7}, {%8,%9}, {%0,%1,%2,%3};"
        : "+f"(c[0]), "+f"(c[1]), "+f"(c[2]), "+f"(c[3])
        : "r"(a[0]), "r"(a[1]), "r"(a[2]), "r"(a[3]), "r"(b[0]), "r"(b[1]));
}

// ======================= fp16 HMMA GEMM (proven config, K=1024) =============
template <int HEADLAYOUT>
__device__ __forceinline__ void mma_gemm_body(
    const __half* __restrict__ A2, const __half* __restrict__ B2,
    const float* __restrict__ bias, void* __restrict__ outv, bool relu) {
    extern __shared__ char smem[];
    const int tid = threadIdx.x;
    const int wid = tid >> 5;
    const int lane = tid & 31;
    const int wm = wid & 3;
    const int wn = wid >> 2;
    const int m0 = blockIdx.y * 128;
    const int n0 = blockIdx.x * 128;

    float acc[2][8][4];
#pragma unroll
    for (int i = 0; i < 2; i++)
#pragma unroll
        for (int j = 0; j < 8; j++)
#pragma unroll
            for (int c = 0; c < 4; c++) acc[i][j][c] = 0.f;

    auto stA = [&](int s) {
        return reinterpret_cast<__half*>(smem + s * STAGE_BYTES);
    };
    auto stB = [&](int s) {
        return reinterpret_cast<__half*>(smem + s * STAGE_BYTES) + STAGE_HALF;
    };

    auto load_chunk = [&](int s, int k0) {
        __half* a = stA(s);
        __half* b = stB(s);
#pragma unroll
        for (int i = 0; i < 4; i++) {
            int c = tid + i * 256;
            int row = c >> 3;
            int seg = (c & 7) * 8;
            cp_async16(smem_u32(a + row * ROWP + seg),
                       A2 + (size_t)(m0 + row) * E_DIM + k0 + seg);
            cp_async16(smem_u32(b + row * ROWP + seg),
                       B2 + (size_t)(n0 + row) * E_DIM + k0 + seg);
        }
        asm volatile("cp.async.commit_group;\n" ::: "memory");
    };

    load_chunk(0, 0);

    const int a_row = lane & 15;
    const int a_c8 = (lane >> 4) * 8;
    const int b_row = (lane & 7) | ((lane & 16) >> 1);
    const int b_c8 = ((lane >> 3) & 1) * 8;

    for (int ch = 0; ch < NCH; ch++) {
        if (ch + 1 < NCH) {
            load_chunk((ch + 1) & 1, (ch + 1) * BK);
            cp_wait<1>();
        } else {
            cp_wait<0>();
        }
        __syncthreads();

        const int buf = ch & 1;
        const uint32_t sbA = smem_u32(stA(buf));
        const uint32_t sbB = smem_u32(stB(buf));

#pragma unroll
        for (int kk = 0; kk < 4; kk++) {
            uint32_t a[2][4], b[8][2];
#pragma unroll
            for (int mt = 0; mt < 2; mt++) {
                uint32_t addr = sbA +
                    2 * ((32 * wm + 16 * mt + a_row) * ROWP + kk * 16 + a_c8);
                ldm_x4(a[mt], addr);
            }
#pragma unroll
            for (int np = 0; np < 4; np++) {
                uint32_t r[4];
                uint32_t addr = sbB +
                    2 * ((64 * wn + 16 * np + b_row) * ROWP + kk * 16 + b_c8);
                ldm_x4(r, addr);
                b[np * 2][0] = r[0]; b[np * 2][1] = r[1];
                b[np * 2 + 1][0] = r[2]; b[np * 2 + 1][1] = r[3];
            }
#pragma unroll
            for (int mt = 0; mt < 2; mt++)
#pragma unroll
                for (int nt = 0; nt < 8; nt++)
                    mma_fp16(acc[mt][nt], a[mt], b[nt]);
        }
        __syncthreads();
    }

    const int g = lane >> 2;
    const int tq = lane & 3;
#pragma unroll
    for (int nt = 0; nt < 8; nt++) {
        const int n = n0 + 64 * wn + 8 * nt + 2 * tq;
        const float b0 = __ldg(bias + n);
        const float b1 = __ldg(bias + n + 1);
#pragma unroll
        for (int mt = 0; mt < 2; mt++) {
            const int mbase = m0 + 32 * wm + 16 * mt + g;
#pragma unroll
            for (int half = 0; half < 2; half++) {
                const int m = mbase + half * 8;
                float v0 = acc[mt][nt][half * 2] + b0;
                float v1 = acc[mt][nt][half * 2 + 1] + b1;
                if (relu) { v0 = fmaxf(v0, 0.f); v1 = fmaxf(v1, 0.f); }
                if (HEADLAYOUT) {
                    __half* out = reinterpret_cast<__half*>(outv);
                    *reinterpret_cast<__half2*>(
                        out + (size_t)(n >> 6) * HWD + (size_t)m * 64 +
                        (n & 63)) =
                        __half2(__float2half(v0), __float2half(v1));
                } else {
                    float* out = reinterpret_cast<float*>(outv);
                    *reinterpret_cast<float2*>(out + (size_t)m * E_DIM + n) =
                        make_float2(v0, v1);
                }
            }
        }
    }
}

__global__ __launch_bounds__(256, 2) void qkv_mma_kernel(
    const __half* __restrict__ af, const __half* __restrict__ w4,
    const float* __restrict__ bq, const float* __restrict__ bk,
    const float* __restrict__ bv, __half* gq, __half* gk, __half* gv) {
    const size_t WSZ = (size_t)E_DIM * E_DIM;
    const __half* B = w4 + (size_t)blockIdx.z * WSZ;
    const float* bias;
    __half* outp;
    bool relu;
    if (blockIdx.z == 0) { bias = bq; outp = gq; relu = true; }
    else if (blockIdx.z == 1) { bias = bk; outp = gk; relu = true; }
    else { bias = bv; outp = gv; relu = false; }
    mma_gemm_body<1>(af, B, bias, outp, relu);
}

__global__ __launch_bounds__(256, 2) void out_mma_kernel(
    const __half* __restrict__ a2, const __half* __restrict__ b2,
    const float* __restrict__ bias, float* __restrict__ out) {
    mma_gemm_body<0>(a2, b2, bias, out, false);
}

// ======================= fp32 -> fp16 cast kernels =======================
__global__ __launch_bounds__(256) void cast_x_kernel(
    const float* __restrict__ in, __half* __restrict__ out) {
    int i = (blockIdx.x * 256 + threadIdx.x) * 4;
    float4 v = *reinterpret_cast<const float4*>(in + i);
    __half2* p = reinterpret_cast<__half2*>(out + i);
    p[0] = __half2(__float2half(v.x), __float2half(v.y));
    p[1] = __half2(__float2half(v.z), __float2half(v.w));
}

__global__ __launch_bounds__(256) void cast_w4_kernel(
    const float* __restrict__ w0, const float* __restrict__ w1,
    const float* __restrict__ w2, const float* __restrict__ w3,
    __half* __restrict__ out) {
    const float* w = (blockIdx.z == 0) ? w0
                     : (blockIdx.z == 1) ? w1
                     : (blockIdx.z == 2) ? w2 : w3;
    __half* o = out + (size_t)blockIdx.z * E_DIM * E_DIM;
    int i = (blockIdx.x * 256 + threadIdx.x) * 4;
    float4 v = *reinterpret_cast<const float4*>(w + i);
    __half2* p = reinterpret_cast<__half2*>(o + i);
    p[0] = __half2(__float2half(v.x), __float2half(v.y));
    p[1] = __half2(__float2half(v.z), __float2half(v.w));
}

// ======================= fused retention (native fp16 HMMA, occ 3) ==========
__global__ __launch_bounds__(256, 3) void retention_kernel(
    const __half* __restrict__ kArr, const __half* __restrict__ vArr,
    const __half* __restrict__ cArr, __half* __restrict__ oH,
    __half* __restrict__ oCat, int mode) {
    extern __shared__ char rsm[];
    const int tid = threadIdx.x;
    const int wid = tid >> 5;
    const int lane = tid & 31;
    const int b = blockIdx.x;
    const int n = b & 15;
    const int idx = b >> 4;

    size_t base;
    int rs;
    if (mode == 0) {
        base = (size_t)n * HWD + (size_t)idx * (WW * DH);
        rs = DH;
    } else {
        base = (size_t)n * HWD + (size_t)idx * DH;
        rs = WW * DH;
    }
    const __half* kS = kArr + base;
    const __half* vS = vArr + base;
    const __half* cS = cArr + base;

    auto load_tile = [&](uint32_t dstOff, const __half* src) {
#pragma unroll
        for (int i = 0; i < 4; i++) {
            int c = tid + i * 256;
            int row = c >> 3;
            int seg = (c & 7) * 8;
            cp_async16(smem_u32(rsm + dstOff + 2 * (row * RLD + seg)),
                       src + (size_t)row * rs + seg);
        }
    };
    load_tile(R_K, kS);
    load_tile(R_V, vS);
    load_tile(R_Q, cS);
    asm volatile("cp.async.commit_group;\n" ::: "memory");
    cp_wait<0>();
    __syncthreads();

    const uint32_t sb = smem_u32(rsm);
    const int g = lane >> 2;
    const int tq = lane & 3;

    // ---- phase A: kvT[e][d] (64x64) via trans ldmatrix, fp16 MMA ----
    const int e0 = (wid >> 1) * 16;
    const int d0 = (wid & 1) * 32;
    const int ta_row = (lane & 7) + ((lane >> 4) & 1) * 8;
    const int ta_col = ((lane >> 3) & 1) * 8;
    const int tb_row = (lane & 7) + ((lane >> 3) & 1) * 8;
    const int tb_col = ((lane >> 4) & 1) * 8;

    float acc1[4][4];
#pragma unroll
    for (int i = 0; i < 4; i++)
#pragma unroll
        for (int j = 0; j < 4; j++) acc1[i][j] = 0.f;

#pragma unroll
    for (int ks = 0; ks < 8; ks++) {
        const int k0 = ks * 16;
        uint32_t av[4];
        ldm_x4t(av, sb + R_V + 2 * ((k0 + ta_row) * RLD + e0 + ta_col));
        uint32_t bk_[2][4];
#pragma unroll
        for (int nq = 0; nq < 2; nq++)
            ldm_x4t(bk_[nq], sb + R_K +
                    2 * ((k0 + tb_row) * RLD + d0 + nq * 16 + tb_col));
#pragma unroll
        for (int nq = 0; nq < 2; nq++)
#pragma unroll
            for (int p = 0; p < 2; p++) {
                uint32_t bf[2] = {bk_[nq][2 * p], bk_[nq][2 * p + 1]};
                mma_fp16(acc1[nq * 2 + p], av, bf);
            }
    }
    __syncthreads();

    // ---- stage kv as split-fp16 hi/lo ----
    {
        __half* kvh = reinterpret_cast<__half*>(rsm + R_KVH);
        __half* kvl = reinterpret_cast<__half*>(rsm + R_KVL);
#pragma unroll
        for (int nt = 0; nt < 4; nt++)
#pragma unroll
            for (int half = 0; half < 2; half++) {
                const int e = e0 + g + half * 8;
                const int d = d0 + nt * 8 + 2 * tq;
                float f0 = acc1[nt][half * 2];
                float f1 = acc1[nt][half * 2 + 1];
                __half h0 = __float2half(f0), h1 = __float2half(f1);
                float l0 = f0 - __half2float(h0);
                float l1 = f1 - __half2float(h1);
                *reinterpret_cast<__half2*>(kvh + e * RLD + d) = __half2(h0, h1);
                *reinterpret_cast<__half2*>(kvl + e * RLD + d) =
                    __half2(__float2half(l0), __float2half(l1));
            }
    }
    __syncthreads();

    // ---- phase B: out[r][e] (128x64) ----
    const int r0 = wid * 16;
    const int a_row = lane & 15;
    const int a_c8 = (lane >> 4) * 8;
    const int b_row = (lane & 7) | ((lane & 16) >> 1);
    const int b_c8 = ((lane >> 3) & 1) * 8;

    float acc2[8][4];
#pragma unroll
    for (int i = 0; i < 8; i++)
#pragma unroll
        for (int j = 0; j < 4; j++) acc2[i][j] = 0.f;

#pragma unroll
    for (int ks = 0; ks < 4; ks++) {
        const int k0 = ks * 16;
        uint32_t aq[4];
        ldm_x4(aq, sb + R_Q + 2 * ((r0 + a_row) * RLD + k0 + a_c8));
        uint32_t kh[4][4], kl[4][4];
#pragma unroll
        for (int nq = 0; nq < 4; nq++) {
            ldm_x4(kh[nq], sb + R_KVH +
                   2 * ((nq * 16 + b_row) * RLD + k0 + b_c8));
            ldm_x4(kl[nq], sb + R_KVL +
                   2 * ((nq * 16 + b_row) * RLD + k0 + b_c8));
        }
#pragma unroll
        for (int nt = 0; nt < 8; nt++) {
            const int nq = nt >> 1;
            const int p = nt & 1;
            uint32_t bfh[2] = {kh[nq][2 * p], kh[nq][2 * p + 1]};
            uint32_t bfl[2] = {kl[nq][2 * p], kl[nq][2 * p + 1]};
            mma_fp16(acc2[nt], aq, bfh);
            mma_fp16(acc2[nt], aq, bfl);
        }
    }

#pragma unroll
    for (int nt = 0; nt < 8; nt++) {
        const int e = nt * 8 + 2 * tq;
#pragma unroll
        for (int half = 0; half < 2; half++) {
            const int r = r0 + g + half * 8;
            float v0 = acc2[nt][half * 2];
            float v1 = acc2[nt][half * 2 + 1];
            __half2 hv(__float2half(v0), __float2half(v1));
            if (mode == 0) {
                *reinterpret_cast<__half2*>(oH + base + (size_t)r * DH + e) =
                    hv;
            } else {
                const int m = r * WW + idx;
                *reinterpret_cast<__half2*>(oCat + (size_t)m * E_DIM +
                                            n * DH + e) = hv;
            }
        }
    }
}

// =======================================================================
extern "C" void kernel_launch(void* const* d_in, const int* in_sizes, int n_in,
                              void* d_out, int out_size) {
    const float* x  = (const float*)d_in[0];
    const float* Wq = (const float*)d_in[1];
    const float* bq = (const float*)d_in[2];
    const float* Wk = (const float*)d_in[3];
    const float* bk = (const float*)d_in[4];
    const float* Wv = (const float*)d_in[5];
    const float* bv = (const float*)d_in[6];
    const float* Wo = (const float*)d_in[7];
    const float* bo = (const float*)d_in[8];
    float* out = (float*)d_out;

    __half *af, *w4, *o2f, *gq, *gk, *gv, *go1;
    cudaGetSymbolAddress((void**)&af, g_af);
    cudaGetSymbolAddress((void**)&w4, g_w4);
    cudaGetSymbolAddress((void**)&o2f, g_o2f);
    cudaGetSymbolAddress((void**)&gq, g_qh);
    cudaGetSymbolAddress((void**)&gk, g_kh);
    cudaGetSymbolAddress((void**)&gv, g_vh);
    cudaGetSymbolAddress((void**)&go1, g_o1h);

    const int WTOT = E_DIM * E_DIM;
    const size_t WSZ = (size_t)E_DIM * E_DIM;

    cudaFuncSetAttribute(qkv_mma_kernel,
                         cudaFuncAttributeMaxDynamicSharedMemorySize,
                         SMEM_TOTAL);
    cudaFuncSetAttribute(out_mma_kernel,
                         cudaFuncAttributeMaxDynamicSharedMemorySize,
                         SMEM_TOTAL);
    cudaFuncSetAttribute(retention_kernel,
                         cudaFuncAttributeMaxDynamicSharedMemorySize,
                         RET_SMEM);

    // casts
    int nx = MROWS * E_DIM;
    cast_x_kernel<<<nx / 1024, 256>>>(x, af);
    dim3 gcw(WTOT / 1024, 1, 4);
    cast_w4_kernel<<<gcw, 256>>>(Wq, Wk, Wv, Wo, w4);

    // q/k/v projections (fp16, K=1024) -> fp16 head-layout outputs
    dim3 gqkv(E_DIM / 128, MROWS / 128, 3);
    qkv_mma_kernel<<<gqkv, 256, SMEM_TOTAL>>>(af, w4, bq, bk, bv, gq, gk, gv);

    // retention (native fp16, 3 CTAs/SM)
    retention_kernel<<<HH * NHEADS, 256, RET_SMEM>>>(gk, gv, gq, go1, nullptr,
                                                     0);
    retention_kernel<<<WW * NHEADS, 256, RET_SMEM>>>(gk, gv, go1, nullptr,
                                                     o2f, 1);

    // output projection (fp16, K=1024) -> fp32
    dim3 g1(E_DIM / 128, MROWS / 128, 1);
    out_mma_kernel<<<g1, 256, SMEM_TOTAL>>>(o2f, w4 + 3 * WSZ, bo, out);
}